// round 3
// baseline (speedup 1.0000x reference)
#include <cuda_runtime.h>
#include <math.h>

#define B_    16
#define C_    384
#define HW_   3136
#define W56   56
#define NTOK  (B_*HW_)     // 50176
#define NH_   8
#define HD_   48
#define SPLIT_ 128
#define HID_  1536
#define R_    192

// ---------------- scratch (device globals; no allocations) ----------------
__device__ float g_s1  [(size_t)B_*SPLIT_*HW_];
__device__ float g_s2  [(size_t)B_*SPLIT_*HW_];
__device__ float g_xfl [(size_t)NTOK*C_];
__device__ float g_ln  [(size_t)NTOK*C_];
__device__ float g_qkv [(size_t)NTOK*3*C_];
__device__ float g_att [(size_t)NTOK*C_];
__device__ float g_mid1[(size_t)NTOK*R_];
__device__ float g_hid [(size_t)NTOK*HID_];
__device__ float g_mid2[(size_t)NTOK*R_];

// ---------------- depthwise conv: out = dwconv(a + b, w) + bias ----------------
__global__ void dwconv_k(const float* __restrict__ a, size_t strideA,
                         const float* __restrict__ bsrc, size_t strideB,
                         const float* __restrict__ w, const float* __restrict__ bias,
                         float* __restrict__ out)
{
    int idx = blockIdx.x * blockDim.x + threadIdx.x;
    if (idx >= B_*SPLIT_*HW_) return;
    int p = idx % HW_;
    int c = (idx / HW_) % SPLIT_;
    int b = idx / (HW_*SPLIT_);
    int y = p / W56, xq = p % W56;
    const float* pa = a    + (size_t)b*strideA + (size_t)c*HW_;
    const float* pb = bsrc + (size_t)b*strideB + (size_t)c*HW_;
    const float* wc = w + c*9;
    float acc = bias[c];
    #pragma unroll
    for (int dy = -1; dy <= 1; dy++) {
        int yy = y + dy;
        if (yy < 0 || yy >= W56) continue;
        #pragma unroll
        for (int dx = -1; dx <= 1; dx++) {
            int xx = xq + dx;
            if (xx < 0 || xx >= W56) continue;
            float v = pa[yy*W56 + xx] + pb[yy*W56 + xx];
            acc = fmaf(v, wc[(dy+1)*3 + (dx+1)], acc);
        }
    }
    out[idx] = acc;
}

// ------------- gather concat[s0, s1, s2] NCHW -> xflat [B*N, C] -------------
__global__ void gather_k(const float* __restrict__ x, float* __restrict__ xflat)
{
    __shared__ float t[32][33];
    int b = blockIdx.z;
    int c0 = blockIdx.y * 32, p0 = blockIdx.x * 32;
    int tx = threadIdx.x, ty = threadIdx.y;
    int c = c0 + ty, p = p0 + tx;
    float v;
    if (c < 128)      v = x[((size_t)b*C_ + c)*HW_ + p];
    else if (c < 256) v = g_s1[((size_t)b*SPLIT_ + (c-128))*HW_ + p];
    else              v = g_s2[((size_t)b*SPLIT_ + (c-256))*HW_ + p];
    t[ty][tx] = v;
    __syncthreads();
    xflat[((size_t)b*HW_ + p0 + ty)*C_ + c0 + tx] = t[tx][ty];
}

// ---------------- final xflat [B*N, C] -> out NCHW ----------------
__global__ void scatter_k(const float* __restrict__ xflat, float* __restrict__ out)
{
    __shared__ float t[32][33];
    int b = blockIdx.z;
    int c0 = blockIdx.y * 32, p0 = blockIdx.x * 32;
    int tx = threadIdx.x, ty = threadIdx.y;
    t[ty][tx] = xflat[((size_t)b*HW_ + p0 + ty)*C_ + c0 + tx];
    __syncthreads();
    out[((size_t)b*C_ + c0 + ty)*HW_ + p0 + tx] = t[tx][ty];
}

// ---------------- LayerNorm over C=384, one 128-thread block per token ------
__device__ __forceinline__ float warp_sum(float v)
{
    #pragma unroll
    for (int o = 16; o > 0; o >>= 1) v += __shfl_xor_sync(0xffffffffu, v, o);
    return v;
}

__global__ void __launch_bounds__(128) ln_k(const float* __restrict__ in,
                                            const float* __restrict__ gam,
                                            const float* __restrict__ bet,
                                            float* __restrict__ outp)
{
    int row = blockIdx.x;
    int tid = threadIdx.x;
    const float* r = in + (size_t)row*C_;
    float v0 = r[tid], v1 = r[tid+128], v2 = r[tid+256];
    __shared__ float red[4];
    int wid = tid >> 5, lane = tid & 31;
    float s = warp_sum(v0 + v1 + v2);
    if (lane == 0) red[wid] = s;
    __syncthreads();
    float mean = (red[0]+red[1]+red[2]+red[3]) * (1.f/384.f);
    float d0 = v0 - mean, d1 = v1 - mean, d2 = v2 - mean;
    float sq = warp_sum(d0*d0 + d1*d1 + d2*d2);
    __syncthreads();
    if (lane == 0) red[wid] = sq;
    __syncthreads();
    float var = (red[0]+red[1]+red[2]+red[3]) * (1.f/384.f);
    float rs = rsqrtf(var + 1e-6f);
    float* o = outp + (size_t)row*C_;
    o[tid]     = d0*rs*gam[tid]     + bet[tid];
    o[tid+128] = d1*rs*gam[tid+128] + bet[tid+128];
    o[tid+256] = d2*rs*gam[tid+256] + bet[tid+256];
}

// ---------------- generic SGEMM: C = A[M,K] @ B[K,N] (+bias)(+gelu)(+=C) ----
// BM=128, BN=64, BK=16, 256 threads, 8x4 per-thread tile.
template<bool BIAS, bool ACCUM, bool GELU_ACT>
__global__ void __launch_bounds__(256) gemm_k(const float* __restrict__ A,
                                              const float* __restrict__ Bw,
                                              const float* __restrict__ bias,
                                              float* __restrict__ C,
                                              int M, int Nn, int K)
{
    __shared__ float As[16][132];
    __shared__ float Bs[16][64];
    int tid = threadIdx.x;
    int tx = tid & 15, ty = tid >> 4;
    int m0 = blockIdx.y * 128, n0 = blockIdx.x * 64;
    const float* Ap = A + (size_t)m0 * K;
    const float* Bp = Bw + n0;

    float acc[8][4];
    #pragma unroll
    for (int i = 0; i < 8; i++)
        #pragma unroll
        for (int j = 0; j < 4; j++) acc[i][j] = 0.f;

    int aid0 = tid*2,     ar0 = aid0 >> 2, ak0 = (aid0 & 3) * 4;
    int aid1 = tid*2 + 1, ar1 = aid1 >> 2, ak1 = (aid1 & 3) * 4;
    int bk = tid >> 4, bn = (tid & 15) * 4;

    for (int k0 = 0; k0 < K; k0 += 16) {
        float4 va0 = *(const float4*)(Ap + (size_t)ar0*K + k0 + ak0);
        float4 va1 = *(const float4*)(Ap + (size_t)ar1*K + k0 + ak1);
        float4 vb  = *(const float4*)(Bp + (size_t)(k0 + bk)*Nn + bn);
        As[ak0  ][ar0] = va0.x; As[ak0+1][ar0] = va0.y;
        As[ak0+2][ar0] = va0.z; As[ak0+3][ar0] = va0.w;
        As[ak1  ][ar1] = va1.x; As[ak1+1][ar1] = va1.y;
        As[ak1+2][ar1] = va1.z; As[ak1+3][ar1] = va1.w;
        *(float4*)&Bs[bk][bn] = vb;
        __syncthreads();
        #pragma unroll
        for (int kk = 0; kk < 16; kk++) {
            float4 a0 = *(const float4*)&As[kk][ty*8];
            float4 a1 = *(const float4*)&As[kk][ty*8 + 4];
            float4 b0 = *(const float4*)&Bs[kk][tx*4];
            float af[8] = {a0.x,a0.y,a0.z,a0.w,a1.x,a1.y,a1.z,a1.w};
            float bf[4] = {b0.x,b0.y,b0.z,b0.w};
            #pragma unroll
            for (int i = 0; i < 8; i++)
                #pragma unroll
                for (int j = 0; j < 4; j++)
                    acc[i][j] = fmaf(af[i], bf[j], acc[i][j]);
        }
        __syncthreads();
    }

    float bv[4] = {0.f, 0.f, 0.f, 0.f};
    if (BIAS) {
        #pragma unroll
        for (int j = 0; j < 4; j++) bv[j] = bias[n0 + tx*4 + j];
    }
    #pragma unroll
    for (int i = 0; i < 8; i++) {
        size_t row = (size_t)(m0 + ty*8 + i);
        float* cp = C + row*Nn + n0 + tx*4;
        float r[4];
        #pragma unroll
        for (int j = 0; j < 4; j++) {
            float v = acc[i][j];
            if (BIAS) v += bv[j];
            if (GELU_ACT) v = 0.5f * v * (1.f + erff(v * 0.70710678118654752f));
            r[j] = v;
        }
        if (ACCUM) {
            float4 o = *(const float4*)cp;
            r[0] += o.x; r[1] += o.y; r[2] += o.z; r[3] += o.w;
        }
        *(float4*)cp = make_float4(r[0], r[1], r[2], r[3]);
    }
}

// ---------------- XCA attention: one CTA per (b, h) ----------------
__global__ void __launch_bounds__(256) xca_k(const float* __restrict__ qkv,
                                             float* __restrict__ out)
{
    __shared__ float qs[48][65];
    __shared__ float ks[48][65];
    __shared__ float Sm[48][49];
    __shared__ float qn[48], kn[48];

    int b = blockIdx.x >> 3, h = blockIdx.x & 7;
    int tid = threadIdx.x;
    const float* qb = qkv + (size_t)b*HW_*1152 + h*48;
    const float* kb = qb + 384;
    const float* vb = qb + 768;
    int ty = tid >> 4, tx = tid & 15;

    float accS[3][3];
    #pragma unroll
    for (int i = 0; i < 3; i++)
        #pragma unroll
        for (int j = 0; j < 3; j++) accS[i][j] = 0.f;
    float nacc = 0.f;

    // Phase A: S = q @ k^T over token dim, plus squared norms
    for (int t0 = 0; t0 < HW_; t0 += 64) {
        #pragma unroll
        for (int q = 0; q < 3; q++) {
            int id = tid*3 + q;            // 0..767
            int ni = id / 12;
            int d4 = (id % 12) * 4;
            float4 v = *(const float4*)(qb + (size_t)(t0+ni)*1152 + d4);
            qs[d4][ni] = v.x; qs[d4+1][ni] = v.y; qs[d4+2][ni] = v.z; qs[d4+3][ni] = v.w;
            v = *(const float4*)(kb + (size_t)(t0+ni)*1152 + d4);
            ks[d4][ni] = v.x; ks[d4+1][ni] = v.y; ks[d4+2][ni] = v.z; ks[d4+3][ni] = v.w;
        }
        __syncthreads();
        #pragma unroll 4
        for (int n = 0; n < 64; n++) {
            float qv[3], kv[3];
            #pragma unroll
            for (int i = 0; i < 3; i++) qv[i] = qs[ty*3+i][n];
            #pragma unroll
            for (int j = 0; j < 3; j++) kv[j] = ks[tx*3+j][n];
            #pragma unroll
            for (int i = 0; i < 3; i++)
                #pragma unroll
                for (int j = 0; j < 3; j++)
                    accS[i][j] = fmaf(qv[i], kv[j], accS[i][j]);
        }
        if (tid < 48) {
            #pragma unroll 4
            for (int n = 0; n < 64; n++) { float v = qs[tid][n]; nacc = fmaf(v, v, nacc); }
        } else if (tid < 96) {
            int d = tid - 48;
            #pragma unroll 4
            for (int n = 0; n < 64; n++) { float v = ks[d][n]; nacc = fmaf(v, v, nacc); }
        }
        __syncthreads();
    }

    #pragma unroll
    for (int i = 0; i < 3; i++)
        #pragma unroll
        for (int j = 0; j < 3; j++) Sm[ty*3+i][tx*3+j] = accS[i][j];
    if (tid < 48)      qn[tid]    = nacc;
    else if (tid < 96) kn[tid-48] = nacc;
    __syncthreads();

    // inverse norms
    if (tid < 48)      qn[tid]    = 1.f / fmaxf(sqrtf(qn[tid]),    1e-12f);
    else if (tid < 96) kn[tid-48] = 1.f / fmaxf(sqrtf(kn[tid-48]), 1e-12f);
    __syncthreads();

    // softmax rows (48 threads, one row each)
    if (tid < 48) {
        float iq = qn[tid];
        float mx = -1e30f;
        #pragma unroll
        for (int e = 0; e < 48; e++) {
            float l = Sm[tid][e] * iq * kn[e];
            Sm[tid][e] = l;
            mx = fmaxf(mx, l);
        }
        float s = 0.f;
        #pragma unroll
        for (int e = 0; e < 48; e++) {
            float ex = expf(Sm[tid][e] - mx);
            Sm[tid][e] = ex;
            s += ex;
        }
        float inv = 1.f / s;
        #pragma unroll
        for (int e = 0; e < 48; e++) Sm[tid][e] *= inv;
    }
    __syncthreads();

    // Phase C: y = attn @ v, streamed over token tiles (reuse qs for v)
    for (int t0 = 0; t0 < HW_; t0 += 64) {
        #pragma unroll
        for (int q = 0; q < 3; q++) {
            int id = tid*3 + q;
            int ni = id / 12;
            int d4 = (id % 12) * 4;
            float4 v = *(const float4*)(vb + (size_t)(t0+ni)*1152 + d4);
            qs[d4][ni] = v.x; qs[d4+1][ni] = v.y; qs[d4+2][ni] = v.z; qs[d4+3][ni] = v.w;
        }
        __syncthreads();
        #pragma unroll
        for (int r = 0; r < 12; r++) {
            int idx = tid + 256*r;         // 0..3071
            int d  = idx % 48;
            int ni = idx / 48;
            float acc = 0.f;
            #pragma unroll
            for (int e = 0; e < 48; e++)
                acc = fmaf(Sm[d][e], qs[e][ni], acc);
            out[((size_t)(b*HW_ + t0 + ni))*C_ + h*48 + d] = acc;
        }
        __syncthreads();
    }
}

// ---------------- launch ----------------
extern "C" void kernel_launch(void* const* d_in, const int* in_sizes, int n_in,
                              void* d_out, int out_size)
{
    (void)in_sizes; (void)n_in; (void)out_size;
    const float* x      = (const float*)d_in[0];
    const float* dw_w0  = (const float*)d_in[1];
    const float* dw_b0  = (const float*)d_in[2];
    const float* dw_w1  = (const float*)d_in[3];
    const float* dw_b1  = (const float*)d_in[4];
    const float* ln1_g  = (const float*)d_in[5];
    const float* ln1_b  = (const float*)d_in[6];
    const float* qkv_w  = (const float*)d_in[7];
    const float* proj_w = (const float*)d_in[8];
    const float* proj_b = (const float*)d_in[9];
    const float* ln2_g  = (const float*)d_in[10];
    const float* ln2_b  = (const float*)d_in[11];
    const float* m1dw   = (const float*)d_in[12];
    const float* m1uw   = (const float*)d_in[13];
    const float* m1ub   = (const float*)d_in[14];
    const float* m2dw   = (const float*)d_in[15];
    const float* m2uw   = (const float*)d_in[16];
    const float* m2ub   = (const float*)d_in[17];
    float* out = (float*)d_out;

    float *s1, *s2, *xfl, *lnb, *qkvb, *attb, *mid1, *hid, *mid2;
    cudaGetSymbolAddress((void**)&s1,   g_s1);
    cudaGetSymbolAddress((void**)&s2,   g_s2);
    cudaGetSymbolAddress((void**)&xfl,  g_xfl);
    cudaGetSymbolAddress((void**)&lnb,  g_ln);
    cudaGetSymbolAddress((void**)&qkvb, g_qkv);
    cudaGetSymbolAddress((void**)&attb, g_att);
    cudaGetSymbolAddress((void**)&mid1, g_mid1);
    cudaGetSymbolAddress((void**)&hid,  g_hid);
    cudaGetSymbolAddress((void**)&mid2, g_mid2);

    const int nconv = B_*SPLIT_*HW_;
    dim3 tp(32, 32);
    dim3 gt(HW_/32, C_/32, B_);

    // multi-scale depthwise chain
    dwconv_k<<<(nconv + 255)/256, 256>>>(x + (size_t)SPLIT_*HW_,   (size_t)C_*HW_,
                                         x,                        (size_t)C_*HW_,
                                         dw_w0, dw_b0, s1);
    dwconv_k<<<(nconv + 255)/256, 256>>>(x + (size_t)2*SPLIT_*HW_, (size_t)C_*HW_,
                                         s1,                       (size_t)SPLIT_*HW_,
                                         dw_w1, dw_b1, s2);
    gather_k<<<gt, tp>>>(x, xfl);

    // attention block
    ln_k<<<NTOK, 128>>>(xfl, ln1_g, ln1_b, lnb);
    gemm_k<false,false,false><<<dim3(1152/64, NTOK/128), 256>>>(lnb, qkv_w, nullptr, qkvb, NTOK, 1152, 384);
    xca_k<<<B_*NH_, 256>>>(qkvb, attb);
    gemm_k<true,true,false><<<dim3(384/64, NTOK/128), 256>>>(attb, proj_w, proj_b, xfl, NTOK, 384, 384);

    // MLP block
    ln_k<<<NTOK, 128>>>(xfl, ln2_g, ln2_b, lnb);
    gemm_k<false,false,false><<<dim3(192/64,  NTOK/128), 256>>>(lnb,  m1dw, nullptr, mid1, NTOK, 192,  384);
    gemm_k<true,false,true ><<<dim3(1536/64, NTOK/128), 256>>>(mid1, m1uw, m1ub,    hid,  NTOK, 1536, 192);
    gemm_k<false,false,false><<<dim3(192/64,  NTOK/128), 256>>>(hid,  m2dw, nullptr, mid2, NTOK, 192,  1536);
    gemm_k<true,true,false ><<<dim3(384/64,  NTOK/128), 256>>>(mid2, m2uw, m2ub,    xfl,  NTOK, 384,  192);

    // back to NCHW
    scatter_k<<<gt, tp>>>(xfl, out);
}

// round 4
// speedup vs baseline: 1.4696x; 1.4696x over previous
#include <cuda_runtime.h>
#include <math.h>

#define B_    16
#define C_    384
#define HW_   3136
#define W56   56
#define NTOK  (B_*HW_)     // 50176
#define NH_   8
#define HD_   48
#define SPLIT_ 128
#define HID_  1536
#define R_    192

// ---------------- scratch (device globals; no allocations) ----------------
__device__ float g_s1  [(size_t)B_*SPLIT_*HW_];
__device__ float g_s2  [(size_t)B_*SPLIT_*HW_];
__device__ float g_xfl [(size_t)NTOK*C_];
__device__ float g_ln  [(size_t)NTOK*C_];
__device__ float g_qkv [(size_t)NTOK*3*C_];
__device__ float g_att [(size_t)NTOK*C_];
__device__ float g_mid1[(size_t)NTOK*R_];
__device__ float g_hid [(size_t)NTOK*HID_];
__device__ float g_mid2[(size_t)NTOK*R_];

// ---------------- depthwise conv: out = dwconv(a + b, w) + bias ----------------
__global__ void dwconv_k(const float* __restrict__ a, size_t strideA,
                         const float* __restrict__ bsrc, size_t strideB,
                         const float* __restrict__ w, const float* __restrict__ bias,
                         float* __restrict__ out)
{
    int idx = blockIdx.x * blockDim.x + threadIdx.x;
    if (idx >= B_*SPLIT_*HW_) return;
    int p = idx % HW_;
    int c = (idx / HW_) % SPLIT_;
    int b = idx / (HW_*SPLIT_);
    int y = p / W56, xq = p % W56;
    const float* pa = a    + (size_t)b*strideA + (size_t)c*HW_;
    const float* pb = bsrc + (size_t)b*strideB + (size_t)c*HW_;
    const float* wc = w + c*9;
    float acc = bias[c];
    #pragma unroll
    for (int dy = -1; dy <= 1; dy++) {
        int yy = y + dy;
        if (yy < 0 || yy >= W56) continue;
        #pragma unroll
        for (int dx = -1; dx <= 1; dx++) {
            int xx = xq + dx;
            if (xx < 0 || xx >= W56) continue;
            float v = pa[yy*W56 + xx] + pb[yy*W56 + xx];
            acc = fmaf(v, wc[(dy+1)*3 + (dx+1)], acc);
        }
    }
    out[idx] = acc;
}

// ------------- gather concat[s0, s1, s2] NCHW -> xflat [B*N, C] -------------
__global__ void gather_k(const float* __restrict__ x, float* __restrict__ xflat)
{
    __shared__ float t[32][33];
    int b = blockIdx.z;
    int c0 = blockIdx.y * 32, p0 = blockIdx.x * 32;
    int tx = threadIdx.x, ty = threadIdx.y;
    int c = c0 + ty, p = p0 + tx;
    float v;
    if (c < 128)      v = x[((size_t)b*C_ + c)*HW_ + p];
    else if (c < 256) v = g_s1[((size_t)b*SPLIT_ + (c-128))*HW_ + p];
    else              v = g_s2[((size_t)b*SPLIT_ + (c-256))*HW_ + p];
    t[ty][tx] = v;
    __syncthreads();
    xflat[((size_t)b*HW_ + p0 + ty)*C_ + c0 + tx] = t[tx][ty];
}

// ---------------- final xflat [B*N, C] -> out NCHW ----------------
__global__ void scatter_k(const float* __restrict__ xflat, float* __restrict__ out)
{
    __shared__ float t[32][33];
    int b = blockIdx.z;
    int c0 = blockIdx.y * 32, p0 = blockIdx.x * 32;
    int tx = threadIdx.x, ty = threadIdx.y;
    t[ty][tx] = xflat[((size_t)b*HW_ + p0 + ty)*C_ + c0 + tx];
    __syncthreads();
    out[((size_t)b*C_ + c0 + ty)*HW_ + p0 + tx] = t[tx][ty];
}

// ---------------- LayerNorm over C=384 ----------------
__device__ __forceinline__ float warp_sum(float v)
{
    #pragma unroll
    for (int o = 16; o > 0; o >>= 1) v += __shfl_xor_sync(0xffffffffu, v, o);
    return v;
}

__global__ void __launch_bounds__(128) ln_k(const float* __restrict__ in,
                                            const float* __restrict__ gam,
                                            const float* __restrict__ bet,
                                            float* __restrict__ outp)
{
    int row = blockIdx.x;
    int tid = threadIdx.x;
    const float* r = in + (size_t)row*C_;
    float v0 = r[tid], v1 = r[tid+128], v2 = r[tid+256];
    __shared__ float red[4];
    int wid = tid >> 5, lane = tid & 31;
    float s = warp_sum(v0 + v1 + v2);
    if (lane == 0) red[wid] = s;
    __syncthreads();
    float mean = (red[0]+red[1]+red[2]+red[3]) * (1.f/384.f);
    float d0 = v0 - mean, d1 = v1 - mean, d2 = v2 - mean;
    float sq = warp_sum(d0*d0 + d1*d1 + d2*d2);
    __syncthreads();
    if (lane == 0) red[wid] = sq;
    __syncthreads();
    float var = (red[0]+red[1]+red[2]+red[3]) * (1.f/384.f);
    float rs = rsqrtf(var + 1e-6f);
    float* o = outp + (size_t)row*C_;
    o[tid]     = d0*rs*gam[tid]     + bet[tid];
    o[tid+128] = d1*rs*gam[tid+128] + bet[tid+128];
    o[tid+256] = d2*rs*gam[tid+256] + bet[tid+256];
}

// ================= tf32 tensor-core GEMM =================
// C[M,N] = A[M,K] @ B[K,N] (+bias)(+gelu)(+=C)
// BM=128, BN=64, BK=16. 256 threads = 8 warps (4 along M x 2 along N),
// warp tile 32x32 via m16n8k8 (2 m-tiles x 4 n-tiles, 2 k-steps).

__device__ __forceinline__ unsigned f2tf(float x)
{
    unsigned r;
    asm("cvt.rna.tf32.f32 %0, %1;" : "=r"(r) : "f"(x));
    return r;
}

__device__ __forceinline__ void mma_tf32(float* c, const unsigned* a, const unsigned* b)
{
    asm volatile(
        "mma.sync.aligned.m16n8k8.row.col.f32.tf32.tf32.f32 "
        "{%0,%1,%2,%3}, {%4,%5,%6,%7}, {%8,%9}, {%0,%1,%2,%3};\n"
        : "+f"(c[0]), "+f"(c[1]), "+f"(c[2]), "+f"(c[3])
        : "r"(a[0]), "r"(a[1]), "r"(a[2]), "r"(a[3]), "r"(b[0]), "r"(b[1]));
}

template<bool BIAS, bool ACCUM, bool GELU_ACT>
__global__ void __launch_bounds__(256) gemm_tc(const float* __restrict__ A,
                                               const float* __restrict__ Bw,
                                               const float* __restrict__ bias,
                                               float* __restrict__ C,
                                               int M, int Nn, int K)
{
    __shared__ unsigned As[2][16][132];
    __shared__ unsigned Bs[2][16][68];

    int tid = threadIdx.x;
    int w = tid >> 5, lane = tid & 31;
    int g = lane >> 2, t = lane & 3;
    int moff = (w & 3) * 32;          // warp m-offset in tile
    int noff = (w >> 2) * 32;         // warp n-offset in tile
    int m0 = blockIdx.y * 128, n0 = blockIdx.x * 64;

    // global load mapping
    int ar0 = tid >> 2,            ac0 = (tid & 3) * 4;          // A float4 #0
    int ar1 = (tid + 256) >> 2,    ac1 = (tid & 3) * 4;          // A float4 #1
    int bk  = tid >> 4,            bn  = (tid & 15) * 4;         // B float4

    const float* Ap = A + (size_t)m0 * K;
    const float* Bp = Bw + n0;

    float acc[2][4][4];
    #pragma unroll
    for (int i = 0; i < 2; i++)
        #pragma unroll
        for (int j = 0; j < 4; j++)
            #pragma unroll
            for (int q = 0; q < 4; q++) acc[i][j][q] = 0.f;

    float4 va0, va1, vb;

    // prologue: tile 0
    va0 = *(const float4*)(Ap + (size_t)ar0*K + ac0);
    va1 = *(const float4*)(Ap + (size_t)ar1*K + ac1);
    vb  = *(const float4*)(Bp + (size_t)bk*Nn + bn);
    As[0][ac0  ][ar0] = f2tf(va0.x); As[0][ac0+1][ar0] = f2tf(va0.y);
    As[0][ac0+2][ar0] = f2tf(va0.z); As[0][ac0+3][ar0] = f2tf(va0.w);
    As[0][ac1  ][ar1] = f2tf(va1.x); As[0][ac1+1][ar1] = f2tf(va1.y);
    As[0][ac1+2][ar1] = f2tf(va1.z); As[0][ac1+3][ar1] = f2tf(va1.w);
    Bs[0][bk][bn  ] = f2tf(vb.x); Bs[0][bk][bn+1] = f2tf(vb.y);
    Bs[0][bk][bn+2] = f2tf(vb.z); Bs[0][bk][bn+3] = f2tf(vb.w);
    __syncthreads();

    int nk = K >> 4;
    for (int it = 0; it < nk; it++) {
        int buf = it & 1;
        bool more = (it + 1 < nk);
        if (more) {
            int k0 = (it + 1) << 4;
            va0 = *(const float4*)(Ap + (size_t)ar0*K + k0 + ac0);
            va1 = *(const float4*)(Ap + (size_t)ar1*K + k0 + ac1);
            vb  = *(const float4*)(Bp + (size_t)(k0 + bk)*Nn + bn);
        }
        // compute on buf (overlaps LDG latency)
        #pragma unroll
        for (int ks = 0; ks < 2; ks++) {
            int kb = ks * 8;
            unsigned af[2][4], bf[4][2];
            #pragma unroll
            for (int i = 0; i < 2; i++) {
                int m = moff + i*16 + g;
                af[i][0] = As[buf][kb+t  ][m];
                af[i][1] = As[buf][kb+t  ][m+8];
                af[i][2] = As[buf][kb+t+4][m];
                af[i][3] = As[buf][kb+t+4][m+8];
            }
            #pragma unroll
            for (int j = 0; j < 4; j++) {
                int n = noff + j*8 + g;
                bf[j][0] = Bs[buf][kb+t  ][n];
                bf[j][1] = Bs[buf][kb+t+4][n];
            }
            #pragma unroll
            for (int i = 0; i < 2; i++)
                #pragma unroll
                for (int j = 0; j < 4; j++)
                    mma_tf32(acc[i][j], af[i], bf[j]);
        }
        if (more) {
            int nb = buf ^ 1;
            As[nb][ac0  ][ar0] = f2tf(va0.x); As[nb][ac0+1][ar0] = f2tf(va0.y);
            As[nb][ac0+2][ar0] = f2tf(va0.z); As[nb][ac0+3][ar0] = f2tf(va0.w);
            As[nb][ac1  ][ar1] = f2tf(va1.x); As[nb][ac1+1][ar1] = f2tf(va1.y);
            As[nb][ac1+2][ar1] = f2tf(va1.z); As[nb][ac1+3][ar1] = f2tf(va1.w);
            Bs[nb][bk][bn  ] = f2tf(vb.x); Bs[nb][bk][bn+1] = f2tf(vb.y);
            Bs[nb][bk][bn+2] = f2tf(vb.z); Bs[nb][bk][bn+3] = f2tf(vb.w);
            __syncthreads();
        }
    }

    // epilogue
    #pragma unroll
    for (int i = 0; i < 2; i++) {
        #pragma unroll
        for (int j = 0; j < 4; j++) {
            int col = n0 + noff + j*8 + t*2;
            float b0 = 0.f, b1 = 0.f;
            if (BIAS) { b0 = bias[col]; b1 = bias[col+1]; }
            #pragma unroll
            for (int half = 0; half < 2; half++) {
                int row = m0 + moff + i*16 + g + half*8;
                float r0 = acc[i][j][half*2]   + b0;
                float r1 = acc[i][j][half*2+1] + b1;
                if (GELU_ACT) {
                    r0 = 0.5f * r0 * (1.f + erff(r0 * 0.70710678118654752f));
                    r1 = 0.5f * r1 * (1.f + erff(r1 * 0.70710678118654752f));
                }
                float2* cp = (float2*)(C + (size_t)row*Nn + col);
                if (ACCUM) {
                    float2 o = *cp;
                    r0 += o.x; r1 += o.y;
                }
                *cp = make_float2(r0, r1);
            }
        }
    }
}

// ---------------- XCA attention: one CTA per (b, h) ----------------
__global__ void __launch_bounds__(256) xca_k(const float* __restrict__ qkv,
                                             float* __restrict__ out)
{
    __shared__ float qs[48][65];
    __shared__ float ks[48][65];
    __shared__ float Sm[48][49];
    __shared__ float qn[48], kn[48];

    int b = blockIdx.x >> 3, h = blockIdx.x & 7;
    int tid = threadIdx.x;
    const float* qb = qkv + (size_t)b*HW_*1152 + h*48;
    const float* kb = qb + 384;
    const float* vb = qb + 768;
    int ty = tid >> 4, tx = tid & 15;

    float accS[3][3];
    #pragma unroll
    for (int i = 0; i < 3; i++)
        #pragma unroll
        for (int j = 0; j < 3; j++) accS[i][j] = 0.f;
    float nacc = 0.f;

    for (int t0 = 0; t0 < HW_; t0 += 64) {
        #pragma unroll
        for (int q = 0; q < 3; q++) {
            int id = tid*3 + q;
            int ni = id / 12;
            int d4 = (id % 12) * 4;
            float4 v = *(const float4*)(qb + (size_t)(t0+ni)*1152 + d4);
            qs[d4][ni] = v.x; qs[d4+1][ni] = v.y; qs[d4+2][ni] = v.z; qs[d4+3][ni] = v.w;
            v = *(const float4*)(kb + (size_t)(t0+ni)*1152 + d4);
            ks[d4][ni] = v.x; ks[d4+1][ni] = v.y; ks[d4+2][ni] = v.z; ks[d4+3][ni] = v.w;
        }
        __syncthreads();
        #pragma unroll 4
        for (int n = 0; n < 64; n++) {
            float qv[3], kv[3];
            #pragma unroll
            for (int i = 0; i < 3; i++) qv[i] = qs[ty*3+i][n];
            #pragma unroll
            for (int j = 0; j < 3; j++) kv[j] = ks[tx*3+j][n];
            #pragma unroll
            for (int i = 0; i < 3; i++)
                #pragma unroll
                for (int j = 0; j < 3; j++)
                    accS[i][j] = fmaf(qv[i], kv[j], accS[i][j]);
        }
        if (tid < 48) {
            #pragma unroll 4
            for (int n = 0; n < 64; n++) { float v = qs[tid][n]; nacc = fmaf(v, v, nacc); }
        } else if (tid < 96) {
            int d = tid - 48;
            #pragma unroll 4
            for (int n = 0; n < 64; n++) { float v = ks[d][n]; nacc = fmaf(v, v, nacc); }
        }
        __syncthreads();
    }

    #pragma unroll
    for (int i = 0; i < 3; i++)
        #pragma unroll
        for (int j = 0; j < 3; j++) Sm[ty*3+i][tx*3+j] = accS[i][j];
    if (tid < 48)      qn[tid]    = nacc;
    else if (tid < 96) kn[tid-48] = nacc;
    __syncthreads();

    if (tid < 48)      qn[tid]    = 1.f / fmaxf(sqrtf(qn[tid]),    1e-12f);
    else if (tid < 96) kn[tid-48] = 1.f / fmaxf(sqrtf(kn[tid-48]), 1e-12f);
    __syncthreads();

    if (tid < 48) {
        float iq = qn[tid];
        float mx = -1e30f;
        #pragma unroll
        for (int e = 0; e < 48; e++) {
            float l = Sm[tid][e] * iq * kn[e];
            Sm[tid][e] = l;
            mx = fmaxf(mx, l);
        }
        float s = 0.f;
        #pragma unroll
        for (int e = 0; e < 48; e++) {
            float ex = expf(Sm[tid][e] - mx);
            Sm[tid][e] = ex;
            s += ex;
        }
        float inv = 1.f / s;
        #pragma unroll
        for (int e = 0; e < 48; e++) Sm[tid][e] *= inv;
    }
    __syncthreads();

    for (int t0 = 0; t0 < HW_; t0 += 64) {
        #pragma unroll
        for (int q = 0; q < 3; q++) {
            int id = tid*3 + q;
            int ni = id / 12;
            int d4 = (id % 12) * 4;
            float4 v = *(const float4*)(vb + (size_t)(t0+ni)*1152 + d4);
            qs[d4][ni] = v.x; qs[d4+1][ni] = v.y; qs[d4+2][ni] = v.z; qs[d4+3][ni] = v.w;
        }
        __syncthreads();
        #pragma unroll
        for (int r = 0; r < 12; r++) {
            int idx = tid + 256*r;
            int d  = idx % 48;
            int ni = idx / 48;
            float acc = 0.f;
            #pragma unroll
            for (int e = 0; e < 48; e++)
                acc = fmaf(Sm[d][e], qs[e][ni], acc);
            out[((size_t)(b*HW_ + t0 + ni))*C_ + h*48 + d] = acc;
        }
        __syncthreads();
    }
}

// ---------------- launch ----------------
extern "C" void kernel_launch(void* const* d_in, const int* in_sizes, int n_in,
                              void* d_out, int out_size)
{
    (void)in_sizes; (void)n_in; (void)out_size;
    const float* x      = (const float*)d_in[0];
    const float* dw_w0  = (const float*)d_in[1];
    const float* dw_b0  = (const float*)d_in[2];
    const float* dw_w1  = (const float*)d_in[3];
    const float* dw_b1  = (const float*)d_in[4];
    const float* ln1_g  = (const float*)d_in[5];
    const float* ln1_b  = (const float*)d_in[6];
    const float* qkv_w  = (const float*)d_in[7];
    const float* proj_w = (const float*)d_in[8];
    const float* proj_b = (const float*)d_in[9];
    const float* ln2_g  = (const float*)d_in[10];
    const float* ln2_b  = (const float*)d_in[11];
    const float* m1dw   = (const float*)d_in[12];
    const float* m1uw   = (const float*)d_in[13];
    const float* m1ub   = (const float*)d_in[14];
    const float* m2dw   = (const float*)d_in[15];
    const float* m2uw   = (const float*)d_in[16];
    const float* m2ub   = (const float*)d_in[17];
    float* out = (float*)d_out;

    float *s1, *s2, *xfl, *lnb, *qkvb, *attb, *mid1, *hid, *mid2;
    cudaGetSymbolAddress((void**)&s1,   g_s1);
    cudaGetSymbolAddress((void**)&s2,   g_s2);
    cudaGetSymbolAddress((void**)&xfl,  g_xfl);
    cudaGetSymbolAddress((void**)&lnb,  g_ln);
    cudaGetSymbolAddress((void**)&qkvb, g_qkv);
    cudaGetSymbolAddress((void**)&attb, g_att);
    cudaGetSymbolAddress((void**)&mid1, g_mid1);
    cudaGetSymbolAddress((void**)&hid,  g_hid);
    cudaGetSymbolAddress((void**)&mid2, g_mid2);

    const int nconv = B_*SPLIT_*HW_;
    dim3 tp(32, 32);
    dim3 gt(HW_/32, C_/32, B_);

    // multi-scale depthwise chain
    dwconv_k<<<(nconv + 255)/256, 256>>>(x + (size_t)SPLIT_*HW_,   (size_t)C_*HW_,
                                         x,                        (size_t)C_*HW_,
                                         dw_w0, dw_b0, s1);
    dwconv_k<<<(nconv + 255)/256, 256>>>(x + (size_t)2*SPLIT_*HW_, (size_t)C_*HW_,
                                         s1,                       (size_t)SPLIT_*HW_,
                                         dw_w1, dw_b1, s2);
    gather_k<<<gt, tp>>>(x, xfl);

    // attention block
    ln_k<<<NTOK, 128>>>(xfl, ln1_g, ln1_b, lnb);
    gemm_tc<false,false,false><<<dim3(1152/64, NTOK/128), 256>>>(lnb, qkv_w, nullptr, qkvb, NTOK, 1152, 384);
    xca_k<<<B_*NH_, 256>>>(qkvb, attb);
    gemm_tc<true,true,false><<<dim3(384/64, NTOK/128), 256>>>(attb, proj_w, proj_b, xfl, NTOK, 384, 384);

    // MLP block
    ln_k<<<NTOK, 128>>>(xfl, ln2_g, ln2_b, lnb);
    gemm_tc<false,false,false><<<dim3(192/64,  NTOK/128), 256>>>(lnb,  m1dw, nullptr, mid1, NTOK, 192,  384);
    gemm_tc<true,false,true ><<<dim3(1536/64, NTOK/128), 256>>>(mid1, m1uw, m1ub,    hid,  NTOK, 1536, 192);
    gemm_tc<false,false,false><<<dim3(192/64,  NTOK/128), 256>>>(hid,  m2dw, nullptr, mid2, NTOK, 192,  1536);
    gemm_tc<true,true,false ><<<dim3(384/64,  NTOK/128), 256>>>(mid2, m2uw, m2ub,    xfl,  NTOK, 384,  192);

    // back to NCHW
    scatter_k<<<gt, tp>>>(xfl, out);
}

// round 7
// speedup vs baseline: 2.6759x; 1.8209x over previous
#include <cuda_runtime.h>
#include <cuda_bf16.h>
#include <stdint.h>
#include <math.h>

#define B_    16
#define C_    384
#define HW_   3136
#define W56   56
#define NTOK  (B_*HW_)     // 50176
#define NH_   8
#define HD_   48
#define SPLIT_ 128
#define HID_  1536
#define R_    192

typedef __nv_bfloat16 bf16;
typedef __nv_bfloat162 bf162;

// ---------------- scratch (device globals; no allocations) ----------------
__device__ float g_s1  [(size_t)B_*SPLIT_*HW_];
__device__ float g_s2  [(size_t)B_*SPLIT_*HW_];
__device__ float g_xfl [(size_t)NTOK*C_];
__device__ bf16  g_ln  [(size_t)NTOK*C_];
__device__ bf16  g_qkv [(size_t)NTOK*3*C_];
__device__ bf16  g_att [(size_t)NTOK*C_];
__device__ bf16  g_mid1[(size_t)NTOK*R_];
__device__ bf16  g_hid [(size_t)NTOK*HID_];
__device__ bf16  g_mid2[(size_t)NTOK*R_];
// bf16 weights
__device__ bf16  g_wqkv [(size_t)C_*3*C_];
__device__ bf16  g_wproj[(size_t)C_*C_];
__device__ bf16  g_w1d  [(size_t)C_*R_];
__device__ bf16  g_w1u  [(size_t)R_*HID_];
__device__ bf16  g_w2d  [(size_t)HID_*R_];
__device__ bf16  g_w2u  [(size_t)R_*C_];

// ---------------- fp32 -> bf16 weight conversion ----------------
__global__ void cvt_k(const float* __restrict__ in, bf16* __restrict__ out, int n)
{
    int i = (blockIdx.x * blockDim.x + threadIdx.x) * 4;
    if (i >= n) return;
    float4 v = *(const float4*)(in + i);
    bf162* o = (bf162*)(out + i);
    o[0] = __floats2bfloat162_rn(v.x, v.y);
    o[1] = __floats2bfloat162_rn(v.z, v.w);
}

// ---------------- depthwise conv: out = dwconv(a + b, w) + bias ----------------
__global__ void dwconv_k(const float* __restrict__ a, size_t strideA,
                         const float* __restrict__ bsrc, size_t strideB,
                         const float* __restrict__ w, const float* __restrict__ bias,
                         float* __restrict__ out)
{
    int idx = blockIdx.x * blockDim.x + threadIdx.x;
    if (idx >= B_*SPLIT_*HW_) return;
    int p = idx % HW_;
    int c = (idx / HW_) % SPLIT_;
    int b = idx / (HW_*SPLIT_);
    int y = p / W56, xq = p % W56;
    const float* pa = a    + (size_t)b*strideA + (size_t)c*HW_;
    const float* pb = bsrc + (size_t)b*strideB + (size_t)c*HW_;
    const float* wc = w + c*9;
    float acc = bias[c];
    #pragma unroll
    for (int dy = -1; dy <= 1; dy++) {
        int yy = y + dy;
        if (yy < 0 || yy >= W56) continue;
        #pragma unroll
        for (int dx = -1; dx <= 1; dx++) {
            int xx = xq + dx;
            if (xx < 0 || xx >= W56) continue;
            float v = pa[yy*W56 + xx] + pb[yy*W56 + xx];
            acc = fmaf(v, wc[(dy+1)*3 + (dx+1)], acc);
        }
    }
    out[idx] = acc;
}

// ------------- gather concat[s0, s1, s2] NCHW -> xflat [B*N, C] -------------
__global__ void gather_k(const float* __restrict__ x, float* __restrict__ xflat)
{
    __shared__ float t[32][33];
    int b = blockIdx.z;
    int c0 = blockIdx.y * 32, p0 = blockIdx.x * 32;
    int tx = threadIdx.x, ty = threadIdx.y;
    int c = c0 + ty, p = p0 + tx;
    float v;
    if (c < 128)      v = x[((size_t)b*C_ + c)*HW_ + p];
    else if (c < 256) v = g_s1[((size_t)b*SPLIT_ + (c-128))*HW_ + p];
    else              v = g_s2[((size_t)b*SPLIT_ + (c-256))*HW_ + p];
    t[ty][tx] = v;
    __syncthreads();
    xflat[((size_t)b*HW_ + p0 + ty)*C_ + c0 + tx] = t[tx][ty];
}

__global__ void scatter_k(const float* __restrict__ xflat, float* __restrict__ out)
{
    __shared__ float t[32][33];
    int b = blockIdx.z;
    int c0 = blockIdx.y * 32, p0 = blockIdx.x * 32;
    int tx = threadIdx.x, ty = threadIdx.y;
    t[ty][tx] = xflat[((size_t)b*HW_ + p0 + ty)*C_ + c0 + tx];
    __syncthreads();
    out[((size_t)b*C_ + c0 + ty)*HW_ + p0 + tx] = t[tx][ty];
}

// ---------------- LayerNorm over C=384, bf16 output ----------------
__device__ __forceinline__ float warp_sum(float v)
{
    #pragma unroll
    for (int o = 16; o > 0; o >>= 1) v += __shfl_xor_sync(0xffffffffu, v, o);
    return v;
}

__global__ void __launch_bounds__(128) ln_k(const float* __restrict__ in,
                                            const float* __restrict__ gam,
                                            const float* __restrict__ bet,
                                            bf16* __restrict__ outp)
{
    int row = blockIdx.x;
    int tid = threadIdx.x;
    const float* r = in + (size_t)row*C_;
    float v0 = r[tid], v1 = r[tid+128], v2 = r[tid+256];
    __shared__ float red[4];
    int wid = tid >> 5, lane = tid & 31;
    float s = warp_sum(v0 + v1 + v2);
    if (lane == 0) red[wid] = s;
    __syncthreads();
    float mean = (red[0]+red[1]+red[2]+red[3]) * (1.f/384.f);
    float d0 = v0 - mean, d1 = v1 - mean, d2 = v2 - mean;
    float sq = warp_sum(d0*d0 + d1*d1 + d2*d2);
    __syncthreads();
    if (lane == 0) red[wid] = sq;
    __syncthreads();
    float var = (red[0]+red[1]+red[2]+red[3]) * (1.f/384.f);
    float rs = rsqrtf(var + 1e-6f);
    bf16* o = outp + (size_t)row*C_;
    o[tid]     = __float2bfloat16(d0*rs*gam[tid]     + bet[tid]);
    o[tid+128] = __float2bfloat16(d1*rs*gam[tid+128] + bet[tid+128]);
    o[tid+256] = __float2bfloat16(d2*rs*gam[tid+256] + bet[tid+256]);
}

// ================= bf16 tensor-core GEMM (ldmatrix + cp.async) =================
__device__ __forceinline__ uint32_t smem_u32(const void* p)
{
    return (uint32_t)__cvta_generic_to_shared(p);
}
__device__ __forceinline__ void cp16(uint32_t dst, const void* src)
{
    asm volatile("cp.async.cg.shared.global [%0], [%1], 16;" :: "r"(dst), "l"(src));
}
__device__ __forceinline__ void cpcommit()
{
    asm volatile("cp.async.commit_group;" ::: "memory");
}
__device__ __forceinline__ void cpwait0()
{
    asm volatile("cp.async.wait_group 0;" ::: "memory");
}
__device__ __forceinline__ void cpwait1()
{
    asm volatile("cp.async.wait_group 1;" ::: "memory");
}
__device__ __forceinline__ void ldsm4(uint32_t* r, uint32_t addr)
{
    asm volatile("ldmatrix.sync.aligned.m8n8.x4.shared.b16 {%0,%1,%2,%3}, [%4];"
        : "=r"(r[0]), "=r"(r[1]), "=r"(r[2]), "=r"(r[3]) : "r"(addr));
}
__device__ __forceinline__ void ldsm4t(uint32_t* r, uint32_t addr)
{
    asm volatile("ldmatrix.sync.aligned.m8n8.x4.trans.shared.b16 {%0,%1,%2,%3}, [%4];"
        : "=r"(r[0]), "=r"(r[1]), "=r"(r[2]), "=r"(r[3]) : "r"(addr));
}
__device__ __forceinline__ void mma_bf16(float* c, const uint32_t* a, const uint32_t* b)
{
    asm volatile(
        "mma.sync.aligned.m16n8k16.row.col.f32.bf16.bf16.f32 "
        "{%0,%1,%2,%3}, {%4,%5,%6,%7}, {%8,%9}, {%0,%1,%2,%3};"
        : "+f"(c[0]), "+f"(c[1]), "+f"(c[2]), "+f"(c[3])
        : "r"(a[0]), "r"(a[1]), "r"(a[2]), "r"(a[3]), "r"(b[0]), "r"(b[1]));
}

// epilogue store helpers: overload on output pointer type (no if constexpr)
__device__ __forceinline__ void epi_store(float* cp, float r0, float r1, bool accum)
{
    float2* p2 = (float2*)cp;
    if (accum) {
        float2 o = *p2;
        r0 += o.x; r1 += o.y;
    }
    *p2 = make_float2(r0, r1);
}
__device__ __forceinline__ void epi_store(bf16* cp, float r0, float r1, bool accum)
{
    (void)accum;
    *(bf162*)cp = __floats2bfloat162_rn(r0, r1);
}

__device__ __forceinline__ void loadA_tile(bf16 (&As)[128][64], const bf16* Ap,
                                           int K, int k0, int tid)
{
    #pragma unroll
    for (int i = 0; i < 4; i++) {
        int q = tid + 256*i;
        int row = q >> 3, c = q & 7;
        int cs = c ^ (row & 7);
        cp16(smem_u32(&As[row][cs*8]), Ap + (size_t)row*K + k0 + c*8);
    }
}
__device__ __forceinline__ void loadB_tile(bf16 (&Bs)[64][64], const bf16* Bp,
                                           int Nn, int k0, int tid)
{
    #pragma unroll
    for (int i = 0; i < 2; i++) {
        int q = tid + 256*i;
        int row = q >> 3, c = q & 7;
        int cs = c ^ (row & 7);
        cp16(smem_u32(&Bs[row][cs*8]), Bp + (size_t)(k0 + row)*Nn + c*8);
    }
}

// BM=128, BN=64, BK=64; 256 threads = 8 warps (4 m x 2 n), warp tile 32x32.
template<typename TOUT, bool BIAS, bool ACCUM, bool GELU_ACT>
__global__ void __launch_bounds__(256) gemm_bf(const bf16* __restrict__ A,
                                               const bf16* __restrict__ Bw,
                                               const float* __restrict__ bias,
                                               TOUT* __restrict__ C,
                                               int M, int Nn, int K)
{
    __shared__ bf16 As[2][128][64];
    __shared__ bf16 Bs[2][64][64];

    int tid = threadIdx.x;
    int w = tid >> 5, lane = tid & 31;
    int g = lane >> 2, t = lane & 3;
    int moff = (w & 3) * 32, noff = (w >> 2) * 32;
    int m0 = blockIdx.y * 128, n0 = blockIdx.x * 64;

    const bf16* Ap = A + (size_t)m0 * K;
    const bf16* Bp = Bw + n0;

    float acc[2][4][4];
    #pragma unroll
    for (int i = 0; i < 2; i++)
        #pragma unroll
        for (int j = 0; j < 4; j++)
            #pragma unroll
            for (int q = 0; q < 4; q++) acc[i][j][q] = 0.f;

    loadA_tile(As[0], Ap, K, 0, tid);
    loadB_tile(Bs[0], Bp, Nn, 0, tid);
    cpcommit();

    int nk = K >> 6;
    for (int it = 0; it < nk; it++) {
        int buf = it & 1;
        if (it + 1 < nk) {
            int k0 = (it + 1) << 6;
            loadA_tile(As[buf ^ 1], Ap, K, k0, tid);
            loadB_tile(Bs[buf ^ 1], Bp, Nn, k0, tid);
            cpcommit();
            cpwait1();
        } else {
            cpwait0();
        }
        __syncthreads();
        #pragma unroll
        for (int ks = 0; ks < 4; ks++) {
            uint32_t af[2][4], bfr[2][4];
            #pragma unroll
            for (int i = 0; i < 2; i++) {
                int mr = moff + i*16 + (lane & 15);
                int cc = (ks*2 + (lane >> 4)) ^ (mr & 7);
                ldsm4(af[i], smem_u32(&As[buf][mr][cc*8]));
            }
            #pragma unroll
            for (int jj = 0; jj < 2; jj++) {
                int kr = ks*16 + (lane & 15);
                int cc = (((noff + jj*16) >> 3) + (lane >> 4)) ^ (kr & 7);
                ldsm4t(bfr[jj], smem_u32(&Bs[buf][kr][cc*8]));
            }
            #pragma unroll
            for (int i = 0; i < 2; i++) {
                mma_bf16(acc[i][0], af[i], &bfr[0][0]);
                mma_bf16(acc[i][1], af[i], &bfr[0][2]);
                mma_bf16(acc[i][2], af[i], &bfr[1][0]);
                mma_bf16(acc[i][3], af[i], &bfr[1][2]);
            }
        }
        __syncthreads();
    }

    // epilogue
    #pragma unroll
    for (int i = 0; i < 2; i++) {
        #pragma unroll
        for (int j = 0; j < 4; j++) {
            int col = n0 + noff + j*8 + t*2;
            float b0 = 0.f, b1 = 0.f;
            if (BIAS) { b0 = bias[col]; b1 = bias[col+1]; }
            #pragma unroll
            for (int hh = 0; hh < 2; hh++) {
                int row = m0 + moff + i*16 + g + hh*8;
                float r0 = acc[i][j][hh*2]   + b0;
                float r1 = acc[i][j][hh*2+1] + b1;
                if (GELU_ACT) {
                    r0 = 0.5f * r0 * (1.f + erff(r0 * 0.70710678118654752f));
                    r1 = 0.5f * r1 * (1.f + erff(r1 * 0.70710678118654752f));
                }
                epi_store(C + (size_t)row*Nn + col, r0, r1, ACCUM);
            }
        }
    }
}

// ---------------- XCA attention: one CTA per (b, h), bf16 in/out ----------------
__device__ __forceinline__ float4 ld4bf(const bf16* p)
{
    uint2 u = *reinterpret_cast<const uint2*>(p);
    bf162 p0 = *reinterpret_cast<bf162*>(&u.x);
    bf162 p1 = *reinterpret_cast<bf162*>(&u.y);
    float2 f0 = __bfloat1622float2(p0);
    float2 f1 = __bfloat1622float2(p1);
    return make_float4(f0.x, f0.y, f1.x, f1.y);
}

__global__ void __launch_bounds__(256) xca_k(const bf16* __restrict__ qkv,
                                             bf16* __restrict__ out)
{
    __shared__ float qs[48][65];
    __shared__ float ks[48][65];
    __shared__ float Sm[48][49];
    __shared__ float qn[48], kn[48];

    int b = blockIdx.x >> 3, h = blockIdx.x & 7;
    int tid = threadIdx.x;
    const bf16* qb = qkv + (size_t)b*HW_*1152 + h*48;
    const bf16* kb = qb + 384;
    const bf16* vb = qb + 768;
    int ty = tid >> 4, tx = tid & 15;

    float accS[3][3];
    #pragma unroll
    for (int i = 0; i < 3; i++)
        #pragma unroll
        for (int j = 0; j < 3; j++) accS[i][j] = 0.f;
    float nacc = 0.f;

    for (int t0 = 0; t0 < HW_; t0 += 64) {
        #pragma unroll
        for (int q = 0; q < 3; q++) {
            int id = tid*3 + q;
            int ni = id / 12;
            int d4 = (id % 12) * 4;
            float4 v = ld4bf(qb + (size_t)(t0+ni)*1152 + d4);
            qs[d4][ni] = v.x; qs[d4+1][ni] = v.y; qs[d4+2][ni] = v.z; qs[d4+3][ni] = v.w;
            v = ld4bf(kb + (size_t)(t0+ni)*1152 + d4);
            ks[d4][ni] = v.x; ks[d4+1][ni] = v.y; ks[d4+2][ni] = v.z; ks[d4+3][ni] = v.w;
        }
        __syncthreads();
        #pragma unroll 4
        for (int n = 0; n < 64; n++) {
            float qv[3], kv[3];
            #pragma unroll
            for (int i = 0; i < 3; i++) qv[i] = qs[ty*3+i][n];
            #pragma unroll
            for (int j = 0; j < 3; j++) kv[j] = ks[tx*3+j][n];
            #pragma unroll
            for (int i = 0; i < 3; i++)
                #pragma unroll
                for (int j = 0; j < 3; j++)
                    accS[i][j] = fmaf(qv[i], kv[j], accS[i][j]);
        }
        if (tid < 48) {
            #pragma unroll 4
            for (int n = 0; n < 64; n++) { float v = qs[tid][n]; nacc = fmaf(v, v, nacc); }
        } else if (tid < 96) {
            int d = tid - 48;
            #pragma unroll 4
            for (int n = 0; n < 64; n++) { float v = ks[d][n]; nacc = fmaf(v, v, nacc); }
        }
        __syncthreads();
    }

    #pragma unroll
    for (int i = 0; i < 3; i++)
        #pragma unroll
        for (int j = 0; j < 3; j++) Sm[ty*3+i][tx*3+j] = accS[i][j];
    if (tid < 48)      qn[tid]    = nacc;
    else if (tid < 96) kn[tid-48] = nacc;
    __syncthreads();

    if (tid < 48)      qn[tid]    = 1.f / fmaxf(sqrtf(qn[tid]),    1e-12f);
    else if (tid < 96) kn[tid-48] = 1.f / fmaxf(sqrtf(kn[tid-48]), 1e-12f);
    __syncthreads();

    if (tid < 48) {
        float iq = qn[tid];
        float mx = -1e30f;
        #pragma unroll
        for (int e = 0; e < 48; e++) {
            float l = Sm[tid][e] * iq * kn[e];
            Sm[tid][e] = l;
            mx = fmaxf(mx, l);
        }
        float s = 0.f;
        #pragma unroll
        for (int e = 0; e < 48; e++) {
            float ex = expf(Sm[tid][e] - mx);
            Sm[tid][e] = ex;
            s += ex;
        }
        float inv = 1.f / s;
        #pragma unroll
        for (int e = 0; e < 48; e++) Sm[tid][e] *= inv;
    }
    __syncthreads();

    for (int t0 = 0; t0 < HW_; t0 += 64) {
        #pragma unroll
        for (int q = 0; q < 3; q++) {
            int id = tid*3 + q;
            int ni = id / 12;
            int d4 = (id % 12) * 4;
            float4 v = ld4bf(vb + (size_t)(t0+ni)*1152 + d4);
            qs[d4][ni] = v.x; qs[d4+1][ni] = v.y; qs[d4+2][ni] = v.z; qs[d4+3][ni] = v.w;
        }
        __syncthreads();
        #pragma unroll
        for (int r = 0; r < 12; r++) {
            int idx = tid + 256*r;
            int d  = idx % 48;
            int ni = idx / 48;
            float acc = 0.f;
            #pragma unroll
            for (int e = 0; e < 48; e++)
                acc = fmaf(Sm[d][e], qs[e][ni], acc);
            out[((size_t)(b*HW_ + t0 + ni))*C_ + h*48 + d] = __float2bfloat16(acc);
        }
        __syncthreads();
    }
}

// ---------------- launch ----------------
extern "C" void kernel_launch(void* const* d_in, const int* in_sizes, int n_in,
                              void* d_out, int out_size)
{
    (void)in_sizes; (void)n_in; (void)out_size;
    const float* x      = (const float*)d_in[0];
    const float* dw_w0  = (const float*)d_in[1];
    const float* dw_b0  = (const float*)d_in[2];
    const float* dw_w1  = (const float*)d_in[3];
    const float* dw_b1  = (const float*)d_in[4];
    const float* ln1_g  = (const float*)d_in[5];
    const float* ln1_b  = (const float*)d_in[6];
    const float* qkv_w  = (const float*)d_in[7];
    const float* proj_w = (const float*)d_in[8];
    const float* proj_b = (const float*)d_in[9];
    const float* ln2_g  = (const float*)d_in[10];
    const float* ln2_b  = (const float*)d_in[11];
    const float* m1dw   = (const float*)d_in[12];
    const float* m1uw   = (const float*)d_in[13];
    const float* m1ub   = (const float*)d_in[14];
    const float* m2dw   = (const float*)d_in[15];
    const float* m2uw   = (const float*)d_in[16];
    const float* m2ub   = (const float*)d_in[17];
    float* out = (float*)d_out;

    void* p = 0;
    cudaGetSymbolAddress(&p, g_s1);
    float* s1 = (float*)p;
    cudaGetSymbolAddress(&p, g_s2);
    float* s2 = (float*)p;
    cudaGetSymbolAddress(&p, g_xfl);
    float* xfl = (float*)p;
    cudaGetSymbolAddress(&p, g_ln);
    bf16* lnb = (bf16*)p;
    cudaGetSymbolAddress(&p, g_qkv);
    bf16* qkvb = (bf16*)p;
    cudaGetSymbolAddress(&p, g_att);
    bf16* attb = (bf16*)p;
    cudaGetSymbolAddress(&p, g_mid1);
    bf16* mid1 = (bf16*)p;
    cudaGetSymbolAddress(&p, g_hid);
    bf16* hid = (bf16*)p;
    cudaGetSymbolAddress(&p, g_mid2);
    bf16* mid2 = (bf16*)p;
    cudaGetSymbolAddress(&p, g_wqkv);
    bf16* wqkv = (bf16*)p;
    cudaGetSymbolAddress(&p, g_wproj);
    bf16* wproj = (bf16*)p;
    cudaGetSymbolAddress(&p, g_w1d);
    bf16* w1d = (bf16*)p;
    cudaGetSymbolAddress(&p, g_w1u);
    bf16* w1u = (bf16*)p;
    cudaGetSymbolAddress(&p, g_w2d);
    bf16* w2d = (bf16*)p;
    cudaGetSymbolAddress(&p, g_w2u);
    bf16* w2u = (bf16*)p;

    // weight conversion fp32 -> bf16
    int ncv;
    ncv = C_*3*C_;
    cvt_k<<<(ncv/4 + 255)/256, 256>>>(qkv_w, wqkv, ncv);
    ncv = C_*C_;
    cvt_k<<<(ncv/4 + 255)/256, 256>>>(proj_w, wproj, ncv);
    ncv = C_*R_;
    cvt_k<<<(ncv/4 + 255)/256, 256>>>(m1dw, w1d, ncv);
    ncv = R_*HID_;
    cvt_k<<<(ncv/4 + 255)/256, 256>>>(m1uw, w1u, ncv);
    ncv = HID_*R_;
    cvt_k<<<(ncv/4 + 255)/256, 256>>>(m2dw, w2d, ncv);
    ncv = R_*C_;
    cvt_k<<<(ncv/4 + 255)/256, 256>>>(m2uw, w2u, ncv);

    const int nconv = B_*SPLIT_*HW_;
    dim3 tp(32, 32);
    dim3 gt(HW_/32, C_/32, B_);

    // multi-scale depthwise chain
    dwconv_k<<<(nconv + 255)/256, 256>>>(x + (size_t)SPLIT_*HW_,   (size_t)C_*HW_,
                                         x,                        (size_t)C_*HW_,
                                         dw_w0, dw_b0, s1);
    dwconv_k<<<(nconv + 255)/256, 256>>>(x + (size_t)2*SPLIT_*HW_, (size_t)C_*HW_,
                                         s1,                       (size_t)SPLIT_*HW_,
                                         dw_w1, dw_b1, s2);
    gather_k<<<gt, tp>>>(x, xfl);

    // attention block
    ln_k<<<NTOK, 128>>>(xfl, ln1_g, ln1_b, lnb);
    gemm_bf<bf16, false, false, false><<<dim3(1152/64, NTOK/128), 256>>>(lnb, wqkv, (const float*)0, qkvb, NTOK, 1152, 384);
    xca_k<<<B_*NH_, 256>>>(qkvb, attb);
    gemm_bf<float, true, true, false><<<dim3(384/64, NTOK/128), 256>>>(attb, wproj, proj_b, xfl, NTOK, 384, 384);

    // MLP block
    ln_k<<<NTOK, 128>>>(xfl, ln2_g, ln2_b, lnb);
    gemm_bf<bf16, false, false, false><<<dim3(192/64, NTOK/128), 256>>>(lnb, w1d, (const float*)0, mid1, NTOK, 192, 384);
    gemm_bf<bf16, true, false, true><<<dim3(1536/64, NTOK/128), 256>>>(mid1, w1u, m1ub, hid, NTOK, 1536, 192);
    gemm_bf<bf16, false, false, false><<<dim3(192/64, NTOK/128), 256>>>(hid, w2d, (const float*)0, mid2, NTOK, 192, 1536);
    gemm_bf<float, true, true, false><<<dim3(384/64, NTOK/128), 256>>>(mid2, w2u, m2ub, xfl, NTOK, 384, 192);

    // back to NCHW
    scatter_k<<<gt, tp>>>(xfl, out);
}

// round 8
// speedup vs baseline: 4.2004x; 1.5697x over previous
#include <cuda_runtime.h>
#include <cuda_bf16.h>
#include <stdint.h>
#include <math.h>

#define B_    16
#define C_    384
#define HW_   3136
#define W56   56
#define NTOK  (B_*HW_)     // 50176
#define NH_   8
#define HD_   48
#define SPLIT_ 128
#define HID_  1536
#define R_    192
#define XA_TOK 448
#define XA_CH  7

typedef __nv_bfloat16 bf16;
typedef __nv_bfloat162 bf162;

// ---------------- scratch (device globals; no allocations) ----------------
__device__ float g_s1  [(size_t)B_*SPLIT_*HW_];
__device__ float g_s2  [(size_t)B_*SPLIT_*HW_];
__device__ float g_xfl [(size_t)NTOK*C_];
__device__ bf16  g_ln  [(size_t)NTOK*C_];
__device__ bf16  g_qkv [(size_t)NTOK*3*C_];
__device__ bf16  g_att [(size_t)NTOK*C_];
__device__ bf16  g_mid1[(size_t)NTOK*R_];
__device__ bf16  g_hid [(size_t)NTOK*HID_];
__device__ bf16  g_mid2[(size_t)NTOK*R_];
// XCA intermediates
__device__ float g_S  [(size_t)128*2304];
__device__ float g_N  [(size_t)128*96];
__device__ bf16  g_aT [(size_t)128*2304];
// bf16 weights
__device__ bf16  g_wqkv [(size_t)C_*3*C_];
__device__ bf16  g_wproj[(size_t)C_*C_];
__device__ bf16  g_w1d  [(size_t)C_*R_];
__device__ bf16  g_w1u  [(size_t)R_*HID_];
__device__ bf16  g_w2d  [(size_t)HID_*R_];
__device__ bf16  g_w2u  [(size_t)R_*C_];

// ---------------- fp32 -> bf16 weight conversion (single kernel) ----------------
__global__ void cvt_all_k(const float* __restrict__ s0, const float* __restrict__ s1,
                          const float* __restrict__ s2, const float* __restrict__ s3,
                          const float* __restrict__ s4, const float* __restrict__ s5,
                          bf16* d0, bf16* d1, bf16* d2, bf16* d3, bf16* d4, bf16* d5)
{
    const int L0 = C_*3*C_, L1 = C_*C_, L2 = C_*R_, L3 = R_*HID_, L4 = HID_*R_, L5 = R_*C_;
    int i = (blockIdx.x*blockDim.x + threadIdx.x)*4;
    const float* s; bf16* d; int off = i;
    if (off < L0) { s = s0; d = d0; }
    else { off -= L0;
      if (off < L1) { s = s1; d = d1; }
      else { off -= L1;
        if (off < L2) { s = s2; d = d2; }
        else { off -= L2;
          if (off < L3) { s = s3; d = d3; }
          else { off -= L3;
            if (off < L4) { s = s4; d = d4; }
            else { off -= L4;
              if (off < L5) { s = s5; d = d5; }
              else return; } } } } }
    float4 v = *(const float4*)(s + off);
    bf162* o = (bf162*)(d + off);
    o[0] = __floats2bfloat162_rn(v.x, v.y);
    o[1] = __floats2bfloat162_rn(v.z, v.w);
}

__global__ void zero2_k(float* a, int na, float* b, int nb)
{
    int i = blockIdx.x*blockDim.x + threadIdx.x;
    if (i < na) a[i] = 0.f;
    else if (i - na < nb) b[i - na] = 0.f;
}

// ---------------- depthwise conv: out = dwconv(a + b, w) + bias ----------------
__global__ void dwconv_k(const float* __restrict__ a, size_t strideA,
                         const float* __restrict__ bsrc, size_t strideB,
                         const float* __restrict__ w, const float* __restrict__ bias,
                         float* __restrict__ out)
{
    int idx = blockIdx.x * blockDim.x + threadIdx.x;
    if (idx >= B_*SPLIT_*HW_) return;
    int p = idx % HW_;
    int c = (idx / HW_) % SPLIT_;
    int b = idx / (HW_*SPLIT_);
    int y = p / W56, xq = p % W56;
    const float* pa = a    + (size_t)b*strideA + (size_t)c*HW_;
    const float* pb = bsrc + (size_t)b*strideB + (size_t)c*HW_;
    const float* wc = w + c*9;
    float acc = bias[c];
    #pragma unroll
    for (int dy = -1; dy <= 1; dy++) {
        int yy = y + dy;
        if (yy < 0 || yy >= W56) continue;
        #pragma unroll
        for (int dx = -1; dx <= 1; dx++) {
            int xx = xq + dx;
            if (xx < 0 || xx >= W56) continue;
            float v = pa[yy*W56 + xx] + pb[yy*W56 + xx];
            acc = fmaf(v, wc[(dy+1)*3 + (dx+1)], acc);
        }
    }
    out[idx] = acc;
}

// ------------- gather concat[s0, s1, s2] NCHW -> xflat [B*N, C] -------------
__global__ void gather_k(const float* __restrict__ x, float* __restrict__ xflat)
{
    __shared__ float t[32][33];
    int b = blockIdx.z;
    int c0 = blockIdx.y * 32, p0 = blockIdx.x * 32;
    int tx = threadIdx.x, ty = threadIdx.y;
    int c = c0 + ty, p = p0 + tx;
    float v;
    if (c < 128)      v = x[((size_t)b*C_ + c)*HW_ + p];
    else if (c < 256) v = g_s1[((size_t)b*SPLIT_ + (c-128))*HW_ + p];
    else              v = g_s2[((size_t)b*SPLIT_ + (c-256))*HW_ + p];
    t[ty][tx] = v;
    __syncthreads();
    xflat[((size_t)b*HW_ + p0 + ty)*C_ + c0 + tx] = t[tx][ty];
}

__global__ void scatter_k(const float* __restrict__ xflat, float* __restrict__ out)
{
    __shared__ float t[32][33];
    int b = blockIdx.z;
    int c0 = blockIdx.y * 32, p0 = blockIdx.x * 32;
    int tx = threadIdx.x, ty = threadIdx.y;
    t[ty][tx] = xflat[((size_t)b*HW_ + p0 + ty)*C_ + c0 + tx];
    __syncthreads();
    out[((size_t)b*C_ + c0 + ty)*HW_ + p0 + tx] = t[tx][ty];
}

// ---------------- LayerNorm over C=384, bf16 output ----------------
__device__ __forceinline__ float warp_sum(float v)
{
    #pragma unroll
    for (int o = 16; o > 0; o >>= 1) v += __shfl_xor_sync(0xffffffffu, v, o);
    return v;
}

__global__ void __launch_bounds__(128) ln_k(const float* __restrict__ in,
                                            const float* __restrict__ gam,
                                            const float* __restrict__ bet,
                                            bf16* __restrict__ outp)
{
    int row = blockIdx.x;
    int tid = threadIdx.x;
    const float* r = in + (size_t)row*C_;
    float v0 = r[tid], v1 = r[tid+128], v2 = r[tid+256];
    __shared__ float red[4];
    int wid = tid >> 5, lane = tid & 31;
    float s = warp_sum(v0 + v1 + v2);
    if (lane == 0) red[wid] = s;
    __syncthreads();
    float mean = (red[0]+red[1]+red[2]+red[3]) * (1.f/384.f);
    float d0 = v0 - mean, d1 = v1 - mean, d2 = v2 - mean;
    float sq = warp_sum(d0*d0 + d1*d1 + d2*d2);
    __syncthreads();
    if (lane == 0) red[wid] = sq;
    __syncthreads();
    float var = (red[0]+red[1]+red[2]+red[3]) * (1.f/384.f);
    float rs = rsqrtf(var + 1e-6f);
    bf16* o = outp + (size_t)row*C_;
    o[tid]     = __float2bfloat16(d0*rs*gam[tid]     + bet[tid]);
    o[tid+128] = __float2bfloat16(d1*rs*gam[tid+128] + bet[tid+128]);
    o[tid+256] = __float2bfloat16(d2*rs*gam[tid+256] + bet[tid+256]);
}

// ================= shared MMA helpers =================
__device__ __forceinline__ uint32_t smem_u32(const void* p)
{
    return (uint32_t)__cvta_generic_to_shared(p);
}
__device__ __forceinline__ void cp16(uint32_t dst, const void* src)
{
    asm volatile("cp.async.cg.shared.global [%0], [%1], 16;" :: "r"(dst), "l"(src));
}
__device__ __forceinline__ void cpcommit()
{
    asm volatile("cp.async.commit_group;" ::: "memory");
}
__device__ __forceinline__ void cpwait0()
{
    asm volatile("cp.async.wait_group 0;" ::: "memory");
}
__device__ __forceinline__ void cpwait1()
{
    asm volatile("cp.async.wait_group 1;" ::: "memory");
}
__device__ __forceinline__ void ldsm4(uint32_t* r, uint32_t addr)
{
    asm volatile("ldmatrix.sync.aligned.m8n8.x4.shared.b16 {%0,%1,%2,%3}, [%4];"
        : "=r"(r[0]), "=r"(r[1]), "=r"(r[2]), "=r"(r[3]) : "r"(addr));
}
__device__ __forceinline__ void ldsm4t(uint32_t* r, uint32_t addr)
{
    asm volatile("ldmatrix.sync.aligned.m8n8.x4.trans.shared.b16 {%0,%1,%2,%3}, [%4];"
        : "=r"(r[0]), "=r"(r[1]), "=r"(r[2]), "=r"(r[3]) : "r"(addr));
}
__device__ __forceinline__ void mma_bf16(float* c, const uint32_t* a, const uint32_t* b)
{
    asm volatile(
        "mma.sync.aligned.m16n8k16.row.col.f32.bf16.bf16.f32 "
        "{%0,%1,%2,%3}, {%4,%5,%6,%7}, {%8,%9}, {%0,%1,%2,%3};"
        : "+f"(c[0]), "+f"(c[1]), "+f"(c[2]), "+f"(c[3])
        : "r"(a[0]), "r"(a[1]), "r"(a[2]), "r"(a[3]), "r"(b[0]), "r"(b[1]));
}

// epilogue store helpers: overload on output pointer type
__device__ __forceinline__ void epi_store(float* cp, float r0, float r1, bool accum)
{
    float2* p2 = (float2*)cp;
    if (accum) {
        float2 o = *p2;
        r0 += o.x; r1 += o.y;
    }
    *p2 = make_float2(r0, r1);
}
__device__ __forceinline__ void epi_store(bf16* cp, float r0, float r1, bool accum)
{
    (void)accum;
    *(bf162*)cp = __floats2bfloat162_rn(r0, r1);
}

__device__ __forceinline__ void loadA_tile(bf16 (&As)[128][64], const bf16* Ap,
                                           int K, int k0, int tid)
{
    #pragma unroll
    for (int i = 0; i < 4; i++) {
        int q = tid + 256*i;
        int row = q >> 3, c = q & 7;
        int cs = c ^ (row & 7);
        cp16(smem_u32(&As[row][cs*8]), Ap + (size_t)row*K + k0 + c*8);
    }
}
__device__ __forceinline__ void loadB_tile(bf16 (&Bs)[64][64], const bf16* Bp,
                                           int Nn, int k0, int tid)
{
    #pragma unroll
    for (int i = 0; i < 2; i++) {
        int q = tid + 256*i;
        int row = q >> 3, c = q & 7;
        int cs = c ^ (row & 7);
        cp16(smem_u32(&Bs[row][cs*8]), Bp + (size_t)(k0 + row)*Nn + c*8);
    }
}

// BM=128, BN=64, BK=64; 256 threads = 8 warps (4 m x 2 n), warp tile 32x32.
template<typename TOUT, bool BIAS, bool ACCUM, bool GELU_ACT>
__global__ void __launch_bounds__(256) gemm_bf(const bf16* __restrict__ A,
                                               const bf16* __restrict__ Bw,
                                               const float* __restrict__ bias,
                                               TOUT* __restrict__ C,
                                               int M, int Nn, int K)
{
    __shared__ bf16 As[2][128][64];
    __shared__ bf16 Bs[2][64][64];

    int tid = threadIdx.x;
    int w = tid >> 5, lane = tid & 31;
    int g = lane >> 2, t = lane & 3;
    int moff = (w & 3) * 32, noff = (w >> 2) * 32;
    int m0 = blockIdx.y * 128, n0 = blockIdx.x * 64;

    const bf16* Ap = A + (size_t)m0 * K;
    const bf16* Bp = Bw + n0;

    float acc[2][4][4];
    #pragma unroll
    for (int i = 0; i < 2; i++)
        #pragma unroll
        for (int j = 0; j < 4; j++)
            #pragma unroll
            for (int q = 0; q < 4; q++) acc[i][j][q] = 0.f;

    loadA_tile(As[0], Ap, K, 0, tid);
    loadB_tile(Bs[0], Bp, Nn, 0, tid);
    cpcommit();

    int nk = K >> 6;
    for (int it = 0; it < nk; it++) {
        int buf = it & 1;
        if (it + 1 < nk) {
            int k0 = (it + 1) << 6;
            loadA_tile(As[buf ^ 1], Ap, K, k0, tid);
            loadB_tile(Bs[buf ^ 1], Bp, Nn, k0, tid);
            cpcommit();
            cpwait1();
        } else {
            cpwait0();
        }
        __syncthreads();
        #pragma unroll
        for (int ks = 0; ks < 4; ks++) {
            uint32_t af[2][4], bfr[2][4];
            #pragma unroll
            for (int i = 0; i < 2; i++) {
                int mr = moff + i*16 + (lane & 15);
                int cc = (ks*2 + (lane >> 4)) ^ (mr & 7);
                ldsm4(af[i], smem_u32(&As[buf][mr][cc*8]));
            }
            #pragma unroll
            for (int jj = 0; jj < 2; jj++) {
                int kr = ks*16 + (lane & 15);
                int cc = (((noff + jj*16) >> 3) + (lane >> 4)) ^ (kr & 7);
                ldsm4t(bfr[jj], smem_u32(&Bs[buf][kr][cc*8]));
            }
            #pragma unroll
            for (int i = 0; i < 2; i++) {
                mma_bf16(acc[i][0], af[i], &bfr[0][0]);
                mma_bf16(acc[i][1], af[i], &bfr[0][2]);
                mma_bf16(acc[i][2], af[i], &bfr[1][0]);
                mma_bf16(acc[i][3], af[i], &bfr[1][2]);
            }
        }
        __syncthreads();
    }

    // epilogue
    #pragma unroll
    for (int i = 0; i < 2; i++) {
        #pragma unroll
        for (int j = 0; j < 4; j++) {
            int col = n0 + noff + j*8 + t*2;
            float b0 = 0.f, b1 = 0.f;
            if (BIAS) { b0 = bias[col]; b1 = bias[col+1]; }
            #pragma unroll
            for (int hh = 0; hh < 2; hh++) {
                int row = m0 + moff + i*16 + g + hh*8;
                float r0 = acc[i][j][hh*2]   + b0;
                float r1 = acc[i][j][hh*2+1] + b1;
                if (GELU_ACT) {
                    r0 = 0.5f * r0 * (1.f + erff(r0 * 0.70710678118654752f));
                    r1 = 0.5f * r1 * (1.f + erff(r1 * 0.70710678118654752f));
                }
                epi_store(C + (size_t)row*Nn + col, r0, r1, ACCUM);
            }
        }
    }
}

// ================= XCA phase A: partial S = q @ k^T + norms (MMA) =================
// grid (128 bh, 7 chunks), 256 threads. Dynamic smem.
__global__ void __launch_bounds__(256) xca_s_k(const bf16* __restrict__ qkv,
                                               float* __restrict__ gS,
                                               float* __restrict__ gN)
{
    extern __shared__ char smraw[];
    bf16*  q_s = (bf16*)smraw;                                // [48][456]
    bf16*  k_s = (bf16*)(smraw + 48*456*2);                   // [448][56]
    float* Ss  = (float*)(smraw + 48*456*2 + (size_t)XA_TOK*56*2); // [48][48]
    float* ns  = Ss + 48*48;                                  // [96]

    int bh = blockIdx.x, chunk = blockIdx.y;
    int b = bh >> 3, h = bh & 7;
    int tid = threadIdx.x;
    int w = tid >> 5, lane = tid & 31;
    int g = lane >> 2, t = lane & 3;
    const bf16* qb = qkv + ((size_t)b*HW_ + chunk*XA_TOK)*1152 + h*48;
    const bf16* kb = qb + 384;

    // k tile (token-major, row pad 56) via cp.async
    for (int i = tid; i < XA_TOK*6; i += 256) {
        int row = i/6, c = i%6;
        cp16(smem_u32(k_s + row*56 + c*8), kb + (size_t)row*1152 + c*8);
    }
    cpcommit();
    // q tile transposed (d-major, row pad 456)
    for (int i = tid; i < XA_TOK*24; i += 256) {
        int tok = i/24, dp = i%24;
        bf162 v = *(const bf162*)(qb + (size_t)tok*1152 + dp*2);
        q_s[(dp*2  )*456 + tok] = v.x;
        q_s[(dp*2+1)*456 + tok] = v.y;
    }
    // zero reduction buffers
    for (int i = tid; i < 48*48; i += 256) Ss[i] = 0.f;
    if (tid < 96) ns[tid] = 0.f;
    cpwait0();
    __syncthreads();

    // partial squared norms (96 rows x 4 segments of 112 tokens)
    for (int u = tid; u < 384; u += 256) {
        int r = u >> 2, seg = u & 3;
        float acc = 0.f;
        if (r < 48) {
            const bf16* p = q_s + r*456 + seg*112;
            for (int x = 0; x < 112; x++) {
                float v = __bfloat162float(p[x]);
                acc = fmaf(v, v, acc);
            }
        } else {
            const bf16* p = k_s + (r - 48) + seg*112*56;
            for (int x = 0; x < 112; x++) {
                float v = __bfloat162float(p[x*56]);
                acc = fmaf(v, v, acc);
            }
        }
        atomicAdd(&ns[r], acc);
    }

    // MMA: S[48][48], 3 m-tiles x 6 n-tiles, warp w does k-steps w, w+8, ...
    float acc[3][6][4];
    #pragma unroll
    for (int i = 0; i < 3; i++)
        #pragma unroll
        for (int j = 0; j < 6; j++)
            #pragma unroll
            for (int q = 0; q < 4; q++) acc[i][j][q] = 0.f;

    for (int s = w; s < 28; s += 8) {
        int k0 = s*16;
        uint32_t af[3][4], bfr[3][4];
        #pragma unroll
        for (int i = 0; i < 3; i++)
            ldsm4(af[i], smem_u32(q_s + (i*16 + (lane & 15))*456 + k0 + (lane >> 4)*8));
        #pragma unroll
        for (int jj = 0; jj < 3; jj++)
            ldsm4t(bfr[jj], smem_u32(k_s + (k0 + (lane & 15))*56 + jj*16 + (lane >> 4)*8));
        #pragma unroll
        for (int i = 0; i < 3; i++) {
            #pragma unroll
            for (int jj = 0; jj < 3; jj++) {
                mma_bf16(acc[i][jj*2  ], af[i], &bfr[jj][0]);
                mma_bf16(acc[i][jj*2+1], af[i], &bfr[jj][2]);
            }
        }
    }

    // reduce warps into Ss
    #pragma unroll
    for (int i = 0; i < 3; i++) {
        #pragma unroll
        for (int j = 0; j < 6; j++) {
            int r0 = i*16 + g, c0 = j*8 + t*2;
            atomicAdd(&Ss[r0*48 + c0    ], acc[i][j][0]);
            atomicAdd(&Ss[r0*48 + c0 + 1], acc[i][j][1]);
            atomicAdd(&Ss[(r0+8)*48 + c0    ], acc[i][j][2]);
            atomicAdd(&Ss[(r0+8)*48 + c0 + 1], acc[i][j][3]);
        }
    }
    __syncthreads();

    for (int i = tid; i < 48*48; i += 256)
        atomicAdd(&gS[(size_t)bh*2304 + i], Ss[i]);
    if (tid < 96)
        atomicAdd(&gN[bh*96 + tid], ns[tid]);
}

// ================= XCA softmax: combine + normalize + softmax -> attn^T bf16 =====
__global__ void __launch_bounds__(96) xca_soft_k(const float* __restrict__ gS,
                                                 const float* __restrict__ gN,
                                                 bf16* __restrict__ gAT)
{
    __shared__ float iq[48], ik[48];
    int bh = blockIdx.x, tid = threadIdx.x;
    if (tid < 48)      iq[tid]    = 1.f / fmaxf(sqrtf(gN[bh*96 + tid]), 1e-12f);
    else               ik[tid-48] = 1.f / fmaxf(sqrtf(gN[bh*96 + tid]), 1e-12f);
    __syncthreads();
    if (tid < 48) {
        float row[48];
        const float* S = gS + (size_t)bh*2304 + tid*48;
        float mx = -1e30f;
        #pragma unroll 8
        for (int e = 0; e < 48; e++) {
            float l = S[e] * iq[tid] * ik[e];
            row[e] = l;
            mx = fmaxf(mx, l);
        }
        float sum = 0.f;
        #pragma unroll 8
        for (int e = 0; e < 48; e++) {
            float ex = expf(row[e] - mx);
            row[e] = ex;
            sum += ex;
        }
        float inv = 1.f / sum;
        #pragma unroll 8
        for (int e = 0; e < 48; e++)
            gAT[(size_t)bh*2304 + e*48 + tid] = __float2bfloat16(row[e] * inv);
    }
}

// ================= XCA phase C: y = v @ attn^T (MMA) =================
// grid (128 bh, 7 chunks), 224 threads = 7 warps, each warp one 64-token tile.
__global__ void __launch_bounds__(224) xca_av_k(const bf16* __restrict__ qkv,
                                                const bf16* __restrict__ gAT,
                                                bf16* __restrict__ outp)
{
    extern __shared__ char smraw[];
    bf16* v_s = (bf16*)smraw;                           // [448][56]
    bf16* aT  = (bf16*)(smraw + (size_t)XA_TOK*56*2);   // [48][56]

    int bh = blockIdx.x, chunk = blockIdx.y;
    int b = bh >> 3, h = bh & 7;
    int tid = threadIdx.x;
    int w = tid >> 5, lane = tid & 31;
    int g = lane >> 2, t = lane & 3;
    const bf16* vb = qkv + ((size_t)b*HW_ + chunk*XA_TOK)*1152 + h*48 + 768;

    for (int i = tid; i < XA_TOK*6; i += 224) {
        int row = i/6, c = i%6;
        cp16(smem_u32(v_s + row*56 + c*8), vb + (size_t)row*1152 + c*8);
    }
    for (int i = tid; i < 48*6; i += 224) {
        int e = i/6, c = i%6;
        cp16(smem_u32(aT + e*56 + c*8), gAT + (size_t)bh*2304 + e*48 + c*8);
    }
    cpcommit();
    cpwait0();
    __syncthreads();

    int tk0 = w*64;
    float acc[4][6][4];
    #pragma unroll
    for (int i = 0; i < 4; i++)
        #pragma unroll
        for (int j = 0; j < 6; j++)
            #pragma unroll
            for (int q = 0; q < 4; q++) acc[i][j][q] = 0.f;

    #pragma unroll
    for (int ks = 0; ks < 3; ks++) {
        int k0 = ks*16;
        uint32_t af[4][4], bfr[3][4];
        #pragma unroll
        for (int i = 0; i < 4; i++)
            ldsm4(af[i], smem_u32(v_s + (tk0 + i*16 + (lane & 15))*56 + k0 + (lane >> 4)*8));
        #pragma unroll
        for (int jj = 0; jj < 3; jj++)
            ldsm4t(bfr[jj], smem_u32(aT + (k0 + (lane & 15))*56 + jj*16 + (lane >> 4)*8));
        #pragma unroll
        for (int i = 0; i < 4; i++) {
            #pragma unroll
            for (int jj = 0; jj < 3; jj++) {
                mma_bf16(acc[i][jj*2  ], af[i], &bfr[jj][0]);
                mma_bf16(acc[i][jj*2+1], af[i], &bfr[jj][2]);
            }
        }
    }

    size_t tokbase = (size_t)b*HW_ + (size_t)chunk*XA_TOK + tk0;
    #pragma unroll
    for (int i = 0; i < 4; i++) {
        #pragma unroll
        for (int j = 0; j < 6; j++) {
            int r0 = i*16 + g, c0 = j*8 + t*2;
            *(bf162*)(outp + (tokbase + r0)*C_ + h*48 + c0) =
                __floats2bfloat162_rn(acc[i][j][0], acc[i][j][1]);
            *(bf162*)(outp + (tokbase + r0 + 8)*C_ + h*48 + c0) =
                __floats2bfloat162_rn(acc[i][j][2], acc[i][j][3]);
        }
    }
}

// ---------------- launch ----------------
extern "C" void kernel_launch(void* const* d_in, const int* in_sizes, int n_in,
                              void* d_out, int out_size)
{
    (void)in_sizes; (void)n_in; (void)out_size;
    const float* x      = (const float*)d_in[0];
    const float* dw_w0  = (const float*)d_in[1];
    const float* dw_b0  = (const float*)d_in[2];
    const float* dw_w1  = (const float*)d_in[3];
    const float* dw_b1  = (const float*)d_in[4];
    const float* ln1_g  = (const float*)d_in[5];
    const float* ln1_b  = (const float*)d_in[6];
    const float* qkv_w  = (const float*)d_in[7];
    const float* proj_w = (const float*)d_in[8];
    const float* proj_b = (const float*)d_in[9];
    const float* ln2_g  = (const float*)d_in[10];
    const float* ln2_b  = (const float*)d_in[11];
    const float* m1dw   = (const float*)d_in[12];
    const float* m1uw   = (const float*)d_in[13];
    const float* m1ub   = (const float*)d_in[14];
    const float* m2dw   = (const float*)d_in[15];
    const float* m2uw   = (const float*)d_in[16];
    const float* m2ub   = (const float*)d_in[17];
    float* out = (float*)d_out;

    void* p = 0;
    cudaGetSymbolAddress(&p, g_s1);
    float* s1 = (float*)p;
    cudaGetSymbolAddress(&p, g_s2);
    float* s2 = (float*)p;
    cudaGetSymbolAddress(&p, g_xfl);
    float* xfl = (float*)p;
    cudaGetSymbolAddress(&p, g_ln);
    bf16* lnb = (bf16*)p;
    cudaGetSymbolAddress(&p, g_qkv);
    bf16* qkvb = (bf16*)p;
    cudaGetSymbolAddress(&p, g_att);
    bf16* attb = (bf16*)p;
    cudaGetSymbolAddress(&p, g_mid1);
    bf16* mid1 = (bf16*)p;
    cudaGetSymbolAddress(&p, g_hid);
    bf16* hid = (bf16*)p;
    cudaGetSymbolAddress(&p, g_mid2);
    bf16* mid2 = (bf16*)p;
    cudaGetSymbolAddress(&p, g_S);
    float* gS = (float*)p;
    cudaGetSymbolAddress(&p, g_N);
    float* gN = (float*)p;
    cudaGetSymbolAddress(&p, g_aT);
    bf16* gAT = (bf16*)p;
    cudaGetSymbolAddress(&p, g_wqkv);
    bf16* wqkv = (bf16*)p;
    cudaGetSymbolAddress(&p, g_wproj);
    bf16* wproj = (bf16*)p;
    cudaGetSymbolAddress(&p, g_w1d);
    bf16* w1d = (bf16*)p;
    cudaGetSymbolAddress(&p, g_w1u);
    bf16* w1u = (bf16*)p;
    cudaGetSymbolAddress(&p, g_w2d);
    bf16* w2d = (bf16*)p;
    cudaGetSymbolAddress(&p, g_w2u);
    bf16* w2u = (bf16*)p;

    // dynamic smem opt-in for XCA kernels (idempotent)
    const int XS_SMEM = 48*456*2 + XA_TOK*56*2 + (48*48 + 96)*4;  // 103552
    const int AV_SMEM = XA_TOK*56*2 + 48*56*2;                    // 55552
    cudaFuncSetAttribute(xca_s_k,  cudaFuncAttributeMaxDynamicSharedMemorySize, XS_SMEM);
    cudaFuncSetAttribute(xca_av_k, cudaFuncAttributeMaxDynamicSharedMemorySize, AV_SMEM);

    // launch 0: all weight conversions in one kernel
    {
        int total = C_*3*C_ + C_*C_ + C_*R_ + R_*HID_ + HID_*R_ + R_*C_;
        cvt_all_k<<<(total/4 + 255)/256, 256>>>(qkv_w, proj_w, m1dw, m1uw, m2dw, m2uw,
                                                wqkv, wproj, w1d, w1u, w2d, w2u);
    }

    const int nconv = B_*SPLIT_*HW_;
    dim3 tp(32, 32);
    dim3 gt(HW_/32, C_/32, B_);

    // launches 1-2: multi-scale depthwise chain
    dwconv_k<<<(nconv + 255)/256, 256>>>(x + (size_t)SPLIT_*HW_,   (size_t)C_*HW_,
                                         x,                        (size_t)C_*HW_,
                                         dw_w0, dw_b0, s1);
    dwconv_k<<<(nconv + 255)/256, 256>>>(x + (size_t)2*SPLIT_*HW_, (size_t)C_*HW_,
                                         s1,                       (size_t)SPLIT_*HW_,
                                         dw_w1, dw_b1, s2);
    // launch 3
    gather_k<<<gt, tp>>>(x, xfl);

    // launch 4: LN1; launch 5: qkv GEMM (profiled by ncu -s 5 -c 1)
    ln_k<<<NTOK, 128>>>(xfl, ln1_g, ln1_b, lnb);
    gemm_bf<bf16, false, false, false><<<dim3(1152/64, NTOK/128), 256>>>(lnb, wqkv, (const float*)0, qkvb, NTOK, 1152, 384);

    // XCA (tensor-core)
    {
        int nz = 128*2304 + 128*96;
        zero2_k<<<(nz + 255)/256, 256>>>(gS, 128*2304, gN, 128*96);
    }
    xca_s_k<<<dim3(128, XA_CH), 256, XS_SMEM>>>(qkvb, gS, gN);
    xca_soft_k<<<128, 96>>>(gS, gN, gAT);
    xca_av_k<<<dim3(128, XA_CH), 224, AV_SMEM>>>(qkvb, gAT, attb);

    gemm_bf<float, true, true, false><<<dim3(384/64, NTOK/128), 256>>>(attb, wproj, proj_b, xfl, NTOK, 384, 384);

    // MLP block
    ln_k<<<NTOK, 128>>>(xfl, ln2_g, ln2_b, lnb);
    gemm_bf<bf16, false, false, false><<<dim3(192/64, NTOK/128), 256>>>(lnb, w1d, (const float*)0, mid1, NTOK, 192, 384);
    gemm_bf<bf16, true, false, true><<<dim3(1536/64, NTOK/128), 256>>>(mid1, w1u, m1ub, hid, NTOK, 1536, 192);
    gemm_bf<bf16, false, false, false><<<dim3(192/64, NTOK/128), 256>>>(hid, w2d, (const float*)0, mid2, NTOK, 192, 1536);
    gemm_bf<float, true, true, false><<<dim3(384/64, NTOK/128), 256>>>(mid2, w2u, m2ub, xfl, NTOK, 384, 192);

    // back to NCHW
    scatter_k<<<gt, tp>>>(xfl, out);
}

// round 10
// speedup vs baseline: 4.7973x; 1.1421x over previous
#include <cuda_runtime.h>
#include <cuda_bf16.h>
#include <stdint.h>
#include <math.h>

#define B_    16
#define C_    384
#define HW_   3136
#define W56   56
#define NTOK  (B_*HW_)     // 50176
#define NH_   8
#define HD_   48
#define SPLIT_ 128
#define HID_  1536
#define R_    192
#define XA_TOK 448
#define XA_CH  7

typedef __nv_bfloat16 bf16;
typedef __nv_bfloat162 bf162;

// ---------------- scratch (device globals; no allocations) ----------------
__device__ float g_s1  [(size_t)B_*SPLIT_*HW_];
__device__ float g_s2  [(size_t)B_*SPLIT_*HW_];
__device__ float g_xfl [(size_t)NTOK*C_];
__device__ bf16  g_ln  [(size_t)NTOK*C_];
__device__ bf16  g_qkv [(size_t)NTOK*3*C_];
__device__ bf16  g_att [(size_t)NTOK*C_];
__device__ bf16  g_mid1[(size_t)NTOK*R_];
__device__ bf16  g_hid [(size_t)NTOK*HID_];
__device__ bf16  g_mid2[(size_t)NTOK*R_];
// XCA intermediates
__device__ float g_S  [(size_t)128*2304];
__device__ float g_N  [(size_t)128*96];
__device__ bf16  g_aT [(size_t)128*2304];
// bf16 weights
__device__ bf16  g_wqkv [(size_t)C_*3*C_];
__device__ bf16  g_wproj[(size_t)C_*C_];
__device__ bf16  g_w1d  [(size_t)C_*R_];
__device__ bf16  g_w1u  [(size_t)R_*HID_];
__device__ bf16  g_w2d  [(size_t)HID_*R_];
__device__ bf16  g_w2u  [(size_t)R_*C_];

// ---------------- fp32 -> bf16 weight conversion (single kernel) ----------------
__global__ void cvt_all_k(const float* __restrict__ s0, const float* __restrict__ s1,
                          const float* __restrict__ s2, const float* __restrict__ s3,
                          const float* __restrict__ s4, const float* __restrict__ s5,
                          bf16* d0, bf16* d1, bf16* d2, bf16* d3, bf16* d4, bf16* d5)
{
    const int L0 = C_*3*C_, L1 = C_*C_, L2 = C_*R_, L3 = R_*HID_, L4 = HID_*R_, L5 = R_*C_;
    int i = (blockIdx.x*blockDim.x + threadIdx.x)*4;
    const float* s; bf16* d; int off = i;
    if (off < L0) { s = s0; d = d0; }
    else { off -= L0;
      if (off < L1) { s = s1; d = d1; }
      else { off -= L1;
        if (off < L2) { s = s2; d = d2; }
        else { off -= L2;
          if (off < L3) { s = s3; d = d3; }
          else { off -= L3;
            if (off < L4) { s = s4; d = d4; }
            else { off -= L4;
              if (off < L5) { s = s5; d = d5; }
              else return; } } } } }
    float4 v = *(const float4*)(s + off);
    bf162* o = (bf162*)(d + off);
    o[0] = __floats2bfloat162_rn(v.x, v.y);
    o[1] = __floats2bfloat162_rn(v.z, v.w);
}

__global__ void zero2_k(float* a, int na, float* b, int nb)
{
    int i = blockIdx.x*blockDim.x + threadIdx.x;
    if (i < na) a[i] = 0.f;
    else if (i - na < nb) b[i - na] = 0.f;
}

// ---------------- depthwise conv: out = dwconv(a + b, w) + bias ----------------
__global__ void dwconv_k(const float* __restrict__ a, size_t strideA,
                         const float* __restrict__ bsrc, size_t strideB,
                         const float* __restrict__ w, const float* __restrict__ bias,
                         float* __restrict__ out)
{
    int idx = blockIdx.x * blockDim.x + threadIdx.x;
    if (idx >= B_*SPLIT_*HW_) return;
    int p = idx % HW_;
    int c = (idx / HW_) % SPLIT_;
    int b = idx / (HW_*SPLIT_);
    int y = p / W56, xq = p % W56;
    const float* pa = a    + (size_t)b*strideA + (size_t)c*HW_;
    const float* pb = bsrc + (size_t)b*strideB + (size_t)c*HW_;
    const float* wc = w + c*9;
    float acc = bias[c];
    #pragma unroll
    for (int dy = -1; dy <= 1; dy++) {
        int yy = y + dy;
        if (yy < 0 || yy >= W56) continue;
        #pragma unroll
        for (int dx = -1; dx <= 1; dx++) {
            int xx = xq + dx;
            if (xx < 0 || xx >= W56) continue;
            float v = pa[yy*W56 + xx] + pb[yy*W56 + xx];
            acc = fmaf(v, wc[(dy+1)*3 + (dx+1)], acc);
        }
    }
    out[idx] = acc;
}

// ------------- fused gather (concat NCHW -> token-major) + LayerNorm1 -------------
// grid (98, 16), 256 threads, dynamic smem 32*385*4 bytes.
__global__ void __launch_bounds__(256) gatherln_k(const float* __restrict__ x,
                                                  const float* __restrict__ gam,
                                                  const float* __restrict__ bet,
                                                  float* __restrict__ xfl,
                                                  bf16* __restrict__ lnb)
{
    extern __shared__ float sm[];   // [32 tok][385]
    __shared__ float mean_s[32], rstd_s[32];
    int b = blockIdx.y, p0 = blockIdx.x * 32;
    int tid = threadIdx.x;

    #pragma unroll
    for (int it = 0; it < 48; it++) {
        int i = tid + 256*it;           // 0..12287
        int c = i >> 5, tok = i & 31;
        float v;
        if (c < 128)      v = x   [((size_t)b*C_ + c)*HW_ + p0 + tok];
        else if (c < 256) v = g_s1[((size_t)b*SPLIT_ + (c-128))*HW_ + p0 + tok];
        else              v = g_s2[((size_t)b*SPLIT_ + (c-256))*HW_ + p0 + tok];
        sm[tok*385 + c] = v;
    }
    __syncthreads();

    // LN stats: 8 warps x 4 tokens, 8 lanes per token
    int w = tid >> 5, lane = tid & 31;
    int sub = lane >> 3, li = lane & 7;
    int tok = w*4 + sub;
    const float* row = sm + tok*385;
    float s = 0.f;
    #pragma unroll
    for (int k = 0; k < 48; k++) s += row[li + 8*k];
    s += __shfl_xor_sync(0xffffffffu, s, 1);
    s += __shfl_xor_sync(0xffffffffu, s, 2);
    s += __shfl_xor_sync(0xffffffffu, s, 4);
    float mean = s * (1.f/384.f);
    float vs = 0.f;
    #pragma unroll
    for (int k = 0; k < 48; k++) { float d = row[li + 8*k] - mean; vs = fmaf(d, d, vs); }
    vs += __shfl_xor_sync(0xffffffffu, vs, 1);
    vs += __shfl_xor_sync(0xffffffffu, vs, 2);
    vs += __shfl_xor_sync(0xffffffffu, vs, 4);
    if (li == 0) {
        mean_s[tok] = mean;
        rstd_s[tok] = rsqrtf(vs * (1.f/384.f) + 1e-6f);
    }
    __syncthreads();

    // write xfl (fp32 residual) + lnb (bf16)
    #pragma unroll
    for (int it = 0; it < 24; it++) {
        int jp = tid + 256*it;          // pair index 0..6143
        int tk = jp / 192;
        int cp = (jp % 192) * 2;
        float v0 = sm[tk*385 + cp], v1 = sm[tk*385 + cp + 1];
        float m = mean_s[tk], r = rstd_s[tk];
        size_t base = ((size_t)b*HW_ + p0 + tk)*C_ + cp;
        *(float2*)(xfl + base) = make_float2(v0, v1);
        float o0 = (v0 - m)*r*gam[cp]   + bet[cp];
        float o1 = (v1 - m)*r*gam[cp+1] + bet[cp+1];
        *(bf162*)(lnb + base) = __floats2bfloat162_rn(o0, o1);
    }
}

// ---------------- LayerNorm over C=384 (LN2), bf16 output ----------------
__device__ __forceinline__ float warp_sum(float v)
{
    #pragma unroll
    for (int o = 16; o > 0; o >>= 1) v += __shfl_xor_sync(0xffffffffu, v, o);
    return v;
}

__global__ void __launch_bounds__(128) ln_k(const float* __restrict__ in,
                                            const float* __restrict__ gam,
                                            const float* __restrict__ bet,
                                            bf16* __restrict__ outp)
{
    int row = blockIdx.x;
    int tid = threadIdx.x;
    const float* r = in + (size_t)row*C_;
    float v0 = r[tid], v1 = r[tid+128], v2 = r[tid+256];
    __shared__ float red[4];
    int wid = tid >> 5, lane = tid & 31;
    float s = warp_sum(v0 + v1 + v2);
    if (lane == 0) red[wid] = s;
    __syncthreads();
    float mean = (red[0]+red[1]+red[2]+red[3]) * (1.f/384.f);
    float d0 = v0 - mean, d1 = v1 - mean, d2 = v2 - mean;
    float sq = warp_sum(d0*d0 + d1*d1 + d2*d2);
    __syncthreads();
    if (lane == 0) red[wid] = sq;
    __syncthreads();
    float var = (red[0]+red[1]+red[2]+red[3]) * (1.f/384.f);
    float rs = rsqrtf(var + 1e-6f);
    bf16* o = outp + (size_t)row*C_;
    o[tid]     = __float2bfloat16(d0*rs*gam[tid]     + bet[tid]);
    o[tid+128] = __float2bfloat16(d1*rs*gam[tid+128] + bet[tid+128]);
    o[tid+256] = __float2bfloat16(d2*rs*gam[tid+256] + bet[tid+256]);
}

// ================= shared MMA helpers =================
__device__ __forceinline__ uint32_t smem_u32(const void* p)
{
    return (uint32_t)__cvta_generic_to_shared(p);
}
__device__ __forceinline__ void cp16(uint32_t dst, const void* src)
{
    asm volatile("cp.async.cg.shared.global [%0], [%1], 16;" :: "r"(dst), "l"(src));
}
__device__ __forceinline__ void cpcommit()
{
    asm volatile("cp.async.commit_group;" ::: "memory");
}
__device__ __forceinline__ void cpwait0()
{
    asm volatile("cp.async.wait_group 0;" ::: "memory");
}
__device__ __forceinline__ void cpwait1()
{
    asm volatile("cp.async.wait_group 1;" ::: "memory");
}
__device__ __forceinline__ void ldsm4(uint32_t* r, uint32_t addr)
{
    asm volatile("ldmatrix.sync.aligned.m8n8.x4.shared.b16 {%0,%1,%2,%3}, [%4];"
        : "=r"(r[0]), "=r"(r[1]), "=r"(r[2]), "=r"(r[3]) : "r"(addr));
}
__device__ __forceinline__ void ldsm4t(uint32_t* r, uint32_t addr)
{
    asm volatile("ldmatrix.sync.aligned.m8n8.x4.trans.shared.b16 {%0,%1,%2,%3}, [%4];"
        : "=r"(r[0]), "=r"(r[1]), "=r"(r[2]), "=r"(r[3]) : "r"(addr));
}
__device__ __forceinline__ void mma_bf16(float* c, const uint32_t* a, const uint32_t* b)
{
    asm volatile(
        "mma.sync.aligned.m16n8k16.row.col.f32.bf16.bf16.f32 "
        "{%0,%1,%2,%3}, {%4,%5,%6,%7}, {%8,%9}, {%0,%1,%2,%3};"
        : "+f"(c[0]), "+f"(c[1]), "+f"(c[2]), "+f"(c[3])
        : "r"(a[0]), "r"(a[1]), "r"(a[2]), "r"(a[3]), "r"(b[0]), "r"(b[1]));
}

// epilogue store helpers
__device__ __forceinline__ void epi_store(float* cp, float r0, float r1, bool accum)
{
    float2* p2 = (float2*)cp;
    if (accum) {
        float2 o = *p2;
        r0 += o.x; r1 += o.y;
    }
    *p2 = make_float2(r0, r1);
}
__device__ __forceinline__ void epi_store(bf16* cp, float r0, float r1, bool accum)
{
    (void)accum;
    *(bf162*)cp = __floats2bfloat162_rn(r0, r1);
}

__device__ __forceinline__ void loadA_tile(bf16 (&As)[128][64], const bf16* Ap,
                                           int K, int k0, int tid)
{
    #pragma unroll
    for (int i = 0; i < 4; i++) {
        int q = tid + 256*i;
        int row = q >> 3, c = q & 7;
        int cs = c ^ (row & 7);
        cp16(smem_u32(&As[row][cs*8]), Ap + (size_t)row*K + k0 + c*8);
    }
}
__device__ __forceinline__ void loadB_tile(bf16 (&Bs)[64][64], const bf16* Bp,
                                           int Nn, int k0, int tid)
{
    #pragma unroll
    for (int i = 0; i < 2; i++) {
        int q = tid + 256*i;
        int row = q >> 3, c = q & 7;
        int cs = c ^ (row & 7);
        cp16(smem_u32(&Bs[row][cs*8]), Bp + (size_t)(k0 + row)*Nn + c*8);
    }
}

// BM=128, BN=64, BK=64; 256 threads = 8 warps (4 m x 2 n), warp tile 32x32.
template<typename TOUT, bool BIAS, bool ACCUM, bool GELU_ACT>
__global__ void __launch_bounds__(256) gemm_bf(const bf16* __restrict__ A,
                                               const bf16* __restrict__ Bw,
                                               const float* __restrict__ bias,
                                               TOUT* __restrict__ C,
                                               int M, int Nn, int K)
{
    __shared__ bf16 As[2][128][64];
    __shared__ bf16 Bs[2][64][64];

    int tid = threadIdx.x;
    int w = tid >> 5, lane = tid & 31;
    int g = lane >> 2, t = lane & 3;
    int moff = (w & 3) * 32, noff = (w >> 2) * 32;
    int m0 = blockIdx.y * 128, n0 = blockIdx.x * 64;

    const bf16* Ap = A + (size_t)m0 * K;
    const bf16* Bp = Bw + n0;

    float acc[2][4][4];
    #pragma unroll
    for (int i = 0; i < 2; i++)
        #pragma unroll
        for (int j = 0; j < 4; j++)
            #pragma unroll
            for (int q = 0; q < 4; q++) acc[i][j][q] = 0.f;

    loadA_tile(As[0], Ap, K, 0, tid);
    loadB_tile(Bs[0], Bp, Nn, 0, tid);
    cpcommit();

    int nk = K >> 6;
    for (int it = 0; it < nk; it++) {
        int buf = it & 1;
        if (it + 1 < nk) {
            int k0 = (it + 1) << 6;
            loadA_tile(As[buf ^ 1], Ap, K, k0, tid);
            loadB_tile(Bs[buf ^ 1], Bp, Nn, k0, tid);
            cpcommit();
            cpwait1();
        } else {
            cpwait0();
        }
        __syncthreads();
        #pragma unroll
        for (int ks = 0; ks < 4; ks++) {
            uint32_t af[2][4], bfr[2][4];
            #pragma unroll
            for (int i = 0; i < 2; i++) {
                int mr = moff + i*16 + (lane & 15);
                int cc = (ks*2 + (lane >> 4)) ^ (mr & 7);
                ldsm4(af[i], smem_u32(&As[buf][mr][cc*8]));
            }
            #pragma unroll
            for (int jj = 0; jj < 2; jj++) {
                int kr = ks*16 + (lane & 15);
                int cc = (((noff + jj*16) >> 3) + (lane >> 4)) ^ (kr & 7);
                ldsm4t(bfr[jj], smem_u32(&Bs[buf][kr][cc*8]));
            }
            #pragma unroll
            for (int i = 0; i < 2; i++) {
                mma_bf16(acc[i][0], af[i], &bfr[0][0]);
                mma_bf16(acc[i][1], af[i], &bfr[0][2]);
                mma_bf16(acc[i][2], af[i], &bfr[1][0]);
                mma_bf16(acc[i][3], af[i], &bfr[1][2]);
            }
        }
        __syncthreads();
    }

    // epilogue
    #pragma unroll
    for (int i = 0; i < 2; i++) {
        #pragma unroll
        for (int j = 0; j < 4; j++) {
            int col = n0 + noff + j*8 + t*2;
            float b0 = 0.f, b1 = 0.f;
            if (BIAS) { b0 = bias[col]; b1 = bias[col+1]; }
            #pragma unroll
            for (int hh = 0; hh < 2; hh++) {
                int row = m0 + moff + i*16 + g + hh*8;
                float r0 = acc[i][j][hh*2]   + b0;
                float r1 = acc[i][j][hh*2+1] + b1;
                if (GELU_ACT) {
                    r0 = 0.5f * r0 * (1.f + erff(r0 * 0.70710678118654752f));
                    r1 = 0.5f * r1 * (1.f + erff(r1 * 0.70710678118654752f));
                }
                epi_store(C + (size_t)row*Nn + col, r0, r1, ACCUM);
            }
        }
    }
}

// ===== final GEMM: z = mid2 @ w2u + bias + residual(xfl), write NCHW out =====
// M=NTOK, Nn=384, K=192. Same pipeline; epilogue transposes via smem reuse.
__global__ void __launch_bounds__(256) gemm_out_k(const bf16* __restrict__ A,
                                                  const bf16* __restrict__ Bw,
                                                  const float* __restrict__ bias,
                                                  const float* __restrict__ resid,
                                                  float* __restrict__ outp)
{
    __shared__ char sbuf[49152];
    bf16 (&As)[2][128][64] = *reinterpret_cast<bf16(*)[2][128][64]>(sbuf);
    bf16 (&Bs)[2][64][64]  = *reinterpret_cast<bf16(*)[2][64][64]>(sbuf + 32768);

    const int K = 192, Nn = 384;
    int tid = threadIdx.x;
    int w = tid >> 5, lane = tid & 31;
    int g = lane >> 2, t = lane & 3;
    int moff = (w & 3) * 32, noff = (w >> 2) * 32;
    int m0 = blockIdx.y * 128, n0 = blockIdx.x * 64;

    const bf16* Ap = A + (size_t)m0 * K;
    const bf16* Bp = Bw + n0;

    float acc[2][4][4];
    #pragma unroll
    for (int i = 0; i < 2; i++)
        #pragma unroll
        for (int j = 0; j < 4; j++)
            #pragma unroll
            for (int q = 0; q < 4; q++) acc[i][j][q] = 0.f;

    loadA_tile(As[0], Ap, K, 0, tid);
    loadB_tile(Bs[0], Bp, Nn, 0, tid);
    cpcommit();

    int nk = K >> 6;   // 3
    for (int it = 0; it < nk; it++) {
        int buf = it & 1;
        if (it + 1 < nk) {
            int k0 = (it + 1) << 6;
            loadA_tile(As[buf ^ 1], Ap, K, k0, tid);
            loadB_tile(Bs[buf ^ 1], Bp, Nn, k0, tid);
            cpcommit();
            cpwait1();
        } else {
            cpwait0();
        }
        __syncthreads();
        #pragma unroll
        for (int ks = 0; ks < 4; ks++) {
            uint32_t af[2][4], bfr[2][4];
            #pragma unroll
            for (int i = 0; i < 2; i++) {
                int mr = moff + i*16 + (lane & 15);
                int cc = (ks*2 + (lane >> 4)) ^ (mr & 7);
                ldsm4(af[i], smem_u32(&As[buf][mr][cc*8]));
            }
            #pragma unroll
            for (int jj = 0; jj < 2; jj++) {
                int kr = ks*16 + (lane & 15);
                int cc = (((noff + jj*16) >> 3) + (lane >> 4)) ^ (kr & 7);
                ldsm4t(bfr[jj], smem_u32(&Bs[buf][kr][cc*8]));
            }
            #pragma unroll
            for (int i = 0; i < 2; i++) {
                mma_bf16(acc[i][0], af[i], &bfr[0][0]);
                mma_bf16(acc[i][1], af[i], &bfr[0][2]);
                mma_bf16(acc[i][2], af[i], &bfr[1][0]);
                mma_bf16(acc[i][3], af[i], &bfr[1][2]);
            }
        }
        __syncthreads();
    }

    // epilogue: bias + residual, stage transposed [64 ch][132] (reuse sbuf)
    float (&tr)[64][132] = *reinterpret_cast<float(*)[64][132]>(sbuf);
    #pragma unroll
    for (int i = 0; i < 2; i++) {
        #pragma unroll
        for (int j = 0; j < 4; j++) {
            int lc = noff + j*8 + t*2;
            float b0 = bias[n0 + lc], b1 = bias[n0 + lc + 1];
            #pragma unroll
            for (int hh = 0; hh < 2; hh++) {
                int lr = moff + i*16 + g + hh*8;
                float2 res = *(const float2*)(resid + (size_t)(m0 + lr)*Nn + n0 + lc);
                tr[lc][lr]     = acc[i][j][hh*2]   + b0 + res.x;
                tr[lc + 1][lr] = acc[i][j][hh*2+1] + b1 + res.y;
            }
        }
    }
    __syncthreads();

    // write out NCHW: 64 channel-rows x 4 chunks of 32 tokens = 256 threads
    {
        int cr = tid >> 2, ch = tid & 3;
        int tok0 = m0 + ch*32;
        int b = tok0 / HW_;
        int p = tok0 - b*HW_;
        float* op = outp + ((size_t)b*C_ + n0 + cr)*HW_ + p;
        #pragma unroll
        for (int z = 0; z < 32; z += 4) {
            float4 v = make_float4(tr[cr][ch*32 + z],     tr[cr][ch*32 + z + 1],
                                   tr[cr][ch*32 + z + 2], tr[cr][ch*32 + z + 3]);
            *(float4*)(op + z) = v;
        }
    }
}

// ================= XCA phase A: partial S = q @ k^T + norms (MMA) =================
__global__ void __launch_bounds__(256) xca_s_k(const bf16* __restrict__ qkv,
                                               float* __restrict__ gS,
                                               float* __restrict__ gN)
{
    extern __shared__ char smraw[];
    bf16*  q_s = (bf16*)smraw;                                // [48][456]
    bf16*  k_s = (bf16*)(smraw + 48*456*2);                   // [448][56]
    float* Ss  = (float*)(smraw + 48*456*2 + (size_t)XA_TOK*56*2); // [48][48]
    float* ns  = Ss + 48*48;                                  // [96]

    int bh = blockIdx.x, chunk = blockIdx.y;
    int b = bh >> 3, h = bh & 7;
    int tid = threadIdx.x;
    int w = tid >> 5, lane = tid & 31;
    int g = lane >> 2, t = lane & 3;
    const bf16* qb = qkv + ((size_t)b*HW_ + chunk*XA_TOK)*1152 + h*48;
    const bf16* kb = qb + 384;

    for (int i = tid; i < XA_TOK*6; i += 256) {
        int row = i/6, c = i%6;
        cp16(smem_u32(k_s + row*56 + c*8), kb + (size_t)row*1152 + c*8);
    }
    cpcommit();
    for (int i = tid; i < XA_TOK*24; i += 256) {
        int tok = i/24, dp = i%24;
        bf162 v = *(const bf162*)(qb + (size_t)tok*1152 + dp*2);
        q_s[(dp*2  )*456 + tok] = v.x;
        q_s[(dp*2+1)*456 + tok] = v.y;
    }
    for (int i = tid; i < 48*48; i += 256) Ss[i] = 0.f;
    if (tid < 96) ns[tid] = 0.f;
    cpwait0();
    __syncthreads();

    for (int u = tid; u < 384; u += 256) {
        int r = u >> 2, seg = u & 3;
        float acc = 0.f;
        if (r < 48) {
            const bf16* p = q_s + r*456 + seg*112;
            for (int x = 0; x < 112; x++) {
                float v = __bfloat162float(p[x]);
                acc = fmaf(v, v, acc);
            }
        } else {
            const bf16* p = k_s + (r - 48) + seg*112*56;
            for (int x = 0; x < 112; x++) {
                float v = __bfloat162float(p[x*56]);
                acc = fmaf(v, v, acc);
            }
        }
        atomicAdd(&ns[r], acc);
    }

    float acc[3][6][4];
    #pragma unroll
    for (int i = 0; i < 3; i++)
        #pragma unroll
        for (int j = 0; j < 6; j++)
            #pragma unroll
            for (int q = 0; q < 4; q++) acc[i][j][q] = 0.f;

    for (int s = w; s < 28; s += 8) {
        int k0 = s*16;
        uint32_t af[3][4], bfr[3][4];
        #pragma unroll
        for (int i = 0; i < 3; i++)
            ldsm4(af[i], smem_u32(q_s + (i*16 + (lane & 15))*456 + k0 + (lane >> 4)*8));
        #pragma unroll
        for (int jj = 0; jj < 3; jj++)
            ldsm4t(bfr[jj], smem_u32(k_s + (k0 + (lane & 15))*56 + jj*16 + (lane >> 4)*8));
        #pragma unroll
        for (int i = 0; i < 3; i++) {
            #pragma unroll
            for (int jj = 0; jj < 3; jj++) {
                mma_bf16(acc[i][jj*2  ], af[i], &bfr[jj][0]);
                mma_bf16(acc[i][jj*2+1], af[i], &bfr[jj][2]);
            }
        }
    }

    #pragma unroll
    for (int i = 0; i < 3; i++) {
        #pragma unroll
        for (int j = 0; j < 6; j++) {
            int r0 = i*16 + g, c0 = j*8 + t*2;
            atomicAdd(&Ss[r0*48 + c0    ], acc[i][j][0]);
            atomicAdd(&Ss[r0*48 + c0 + 1], acc[i][j][1]);
            atomicAdd(&Ss[(r0+8)*48 + c0    ], acc[i][j][2]);
            atomicAdd(&Ss[(r0+8)*48 + c0 + 1], acc[i][j][3]);
        }
    }
    __syncthreads();

    for (int i = tid; i < 48*48; i += 256)
        atomicAdd(&gS[(size_t)bh*2304 + i], Ss[i]);
    if (tid < 96)
        atomicAdd(&gN[bh*96 + tid], ns[tid]);
}

// ================= XCA softmax =================
__global__ void __launch_bounds__(96) xca_soft_k(const float* __restrict__ gS,
                                                 const float* __restrict__ gN,
                                                 bf16* __restrict__ gAT)
{
    __shared__ float iq[48], ik[48];
    int bh = blockIdx.x, tid = threadIdx.x;
    if (tid < 48)      iq[tid]    = 1.f / fmaxf(sqrtf(gN[bh*96 + tid]), 1e-12f);
    else               ik[tid-48] = 1.f / fmaxf(sqrtf(gN[bh*96 + tid]), 1e-12f);
    __syncthreads();
    if (tid < 48) {
        float row[48];
        const float* S = gS + (size_t)bh*2304 + tid*48;
        float mx = -1e30f;
        #pragma unroll 8
        for (int e = 0; e < 48; e++) {
            float l = S[e] * iq[tid] * ik[e];
            row[e] = l;
            mx = fmaxf(mx, l);
        }
        float sum = 0.f;
        #pragma unroll 8
        for (int e = 0; e < 48; e++) {
            float ex = expf(row[e] - mx);
            row[e] = ex;
            sum += ex;
        }
        float inv = 1.f / sum;
        #pragma unroll 8
        for (int e = 0; e < 48; e++)
            gAT[(size_t)bh*2304 + e*48 + tid] = __float2bfloat16(row[e] * inv);
    }
}

// ================= XCA phase C: y = v @ attn^T (MMA) =================
__global__ void __launch_bounds__(224) xca_av_k(const bf16* __restrict__ qkv,
                                                const bf16* __restrict__ gAT,
                                                bf16* __restrict__ outp)
{
    extern __shared__ char smraw[];
    bf16* v_s = (bf16*)smraw;                           // [448][56]
    bf16* aT  = (bf16*)(smraw + (size_t)XA_TOK*56*2);   // [48][56]

    int bh = blockIdx.x, chunk = blockIdx.y;
    int b = bh >> 3, h = bh & 7;
    int tid = threadIdx.x;
    int w = tid >> 5, lane = tid & 31;
    int g = lane >> 2, t = lane & 3;
    const bf16* vb = qkv + ((size_t)b*HW_ + chunk*XA_TOK)*1152 + h*48 + 768;

    for (int i = tid; i < XA_TOK*6; i += 224) {
        int row = i/6, c = i%6;
        cp16(smem_u32(v_s + row*56 + c*8), vb + (size_t)row*1152 + c*8);
    }
    for (int i = tid; i < 48*6; i += 224) {
        int e = i/6, c = i%6;
        cp16(smem_u32(aT + e*56 + c*8), gAT + (size_t)bh*2304 + e*48 + c*8);
    }
    cpcommit();
    cpwait0();
    __syncthreads();

    int tk0 = w*64;
    float acc[4][6][4];
    #pragma unroll
    for (int i = 0; i < 4; i++)
        #pragma unroll
        for (int j = 0; j < 6; j++)
            #pragma unroll
            for (int q = 0; q < 4; q++) acc[i][j][q] = 0.f;

    #pragma unroll
    for (int ks = 0; ks < 3; ks++) {
        int k0 = ks*16;
        uint32_t af[4][4], bfr[3][4];
        #pragma unroll
        for (int i = 0; i < 4; i++)
            ldsm4(af[i], smem_u32(v_s + (tk0 + i*16 + (lane & 15))*56 + k0 + (lane >> 4)*8));
        #pragma unroll
        for (int jj = 0; jj < 3; jj++)
            ldsm4t(bfr[jj], smem_u32(aT + (k0 + (lane & 15))*56 + jj*16 + (lane >> 4)*8));
        #pragma unroll
        for (int i = 0; i < 4; i++) {
            #pragma unroll
            for (int jj = 0; jj < 3; jj++) {
                mma_bf16(acc[i][jj*2  ], af[i], &bfr[jj][0]);
                mma_bf16(acc[i][jj*2+1], af[i], &bfr[jj][2]);
            }
        }
    }

    size_t tokbase = (size_t)b*HW_ + (size_t)chunk*XA_TOK + tk0;
    #pragma unroll
    for (int i = 0; i < 4; i++) {
        #pragma unroll
        for (int j = 0; j < 6; j++) {
            int r0 = i*16 + g, c0 = j*8 + t*2;
            *(bf162*)(outp + (tokbase + r0)*C_ + h*48 + c0) =
                __floats2bfloat162_rn(acc[i][j][0], acc[i][j][1]);
            *(bf162*)(outp + (tokbase + r0 + 8)*C_ + h*48 + c0) =
                __floats2bfloat162_rn(acc[i][j][2], acc[i][j][3]);
        }
    }
}

// ---------------- launch ----------------
extern "C" void kernel_launch(void* const* d_in, const int* in_sizes, int n_in,
                              void* d_out, int out_size)
{
    (void)in_sizes; (void)n_in; (void)out_size;
    const float* x      = (const float*)d_in[0];
    const float* dw_w0  = (const float*)d_in[1];
    const float* dw_b0  = (const float*)d_in[2];
    const float* dw_w1  = (const float*)d_in[3];
    const float* dw_b1  = (const float*)d_in[4];
    const float* ln1_g  = (const float*)d_in[5];
    const float* ln1_b  = (const float*)d_in[6];
    const float* qkv_w  = (const float*)d_in[7];
    const float* proj_w = (const float*)d_in[8];
    const float* proj_b = (const float*)d_in[9];
    const float* ln2_g  = (const float*)d_in[10];
    const float* ln2_b  = (const float*)d_in[11];
    const float* m1dw   = (const float*)d_in[12];
    const float* m1uw   = (const float*)d_in[13];
    const float* m1ub   = (const float*)d_in[14];
    const float* m2dw   = (const float*)d_in[15];
    const float* m2uw   = (const float*)d_in[16];
    const float* m2ub   = (const float*)d_in[17];
    float* out = (float*)d_out;

    void* p = 0;
    cudaGetSymbolAddress(&p, g_s1);
    float* s1 = (float*)p;
    cudaGetSymbolAddress(&p, g_s2);
    float* s2 = (float*)p;
    cudaGetSymbolAddress(&p, g_xfl);
    float* xfl = (float*)p;
    cudaGetSymbolAddress(&p, g_ln);
    bf16* lnb = (bf16*)p;
    cudaGetSymbolAddress(&p, g_qkv);
    bf16* qkvb = (bf16*)p;
    cudaGetSymbolAddress(&p, g_att);
    bf16* attb = (bf16*)p;
    cudaGetSymbolAddress(&p, g_mid1);
    bf16* mid1 = (bf16*)p;
    cudaGetSymbolAddress(&p, g_hid);
    bf16* hid = (bf16*)p;
    cudaGetSymbolAddress(&p, g_mid2);
    bf16* mid2 = (bf16*)p;
    cudaGetSymbolAddress(&p, g_S);
    float* gS = (float*)p;
    cudaGetSymbolAddress(&p, g_N);
    float* gN = (float*)p;
    cudaGetSymbolAddress(&p, g_aT);
    bf16* gAT = (bf16*)p;
    cudaGetSymbolAddress(&p, g_wqkv);
    bf16* wqkv = (bf16*)p;
    cudaGetSymbolAddress(&p, g_wproj);
    bf16* wproj = (bf16*)p;
    cudaGetSymbolAddress(&p, g_w1d);
    bf16* w1d = (bf16*)p;
    cudaGetSymbolAddress(&p, g_w1u);
    bf16* w1u = (bf16*)p;
    cudaGetSymbolAddress(&p, g_w2d);
    bf16* w2d = (bf16*)p;
    cudaGetSymbolAddress(&p, g_w2u);
    bf16* w2u = (bf16*)p;

    // dynamic smem opt-in
    const int XS_SMEM = 48*456*2 + XA_TOK*56*2 + (48*48 + 96)*4;  // 103552
    const int AV_SMEM = XA_TOK*56*2 + 48*56*2;                    // 55552
    const int GL_SMEM = 32*385*4;                                 // 49280
    cudaFuncSetAttribute(xca_s_k,   cudaFuncAttributeMaxDynamicSharedMemorySize, XS_SMEM);
    cudaFuncSetAttribute(xca_av_k,  cudaFuncAttributeMaxDynamicSharedMemorySize, AV_SMEM);
    cudaFuncSetAttribute(gatherln_k, cudaFuncAttributeMaxDynamicSharedMemorySize, GL_SMEM);

    // weight conversions
    {
        int total = C_*3*C_ + C_*C_ + C_*R_ + R_*HID_ + HID_*R_ + R_*C_;
        cvt_all_k<<<(total/4 + 255)/256, 256>>>(qkv_w, proj_w, m1dw, m1uw, m2dw, m2uw,
                                                wqkv, wproj, w1d, w1u, w2d, w2u);
    }

    const int nconv = B_*SPLIT_*HW_;

    // multi-scale depthwise chain
    dwconv_k<<<(nconv + 255)/256, 256>>>(x + (size_t)SPLIT_*HW_,   (size_t)C_*HW_,
                                         x,                        (size_t)C_*HW_,
                                         dw_w0, dw_b0, s1);
    dwconv_k<<<(nconv + 255)/256, 256>>>(x + (size_t)2*SPLIT_*HW_, (size_t)C_*HW_,
                                         s1,                       (size_t)SPLIT_*HW_,
                                         dw_w1, dw_b1, s2);

    // fused gather + LN1
    gatherln_k<<<dim3(HW_/32, B_), 256, GL_SMEM>>>(x, ln1_g, ln1_b, xfl, lnb);

    // qkv GEMM
    gemm_bf<bf16, false, false, false><<<dim3(1152/64, NTOK/128), 256>>>(lnb, wqkv, (const float*)0, qkvb, NTOK, 1152, 384);

    // XCA (tensor-core)
    {
        int nz = 128*2304 + 128*96;
        zero2_k<<<(nz + 255)/256, 256>>>(gS, 128*2304, gN, 128*96);
    }
    xca_s_k<<<dim3(128, XA_CH), 256, XS_SMEM>>>(qkvb, gS, gN);
    xca_soft_k<<<128, 96>>>(gS, gN, gAT);
    xca_av_k<<<dim3(128, XA_CH), 224, AV_SMEM>>>(qkvb, gAT, attb);

    gemm_bf<float, true, true, false><<<dim3(384/64, NTOK/128), 256>>>(attb, wproj, proj_b, xfl, NTOK, 384, 384);

    // MLP block
    ln_k<<<NTOK, 128>>>(xfl, ln2_g, ln2_b, lnb);
    gemm_bf<bf16, false, false, false><<<dim3(192/64, NTOK/128), 256>>>(lnb, w1d, (const float*)0, mid1, NTOK, 192, 384);
    gemm_bf<bf16, true, false, true><<<dim3(1536/64, NTOK/128), 256>>>(mid1, w1u, m1ub, hid, NTOK, 1536, 192);
    gemm_bf<bf16, false, false, false><<<dim3(192/64, NTOK/128), 256>>>(hid, w2d, (const float*)0, mid2, NTOK, 192, 1536);

    // final GEMM fused with residual + NCHW scatter
    gemm_out_k<<<dim3(384/64, NTOK/128), 256>>>(mid2, w2u, m2ub, xfl, out);
}

// round 11
// speedup vs baseline: 4.9304x; 1.0277x over previous
#include <cuda_runtime.h>
#include <cuda_bf16.h>
#include <stdint.h>
#include <math.h>

#define B_    16
#define C_    384
#define HW_   3136
#define W56   56
#define NTOK  (B_*HW_)     // 50176
#define NH_   8
#define HD_   48
#define SPLIT_ 128
#define HID_  1536
#define R_    192
#define XA_TOK 448
#define XA_CH  7

typedef __nv_bfloat16 bf16;
typedef __nv_bfloat162 bf162;

// ---------------- scratch (device globals; no allocations) ----------------
__device__ float g_s1  [(size_t)B_*SPLIT_*HW_];
__device__ float g_s2  [(size_t)B_*SPLIT_*HW_];
__device__ float g_xfl [(size_t)NTOK*C_];
__device__ bf16  g_ln  [(size_t)NTOK*C_];
__device__ bf16  g_qkv [(size_t)NTOK*3*C_];
__device__ bf16  g_att [(size_t)NTOK*C_];
__device__ bf16  g_mid1[(size_t)NTOK*R_];
__device__ bf16  g_hid [(size_t)NTOK*HID_];
__device__ bf16  g_mid2[(size_t)NTOK*R_];
// XCA intermediates
__device__ float g_S  [(size_t)128*2304];
__device__ float g_N  [(size_t)128*96];
__device__ bf16  g_aT [(size_t)128*2304];
// bf16 weights
__device__ bf16  g_wqkv [(size_t)C_*3*C_];
__device__ bf16  g_wproj[(size_t)C_*C_];
__device__ bf16  g_w1d  [(size_t)C_*R_];
__device__ bf16  g_w1u  [(size_t)R_*HID_];
__device__ bf16  g_w2d  [(size_t)HID_*R_];
__device__ bf16  g_w2u  [(size_t)R_*C_];

// ---------------- device bodies shared by prologue ----------------
__device__ __forceinline__ void dwconv_body(int idx,
    const float* a, size_t strideA, const float* bsrc, size_t strideB,
    const float* w, const float* bias, float* outp)
{
    if (idx >= B_*SPLIT_*HW_) return;
    int p = idx % HW_;
    int c = (idx / HW_) % SPLIT_;
    int b = idx / (HW_*SPLIT_);
    int y = p / W56, xq = p % W56;
    const float* pa = a    + (size_t)b*strideA + (size_t)c*HW_;
    const float* pb = bsrc + (size_t)b*strideB + (size_t)c*HW_;
    const float* wc = w + c*9;
    float acc = bias[c];
    #pragma unroll
    for (int dy = -1; dy <= 1; dy++) {
        int yy = y + dy;
        if (yy < 0 || yy >= W56) continue;
        #pragma unroll
        for (int dx = -1; dx <= 1; dx++) {
            int xx = xq + dx;
            if (xx < 0 || xx >= W56) continue;
            float v = pa[yy*W56 + xx] + pb[yy*W56 + xx];
            acc = fmaf(v, wc[(dy+1)*3 + (dx+1)], acc);
        }
    }
    outp[idx] = acc;
}

__device__ __forceinline__ void cvt_body(int i,
    const float* s0, const float* s1p, const float* s2p, const float* s3,
    const float* s4, const float* s5,
    bf16* d0, bf16* d1, bf16* d2, bf16* d3, bf16* d4, bf16* d5)
{
    const int L0 = C_*3*C_, L1 = C_*C_, L2 = C_*R_, L3 = R_*HID_, L4 = HID_*R_, L5 = R_*C_;
    const float* s; bf16* d; int off = i;
    if (off < L0) { s = s0; d = d0; }
    else { off -= L0;
      if (off < L1) { s = s1p; d = d1; }
      else { off -= L1;
        if (off < L2) { s = s2p; d = d2; }
        else { off -= L2;
          if (off < L3) { s = s3; d = d3; }
          else { off -= L3;
            if (off < L4) { s = s4; d = d4; }
            else { off -= L4;
              if (off < L5) { s = s5; d = d5; }
              else return; } } } } }
    float4 v = *(const float4*)(s + off);
    bf162* o = (bf162*)(d + off);
    o[0] = __floats2bfloat162_rn(v.x, v.y);
    o[1] = __floats2bfloat162_rn(v.z, v.w);
}

// prologue: dwconv0 + weight cvt + zero(S,N), partitioned by blockIdx.
#define DW_BLOCKS  ((B_*SPLIT_*HW_ + 255)/256)
#define CVT_TOTAL  (C_*3*C_ + C_*C_ + C_*R_ + R_*HID_ + HID_*R_ + R_*C_)
#define CVT_BLOCKS ((CVT_TOTAL/4 + 255)/256)
#define ZR_TOTAL   (128*2304 + 128*96)
#define ZR_BLOCKS  ((ZR_TOTAL + 255)/256)

__global__ void __launch_bounds__(256) prologue_k(
    const float* __restrict__ x, const float* __restrict__ dw_w0,
    const float* __restrict__ dw_b0, float* __restrict__ s1out,
    const float* qkv_w, const float* proj_w, const float* m1dw,
    const float* m1uw, const float* m2dw, const float* m2uw,
    bf16* wqkv, bf16* wproj, bf16* w1d, bf16* w1u, bf16* w2d, bf16* w2u,
    float* gS, float* gN)
{
    int bid = blockIdx.x, tid = threadIdx.x;
    if (bid < DW_BLOCKS) {
        dwconv_body(bid*256 + tid,
                    x + (size_t)SPLIT_*HW_, (size_t)C_*HW_,
                    x, (size_t)C_*HW_, dw_w0, dw_b0, s1out);
    } else if (bid < DW_BLOCKS + CVT_BLOCKS) {
        int i = ((bid - DW_BLOCKS)*256 + tid)*4;
        cvt_body(i, qkv_w, proj_w, m1dw, m1uw, m2dw, m2uw,
                 wqkv, wproj, w1d, w1u, w2d, w2u);
    } else {
        int i = (bid - DW_BLOCKS - CVT_BLOCKS)*256 + tid;
        if (i < 128*2304) gS[i] = 0.f;
        else if (i < ZR_TOTAL) gN[i - 128*2304] = 0.f;
    }
}

// ---------------- depthwise conv (second stage) ----------------
__global__ void dwconv_k(const float* __restrict__ a, size_t strideA,
                         const float* __restrict__ bsrc, size_t strideB,
                         const float* __restrict__ w, const float* __restrict__ bias,
                         float* __restrict__ out)
{
    dwconv_body(blockIdx.x*blockDim.x + threadIdx.x, a, strideA, bsrc, strideB, w, bias, out);
}

// ------------- fused gather (concat NCHW -> token-major) + LayerNorm1 -------------
__global__ void __launch_bounds__(256) gatherln_k(const float* __restrict__ x,
                                                  const float* __restrict__ gam,
                                                  const float* __restrict__ bet,
                                                  float* __restrict__ xfl,
                                                  bf16* __restrict__ lnb)
{
    extern __shared__ float sm[];   // [32 tok][385]
    __shared__ float mean_s[32], rstd_s[32];
    int b = blockIdx.y, p0 = blockIdx.x * 32;
    int tid = threadIdx.x;

    #pragma unroll
    for (int it = 0; it < 48; it++) {
        int i = tid + 256*it;
        int c = i >> 5, tok = i & 31;
        float v;
        if (c < 128)      v = x   [((size_t)b*C_ + c)*HW_ + p0 + tok];
        else if (c < 256) v = g_s1[((size_t)b*SPLIT_ + (c-128))*HW_ + p0 + tok];
        else              v = g_s2[((size_t)b*SPLIT_ + (c-256))*HW_ + p0 + tok];
        sm[tok*385 + c] = v;
    }
    __syncthreads();

    int w = tid >> 5, lane = tid & 31;
    int sub = lane >> 3, li = lane & 7;
    int tok = w*4 + sub;
    const float* row = sm + tok*385;
    float s = 0.f;
    #pragma unroll
    for (int k = 0; k < 48; k++) s += row[li + 8*k];
    s += __shfl_xor_sync(0xffffffffu, s, 1);
    s += __shfl_xor_sync(0xffffffffu, s, 2);
    s += __shfl_xor_sync(0xffffffffu, s, 4);
    float mean = s * (1.f/384.f);
    float vs = 0.f;
    #pragma unroll
    for (int k = 0; k < 48; k++) { float d = row[li + 8*k] - mean; vs = fmaf(d, d, vs); }
    vs += __shfl_xor_sync(0xffffffffu, vs, 1);
    vs += __shfl_xor_sync(0xffffffffu, vs, 2);
    vs += __shfl_xor_sync(0xffffffffu, vs, 4);
    if (li == 0) {
        mean_s[tok] = mean;
        rstd_s[tok] = rsqrtf(vs * (1.f/384.f) + 1e-6f);
    }
    __syncthreads();

    #pragma unroll
    for (int it = 0; it < 24; it++) {
        int jp = tid + 256*it;
        int tk = jp / 192;
        int cp = (jp % 192) * 2;
        float v0 = sm[tk*385 + cp], v1 = sm[tk*385 + cp + 1];
        float m = mean_s[tk], r = rstd_s[tk];
        size_t base = ((size_t)b*HW_ + p0 + tk)*C_ + cp;
        *(float2*)(xfl + base) = make_float2(v0, v1);
        float o0 = (v0 - m)*r*gam[cp]   + bet[cp];
        float o1 = (v1 - m)*r*gam[cp+1] + bet[cp+1];
        *(bf162*)(lnb + base) = __floats2bfloat162_rn(o0, o1);
    }
}

// ---------------- LayerNorm (LN2) ----------------
__device__ __forceinline__ float warp_sum(float v)
{
    #pragma unroll
    for (int o = 16; o > 0; o >>= 1) v += __shfl_xor_sync(0xffffffffu, v, o);
    return v;
}

__global__ void __launch_bounds__(128) ln_k(const float* __restrict__ in,
                                            const float* __restrict__ gam,
                                            const float* __restrict__ bet,
                                            bf16* __restrict__ outp)
{
    int row = blockIdx.x;
    int tid = threadIdx.x;
    const float* r = in + (size_t)row*C_;
    float v0 = r[tid], v1 = r[tid+128], v2 = r[tid+256];
    __shared__ float red[4];
    int wid = tid >> 5, lane = tid & 31;
    float s = warp_sum(v0 + v1 + v2);
    if (lane == 0) red[wid] = s;
    __syncthreads();
    float mean = (red[0]+red[1]+red[2]+red[3]) * (1.f/384.f);
    float d0 = v0 - mean, d1 = v1 - mean, d2 = v2 - mean;
    float sq = warp_sum(d0*d0 + d1*d1 + d2*d2);
    __syncthreads();
    if (lane == 0) red[wid] = sq;
    __syncthreads();
    float var = (red[0]+red[1]+red[2]+red[3]) * (1.f/384.f);
    float rs = rsqrtf(var + 1e-6f);
    bf16* o = outp + (size_t)row*C_;
    o[tid]     = __float2bfloat16(d0*rs*gam[tid]     + bet[tid]);
    o[tid+128] = __float2bfloat16(d1*rs*gam[tid+128] + bet[tid+128]);
    o[tid+256] = __float2bfloat16(d2*rs*gam[tid+256] + bet[tid+256]);
}

// ================= shared MMA helpers =================
__device__ __forceinline__ uint32_t smem_u32(const void* p)
{
    return (uint32_t)__cvta_generic_to_shared(p);
}
__device__ __forceinline__ void cp16(uint32_t dst, const void* src)
{
    asm volatile("cp.async.cg.shared.global [%0], [%1], 16;" :: "r"(dst), "l"(src));
}
__device__ __forceinline__ void cpcommit()
{
    asm volatile("cp.async.commit_group;" ::: "memory");
}
__device__ __forceinline__ void cpwait0()
{
    asm volatile("cp.async.wait_group 0;" ::: "memory");
}
__device__ __forceinline__ void cpwait1()
{
    asm volatile("cp.async.wait_group 1;" ::: "memory");
}
__device__ __forceinline__ void ldsm4(uint32_t* r, uint32_t addr)
{
    asm volatile("ldmatrix.sync.aligned.m8n8.x4.shared.b16 {%0,%1,%2,%3}, [%4];"
        : "=r"(r[0]), "=r"(r[1]), "=r"(r[2]), "=r"(r[3]) : "r"(addr));
}
__device__ __forceinline__ void ldsm4t(uint32_t* r, uint32_t addr)
{
    asm volatile("ldmatrix.sync.aligned.m8n8.x4.trans.shared.b16 {%0,%1,%2,%3}, [%4];"
        : "=r"(r[0]), "=r"(r[1]), "=r"(r[2]), "=r"(r[3]) : "r"(addr));
}
__device__ __forceinline__ void mma_bf16(float* c, const uint32_t* a, const uint32_t* b)
{
    asm volatile(
        "mma.sync.aligned.m16n8k16.row.col.f32.bf16.bf16.f32 "
        "{%0,%1,%2,%3}, {%4,%5,%6,%7}, {%8,%9}, {%0,%1,%2,%3};"
        : "+f"(c[0]), "+f"(c[1]), "+f"(c[2]), "+f"(c[3])
        : "r"(a[0]), "r"(a[1]), "r"(a[2]), "r"(a[3]), "r"(b[0]), "r"(b[1]));
}

__device__ __forceinline__ void epi_store(float* cp, float r0, float r1, bool accum)
{
    float2* p2 = (float2*)cp;
    if (accum) {
        float2 o = *p2;
        r0 += o.x; r1 += o.y;
    }
    *p2 = make_float2(r0, r1);
}
__device__ __forceinline__ void epi_store(bf16* cp, float r0, float r1, bool accum)
{
    (void)accum;
    *(bf162*)cp = __floats2bfloat162_rn(r0, r1);
}

__device__ __forceinline__ void loadA_tile(bf16 (&As)[128][64], const bf16* Ap,
                                           int K, int k0, int tid)
{
    #pragma unroll
    for (int i = 0; i < 4; i++) {
        int q = tid + 256*i;
        int row = q >> 3, c = q & 7;
        int cs = c ^ (row & 7);
        cp16(smem_u32(&As[row][cs*8]), Ap + (size_t)row*K + k0 + c*8);
    }
}
__device__ __forceinline__ void loadB_tile(bf16 (&Bs)[64][64], const bf16* Bp,
                                           int Nn, int k0, int tid)
{
    #pragma unroll
    for (int i = 0; i < 2; i++) {
        int q = tid + 256*i;
        int row = q >> 3, c = q & 7;
        int cs = c ^ (row & 7);
        cp16(smem_u32(&Bs[row][cs*8]), Bp + (size_t)(k0 + row)*Nn + c*8);
    }
}
__device__ __forceinline__ void loadB_tile2(bf16 (&Bs)[64][128], const bf16* Bp,
                                            int Nn, int k0, int tid)
{
    #pragma unroll
    for (int i = 0; i < 4; i++) {
        int q = tid + 256*i;
        int row = q >> 4, c = q & 15;
        int cs = c ^ (row & 7);
        cp16(smem_u32(&Bs[row][cs*8]), Bp + (size_t)(k0 + row)*Nn + c*8);
    }
}

// =============== BN=64 GEMM (for N=192 GEMMs): BM=128, BK=64 ===============
template<typename TOUT, bool BIAS, bool ACCUM, bool GELU_ACT>
__global__ void __launch_bounds__(256) gemm_bf(const bf16* __restrict__ A,
                                               const bf16* __restrict__ Bw,
                                               const float* __restrict__ bias,
                                               TOUT* __restrict__ C,
                                               int M, int Nn, int K)
{
    __shared__ bf16 As[2][128][64];
    __shared__ bf16 Bs[2][64][64];

    int tid = threadIdx.x;
    int w = tid >> 5, lane = tid & 31;
    int g = lane >> 2, t = lane & 3;
    int moff = (w & 3) * 32, noff = (w >> 2) * 32;
    int m0 = blockIdx.y * 128, n0 = blockIdx.x * 64;

    const bf16* Ap = A + (size_t)m0 * K;
    const bf16* Bp = Bw + n0;

    float acc[2][4][4];
    #pragma unroll
    for (int i = 0; i < 2; i++)
        #pragma unroll
        for (int j = 0; j < 4; j++)
            #pragma unroll
            for (int q = 0; q < 4; q++) acc[i][j][q] = 0.f;

    loadA_tile(As[0], Ap, K, 0, tid);
    loadB_tile(Bs[0], Bp, Nn, 0, tid);
    cpcommit();

    int nk = K >> 6;
    for (int it = 0; it < nk; it++) {
        int buf = it & 1;
        if (it + 1 < nk) {
            int k0 = (it + 1) << 6;
            loadA_tile(As[buf ^ 1], Ap, K, k0, tid);
            loadB_tile(Bs[buf ^ 1], Bp, Nn, k0, tid);
            cpcommit();
            cpwait1();
        } else {
            cpwait0();
        }
        __syncthreads();
        #pragma unroll
        for (int ks = 0; ks < 4; ks++) {
            uint32_t af[2][4], bfr[2][4];
            #pragma unroll
            for (int i = 0; i < 2; i++) {
                int mr = moff + i*16 + (lane & 15);
                int cc = (ks*2 + (lane >> 4)) ^ (mr & 7);
                ldsm4(af[i], smem_u32(&As[buf][mr][cc*8]));
            }
            #pragma unroll
            for (int jj = 0; jj < 2; jj++) {
                int kr = ks*16 + (lane & 15);
                int cc = (((noff + jj*16) >> 3) + (lane >> 4)) ^ (kr & 7);
                ldsm4t(bfr[jj], smem_u32(&Bs[buf][kr][cc*8]));
            }
            #pragma unroll
            for (int i = 0; i < 2; i++) {
                mma_bf16(acc[i][0], af[i], &bfr[0][0]);
                mma_bf16(acc[i][1], af[i], &bfr[0][2]);
                mma_bf16(acc[i][2], af[i], &bfr[1][0]);
                mma_bf16(acc[i][3], af[i], &bfr[1][2]);
            }
        }
        __syncthreads();
    }

    #pragma unroll
    for (int i = 0; i < 2; i++) {
        #pragma unroll
        for (int j = 0; j < 4; j++) {
            int col = n0 + noff + j*8 + t*2;
            float b0 = 0.f, b1 = 0.f;
            if (BIAS) { b0 = bias[col]; b1 = bias[col+1]; }
            #pragma unroll
            for (int hh = 0; hh < 2; hh++) {
                int row = m0 + moff + i*16 + g + hh*8;
                float r0 = acc[i][j][hh*2]   + b0;
                float r1 = acc[i][j][hh*2+1] + b1;
                if (GELU_ACT) {
                    r0 = 0.5f * r0 * (1.f + erff(r0 * 0.70710678118654752f));
                    r1 = 0.5f * r1 * (1.f + erff(r1 * 0.70710678118654752f));
                }
                epi_store(C + (size_t)row*Nn + col, r0, r1, ACCUM);
            }
        }
    }
}

// =============== BN=128 GEMM (big-N GEMMs): BM=128, BK=64, warp 64x32 ===============
template<typename TOUT, bool BIAS, bool ACCUM, bool GELU_ACT>
__global__ void __launch_bounds__(256) gemm2_k(const bf16* __restrict__ A,
                                               const bf16* __restrict__ Bw,
                                               const float* __restrict__ bias,
                                               TOUT* __restrict__ C,
                                               int M, int Nn, int K)
{
    extern __shared__ char sm2[];
    bf16 (*As)[128][64]  = reinterpret_cast<bf16(*)[128][64]>(sm2);           // 2 stages
    bf16 (*Bs)[64][128]  = reinterpret_cast<bf16(*)[64][128]>(sm2 + 2*128*64*2);

    int tid = threadIdx.x;
    int w = tid >> 5, lane = tid & 31;
    int g = lane >> 2, t = lane & 3;
    int moff = (w & 1) * 64, noff = (w >> 1) * 32;
    int m0 = blockIdx.y * 128, n0 = blockIdx.x * 128;

    const bf16* Ap = A + (size_t)m0 * K;
    const bf16* Bp = Bw + n0;

    float acc[4][4][4];
    #pragma unroll
    for (int i = 0; i < 4; i++)
        #pragma unroll
        for (int j = 0; j < 4; j++)
            #pragma unroll
            for (int q = 0; q < 4; q++) acc[i][j][q] = 0.f;

    loadA_tile(As[0], Ap, K, 0, tid);
    loadB_tile2(Bs[0], Bp, Nn, 0, tid);
    cpcommit();

    int nk = K >> 6;
    for (int it = 0; it < nk; it++) {
        int buf = it & 1;
        if (it + 1 < nk) {
            int k0 = (it + 1) << 6;
            loadA_tile(As[buf ^ 1], Ap, K, k0, tid);
            loadB_tile2(Bs[buf ^ 1], Bp, Nn, k0, tid);
            cpcommit();
            cpwait1();
        } else {
            cpwait0();
        }
        __syncthreads();
        #pragma unroll
        for (int ks = 0; ks < 4; ks++) {
            uint32_t af[4][4], bfr[2][4];
            #pragma unroll
            for (int i = 0; i < 4; i++) {
                int mr = moff + i*16 + (lane & 15);
                int cc = (ks*2 + (lane >> 4)) ^ (mr & 7);
                ldsm4(af[i], smem_u32(&As[buf][mr][cc*8]));
            }
            #pragma unroll
            for (int jj = 0; jj < 2; jj++) {
                int kr = ks*16 + (lane & 15);
                int jch = (noff >> 3) + jj*2 + (lane >> 4);
                int cc = jch ^ (kr & 7);
                ldsm4t(bfr[jj], smem_u32(&Bs[buf][kr][cc*8]));
            }
            #pragma unroll
            for (int i = 0; i < 4; i++) {
                mma_bf16(acc[i][0], af[i], &bfr[0][0]);
                mma_bf16(acc[i][1], af[i], &bfr[0][2]);
                mma_bf16(acc[i][2], af[i], &bfr[1][0]);
                mma_bf16(acc[i][3], af[i], &bfr[1][2]);
            }
        }
        __syncthreads();
    }

    #pragma unroll
    for (int i = 0; i < 4; i++) {
        #pragma unroll
        for (int j = 0; j < 4; j++) {
            int col = n0 + noff + j*8 + t*2;
            float b0 = 0.f, b1 = 0.f;
            if (BIAS) { b0 = bias[col]; b1 = bias[col+1]; }
            #pragma unroll
            for (int hh = 0; hh < 2; hh++) {
                int row = m0 + moff + i*16 + g + hh*8;
                float r0 = acc[i][j][hh*2]   + b0;
                float r1 = acc[i][j][hh*2+1] + b1;
                if (GELU_ACT) {
                    r0 = 0.5f * r0 * (1.f + erff(r0 * 0.70710678118654752f));
                    r1 = 0.5f * r1 * (1.f + erff(r1 * 0.70710678118654752f));
                }
                epi_store(C + (size_t)row*Nn + col, r0, r1, ACCUM);
            }
        }
    }
}

// ===== final GEMM: z = mid2 @ w2u + bias + residual(xfl), write NCHW out =====
__global__ void __launch_bounds__(256) gemm_out_k(const bf16* __restrict__ A,
                                                  const bf16* __restrict__ Bw,
                                                  const float* __restrict__ bias,
                                                  const float* __restrict__ resid,
                                                  float* __restrict__ outp)
{
    __shared__ char sbuf[49152];
    bf16 (&As)[2][128][64] = *reinterpret_cast<bf16(*)[2][128][64]>(sbuf);
    bf16 (&Bs)[2][64][64]  = *reinterpret_cast<bf16(*)[2][64][64]>(sbuf + 32768);

    const int K = 192, Nn = 384;
    int tid = threadIdx.x;
    int w = tid >> 5, lane = tid & 31;
    int g = lane >> 2, t = lane & 3;
    int moff = (w & 3) * 32, noff = (w >> 2) * 32;
    int m0 = blockIdx.y * 128, n0 = blockIdx.x * 64;

    const bf16* Ap = A + (size_t)m0 * K;
    const bf16* Bp = Bw + n0;

    float acc[2][4][4];
    #pragma unroll
    for (int i = 0; i < 2; i++)
        #pragma unroll
        for (int j = 0; j < 4; j++)
            #pragma unroll
            for (int q = 0; q < 4; q++) acc[i][j][q] = 0.f;

    loadA_tile(As[0], Ap, K, 0, tid);
    loadB_tile(Bs[0], Bp, Nn, 0, tid);
    cpcommit();

    int nk = K >> 6;   // 3
    for (int it = 0; it < nk; it++) {
        int buf = it & 1;
        if (it + 1 < nk) {
            int k0 = (it + 1) << 6;
            loadA_tile(As[buf ^ 1], Ap, K, k0, tid);
            loadB_tile(Bs[buf ^ 1], Bp, Nn, k0, tid);
            cpcommit();
            cpwait1();
        } else {
            cpwait0();
        }
        __syncthreads();
        #pragma unroll
        for (int ks = 0; ks < 4; ks++) {
            uint32_t af[2][4], bfr[2][4];
            #pragma unroll
            for (int i = 0; i < 2; i++) {
                int mr = moff + i*16 + (lane & 15);
                int cc = (ks*2 + (lane >> 4)) ^ (mr & 7);
                ldsm4(af[i], smem_u32(&As[buf][mr][cc*8]));
            }
            #pragma unroll
            for (int jj = 0; jj < 2; jj++) {
                int kr = ks*16 + (lane & 15);
                int cc = (((noff + jj*16) >> 3) + (lane >> 4)) ^ (kr & 7);
                ldsm4t(bfr[jj], smem_u32(&Bs[buf][kr][cc*8]));
            }
            #pragma unroll
            for (int i = 0; i < 2; i++) {
                mma_bf16(acc[i][0], af[i], &bfr[0][0]);
                mma_bf16(acc[i][1], af[i], &bfr[0][2]);
                mma_bf16(acc[i][2], af[i], &bfr[1][0]);
                mma_bf16(acc[i][3], af[i], &bfr[1][2]);
            }
        }
        __syncthreads();
    }

    float (&tr)[64][132] = *reinterpret_cast<float(*)[64][132]>(sbuf);
    #pragma unroll
    for (int i = 0; i < 2; i++) {
        #pragma unroll
        for (int j = 0; j < 4; j++) {
            int lc = noff + j*8 + t*2;
            float b0 = bias[n0 + lc], b1 = bias[n0 + lc + 1];
            #pragma unroll
            for (int hh = 0; hh < 2; hh++) {
                int lr = moff + i*16 + g + hh*8;
                float2 res = *(const float2*)(resid + (size_t)(m0 + lr)*Nn + n0 + lc);
                tr[lc][lr]     = acc[i][j][hh*2]   + b0 + res.x;
                tr[lc + 1][lr] = acc[i][j][hh*2+1] + b1 + res.y;
            }
        }
    }
    __syncthreads();

    {
        int cr = tid >> 2, ch = tid & 3;
        int tok0 = m0 + ch*32;
        int b = tok0 / HW_;
        int p = tok0 - b*HW_;
        float* op = outp + ((size_t)b*C_ + n0 + cr)*HW_ + p;
        #pragma unroll
        for (int z = 0; z < 32; z += 4) {
            float4 v = make_float4(tr[cr][ch*32 + z],     tr[cr][ch*32 + z + 1],
                                   tr[cr][ch*32 + z + 2], tr[cr][ch*32 + z + 3]);
            *(float4*)(op + z) = v;
        }
    }
}

// ================= XCA phase A: partial S = q @ k^T + norms (MMA) =================
__global__ void __launch_bounds__(256) xca_s_k(const bf16* __restrict__ qkv,
                                               float* __restrict__ gS,
                                               float* __restrict__ gN)
{
    extern __shared__ char smraw[];
    bf16*  q_s = (bf16*)smraw;                                // [48][456]
    bf16*  k_s = (bf16*)(smraw + 48*456*2);                   // [448][56]
    float* Ss  = (float*)(smraw + 48*456*2 + (size_t)XA_TOK*56*2); // [48][48]
    float* ns  = Ss + 48*48;                                  // [96]

    int bh = blockIdx.x, chunk = blockIdx.y;
    int b = bh >> 3, h = bh & 7;
    int tid = threadIdx.x;
    int w = tid >> 5, lane = tid & 31;
    int g = lane >> 2, t = lane & 3;
    const bf16* qb = qkv + ((size_t)b*HW_ + chunk*XA_TOK)*1152 + h*48;
    const bf16* kb = qb + 384;

    for (int i = tid; i < XA_TOK*6; i += 256) {
        int row = i/6, c = i%6;
        cp16(smem_u32(k_s + row*56 + c*8), kb + (size_t)row*1152 + c*8);
    }
    cpcommit();
    for (int i = tid; i < XA_TOK*24; i += 256) {
        int tok = i/24, dp = i%24;
        bf162 v = *(const bf162*)(qb + (size_t)tok*1152 + dp*2);
        q_s[(dp*2  )*456 + tok] = v.x;
        q_s[(dp*2+1)*456 + tok] = v.y;
    }
    for (int i = tid; i < 48*48; i += 256) Ss[i] = 0.f;
    if (tid < 96) ns[tid] = 0.f;
    cpwait0();
    __syncthreads();

    for (int u = tid; u < 384; u += 256) {
        int r = u >> 2, seg = u & 3;
        float acc = 0.f;
        if (r < 48) {
            const bf16* p = q_s + r*456 + seg*112;
            for (int x = 0; x < 112; x++) {
                float v = __bfloat162float(p[x]);
                acc = fmaf(v, v, acc);
            }
        } else {
            const bf16* p = k_s + (r - 48) + seg*112*56;
            for (int x = 0; x < 112; x++) {
                float v = __bfloat162float(p[x*56]);
                acc = fmaf(v, v, acc);
            }
        }
        atomicAdd(&ns[r], acc);
    }

    float acc[3][6][4];
    #pragma unroll
    for (int i = 0; i < 3; i++)
        #pragma unroll
        for (int j = 0; j < 6; j++)
            #pragma unroll
            for (int q = 0; q < 4; q++) acc[i][j][q] = 0.f;

    for (int s = w; s < 28; s += 8) {
        int k0 = s*16;
        uint32_t af[3][4], bfr[3][4];
        #pragma unroll
        for (int i = 0; i < 3; i++)
            ldsm4(af[i], smem_u32(q_s + (i*16 + (lane & 15))*456 + k0 + (lane >> 4)*8));
        #pragma unroll
        for (int jj = 0; jj < 3; jj++)
            ldsm4t(bfr[jj], smem_u32(k_s + (k0 + (lane & 15))*56 + jj*16 + (lane >> 4)*8));
        #pragma unroll
        for (int i = 0; i < 3; i++) {
            #pragma unroll
            for (int jj = 0; jj < 3; jj++) {
                mma_bf16(acc[i][jj*2  ], af[i], &bfr[jj][0]);
                mma_bf16(acc[i][jj*2+1], af[i], &bfr[jj][2]);
            }
        }
    }

    #pragma unroll
    for (int i = 0; i < 3; i++) {
        #pragma unroll
        for (int j = 0; j < 6; j++) {
            int r0 = i*16 + g, c0 = j*8 + t*2;
            atomicAdd(&Ss[r0*48 + c0    ], acc[i][j][0]);
            atomicAdd(&Ss[r0*48 + c0 + 1], acc[i][j][1]);
            atomicAdd(&Ss[(r0+8)*48 + c0    ], acc[i][j][2]);
            atomicAdd(&Ss[(r0+8)*48 + c0 + 1], acc[i][j][3]);
        }
    }
    __syncthreads();

    for (int i = tid; i < 48*48; i += 256)
        atomicAdd(&gS[(size_t)bh*2304 + i], Ss[i]);
    if (tid < 96)
        atomicAdd(&gN[bh*96 + tid], ns[tid]);
}

// ================= XCA softmax =================
__global__ void __launch_bounds__(96) xca_soft_k(const float* __restrict__ gS,
                                                 const float* __restrict__ gN,
                                                 bf16* __restrict__ gAT)
{
    __shared__ float iq[48], ik[48];
    int bh = blockIdx.x, tid = threadIdx.x;
    if (tid < 48)      iq[tid]    = 1.f / fmaxf(sqrtf(gN[bh*96 + tid]), 1e-12f);
    else               ik[tid-48] = 1.f / fmaxf(sqrtf(gN[bh*96 + tid]), 1e-12f);
    __syncthreads();
    if (tid < 48) {
        float row[48];
        const float* S = gS + (size_t)bh*2304 + tid*48;
        float mx = -1e30f;
        #pragma unroll 8
        for (int e = 0; e < 48; e++) {
            float l = S[e] * iq[tid] * ik[e];
            row[e] = l;
            mx = fmaxf(mx, l);
        }
        float sum = 0.f;
        #pragma unroll 8
        for (int e = 0; e < 48; e++) {
            float ex = expf(row[e] - mx);
            row[e] = ex;
            sum += ex;
        }
        float inv = 1.f / sum;
        #pragma unroll 8
        for (int e = 0; e < 48; e++)
            gAT[(size_t)bh*2304 + e*48 + tid] = __float2bfloat16(row[e] * inv);
    }
}

// ================= XCA phase C: y = v @ attn^T (MMA) =================
__global__ void __launch_bounds__(224) xca_av_k(const bf16* __restrict__ qkv,
                                                const bf16* __restrict__ gAT,
                                                bf16* __restrict__ outp)
{
    extern __shared__ char smraw[];
    bf16* v_s = (bf16*)smraw;                           // [448][56]
    bf16* aT  = (bf16*)(smraw + (size_t)XA_TOK*56*2);   // [48][56]

    int bh = blockIdx.x, chunk = blockIdx.y;
    int b = bh >> 3, h = bh & 7;
    int tid = threadIdx.x;
    int w = tid >> 5, lane = tid & 31;
    int g = lane >> 2, t = lane & 3;
    const bf16* vb = qkv + ((size_t)b*HW_ + chunk*XA_TOK)*1152 + h*48 + 768;

    for (int i = tid; i < XA_TOK*6; i += 224) {
        int row = i/6, c = i%6;
        cp16(smem_u32(v_s + row*56 + c*8), vb + (size_t)row*1152 + c*8);
    }
    for (int i = tid; i < 48*6; i += 224) {
        int e = i/6, c = i%6;
        cp16(smem_u32(aT + e*56 + c*8), gAT + (size_t)bh*2304 + e*48 + c*8);
    }
    cpcommit();
    cpwait0();
    __syncthreads();

    int tk0 = w*64;
    float acc[4][6][4];
    #pragma unroll
    for (int i = 0; i < 4; i++)
        #pragma unroll
        for (int j = 0; j < 6; j++)
            #pragma unroll
            for (int q = 0; q < 4; q++) acc[i][j][q] = 0.f;

    #pragma unroll
    for (int ks = 0; ks < 3; ks++) {
        int k0 = ks*16;
        uint32_t af[4][4], bfr[3][4];
        #pragma unroll
        for (int i = 0; i < 4; i++)
            ldsm4(af[i], smem_u32(v_s + (tk0 + i*16 + (lane & 15))*56 + k0 + (lane >> 4)*8));
        #pragma unroll
        for (int jj = 0; jj < 3; jj++)
            ldsm4t(bfr[jj], smem_u32(aT + (k0 + (lane & 15))*56 + jj*16 + (lane >> 4)*8));
        #pragma unroll
        for (int i = 0; i < 4; i++) {
            #pragma unroll
            for (int jj = 0; jj < 3; jj++) {
                mma_bf16(acc[i][jj*2  ], af[i], &bfr[jj][0]);
                mma_bf16(acc[i][jj*2+1], af[i], &bfr[jj][2]);
            }
        }
    }

    size_t tokbase = (size_t)b*HW_ + (size_t)chunk*XA_TOK + tk0;
    #pragma unroll
    for (int i = 0; i < 4; i++) {
        #pragma unroll
        for (int j = 0; j < 6; j++) {
            int r0 = i*16 + g, c0 = j*8 + t*2;
            *(bf162*)(outp + (tokbase + r0)*C_ + h*48 + c0) =
                __floats2bfloat162_rn(acc[i][j][0], acc[i][j][1]);
            *(bf162*)(outp + (tokbase + r0 + 8)*C_ + h*48 + c0) =
                __floats2bfloat162_rn(acc[i][j][2], acc[i][j][3]);
        }
    }
}

// ---------------- launch ----------------
extern "C" void kernel_launch(void* const* d_in, const int* in_sizes, int n_in,
                              void* d_out, int out_size)
{
    (void)in_sizes; (void)n_in; (void)out_size;
    const float* x      = (const float*)d_in[0];
    const float* dw_w0  = (const float*)d_in[1];
    const float* dw_b0  = (const float*)d_in[2];
    const float* dw_w1  = (const float*)d_in[3];
    const float* dw_b1  = (const float*)d_in[4];
    const float* ln1_g  = (const float*)d_in[5];
    const float* ln1_b  = (const float*)d_in[6];
    const float* qkv_w  = (const float*)d_in[7];
    const float* proj_w = (const float*)d_in[8];
    const float* proj_b = (const float*)d_in[9];
    const float* ln2_g  = (const float*)d_in[10];
    const float* ln2_b  = (const float*)d_in[11];
    const float* m1dw   = (const float*)d_in[12];
    const float* m1uw   = (const float*)d_in[13];
    const float* m1ub   = (const float*)d_in[14];
    const float* m2dw   = (const float*)d_in[15];
    const float* m2uw   = (const float*)d_in[16];
    const float* m2ub   = (const float*)d_in[17];
    float* out = (float*)d_out;

    void* p = 0;
    cudaGetSymbolAddress(&p, g_s1);
    float* s1 = (float*)p;
    cudaGetSymbolAddress(&p, g_s2);
    float* s2 = (float*)p;
    cudaGetSymbolAddress(&p, g_xfl);
    float* xfl = (float*)p;
    cudaGetSymbolAddress(&p, g_ln);
    bf16* lnb = (bf16*)p;
    cudaGetSymbolAddress(&p, g_qkv);
    bf16* qkvb = (bf16*)p;
    cudaGetSymbolAddress(&p, g_att);
    bf16* attb = (bf16*)p;
    cudaGetSymbolAddress(&p, g_mid1);
    bf16* mid1 = (bf16*)p;
    cudaGetSymbolAddress(&p, g_hid);
    bf16* hid = (bf16*)p;
    cudaGetSymbolAddress(&p, g_mid2);
    bf16* mid2 = (bf16*)p;
    cudaGetSymbolAddress(&p, g_S);
    float* gS = (float*)p;
    cudaGetSymbolAddress(&p, g_N);
    float* gN = (float*)p;
    cudaGetSymbolAddress(&p, g_aT);
    bf16* gAT = (bf16*)p;
    cudaGetSymbolAddress(&p, g_wqkv);
    bf16* wqkv = (bf16*)p;
    cudaGetSymbolAddress(&p, g_wproj);
    bf16* wproj = (bf16*)p;
    cudaGetSymbolAddress(&p, g_w1d);
    bf16* w1d = (bf16*)p;
    cudaGetSymbolAddress(&p, g_w1u);
    bf16* w1u = (bf16*)p;
    cudaGetSymbolAddress(&p, g_w2d);
    bf16* w2d = (bf16*)p;
    cudaGetSymbolAddress(&p, g_w2u);
    bf16* w2u = (bf16*)p;

    // dynamic smem opt-in
    const int XS_SMEM = 48*456*2 + XA_TOK*56*2 + (48*48 + 96)*4;  // 103552
    const int AV_SMEM = XA_TOK*56*2 + 48*56*2;                    // 55552
    const int GL_SMEM = 32*385*4;                                 // 49280
    const int G2_SMEM = 2*128*64*2 + 2*64*128*2;                  // 65536
    cudaFuncSetAttribute(xca_s_k,   cudaFuncAttributeMaxDynamicSharedMemorySize, XS_SMEM);
    cudaFuncSetAttribute(xca_av_k,  cudaFuncAttributeMaxDynamicSharedMemorySize, AV_SMEM);
    cudaFuncSetAttribute(gatherln_k, cudaFuncAttributeMaxDynamicSharedMemorySize, GL_SMEM);
    cudaFuncSetAttribute(gemm2_k<bf16, false, false, false>, cudaFuncAttributeMaxDynamicSharedMemorySize, G2_SMEM);
    cudaFuncSetAttribute(gemm2_k<float, true, true, false>,  cudaFuncAttributeMaxDynamicSharedMemorySize, G2_SMEM);
    cudaFuncSetAttribute(gemm2_k<bf16, true, false, true>,   cudaFuncAttributeMaxDynamicSharedMemorySize, G2_SMEM);

    // launch 0: prologue (dwconv0 + weight cvt + zero S/N)
    prologue_k<<<DW_BLOCKS + CVT_BLOCKS + ZR_BLOCKS, 256>>>(
        x, dw_w0, dw_b0, s1,
        qkv_w, proj_w, m1dw, m1uw, m2dw, m2uw,
        wqkv, wproj, w1d, w1u, w2d, w2u, gS, gN);

    // launch 1: dwconv stage 2
    dwconv_k<<<DW_BLOCKS, 256>>>(x + (size_t)2*SPLIT_*HW_, (size_t)C_*HW_,
                                 s1, (size_t)SPLIT_*HW_, dw_w1, dw_b1, s2);

    // launch 2: fused gather + LN1
    gatherln_k<<<dim3(HW_/32, B_), 256, GL_SMEM>>>(x, ln1_g, ln1_b, xfl, lnb);

    // launch 3: qkv GEMM (profiled slot)
    gemm2_k<bf16, false, false, false><<<dim3(1152/128, NTOK/128), 256, G2_SMEM>>>(lnb, wqkv, (const float*)0, qkvb, NTOK, 1152, 384);

    // XCA
    xca_s_k<<<dim3(128, XA_CH), 256, XS_SMEM>>>(qkvb, gS, gN);
    xca_soft_k<<<128, 96>>>(gS, gN, gAT);
    xca_av_k<<<dim3(128, XA_CH), 224, AV_SMEM>>>(qkvb, gAT, attb);

    // proj GEMM (+bias, += residual into xfl)
    gemm2_k<float, true, true, false><<<dim3(384/128, NTOK/128), 256, G2_SMEM>>>(attb, wproj, proj_b, xfl, NTOK, 384, 384);

    // MLP
    ln_k<<<NTOK, 128>>>(xfl, ln2_g, ln2_b, lnb);
    gemm_bf<bf16, false, false, false><<<dim3(192/64, NTOK/128), 256>>>(lnb, w1d, (const float*)0, mid1, NTOK, 192, 384);
    gemm2_k<bf16, true, false, true><<<dim3(1536/128, NTOK/128), 256, G2_SMEM>>>(mid1, w1u, m1ub, hid, NTOK, 1536, 192);
    gemm_bf<bf16, false, false, false><<<dim3(192/64, NTOK/128), 256>>>(hid, w2d, (const float*)0, mid2, NTOK, 192, 1536);

    // final GEMM fused with residual + NCHW scatter
    gemm_out_k<<<dim3(384/64, NTOK/128), 256>>>(mid2, w2u, m2ub, xfl, out);
}

// round 12
// speedup vs baseline: 4.9491x; 1.0038x over previous
#include <cuda_runtime.h>
#include <cuda_bf16.h>
#include <stdint.h>
#include <math.h>

#define B_    16
#define C_    384
#define HW_   3136
#define W56   56
#define NTOK  (B_*HW_)     // 50176
#define NH_   8
#define HD_   48
#define SPLIT_ 128
#define HID_  1536
#define R_    192
#define XA_TOK 448
#define XA_CH  7

typedef __nv_bfloat16 bf16;
typedef __nv_bfloat162 bf162;

// ---------------- scratch (device globals; no allocations) ----------------
__device__ float g_s1  [(size_t)B_*SPLIT_*HW_];
__device__ float g_s2  [(size_t)B_*SPLIT_*HW_];
__device__ float g_xfl [(size_t)NTOK*C_];
__device__ bf16  g_ln  [(size_t)NTOK*C_];
__device__ bf16  g_qkv [(size_t)NTOK*3*C_];
__device__ bf16  g_att [(size_t)NTOK*C_];
__device__ bf16  g_mid1[(size_t)NTOK*R_];
__device__ bf16  g_hid [(size_t)NTOK*HID_];
__device__ bf16  g_mid2[(size_t)NTOK*R_];
// XCA intermediates
__device__ float g_S  [(size_t)128*2304];
__device__ float g_N  [(size_t)128*96];
__device__ bf16  g_aT [(size_t)128*2304];
// bf16 weights
__device__ bf16  g_wqkv [(size_t)C_*3*C_];
__device__ bf16  g_wproj[(size_t)C_*C_];
__device__ bf16  g_w1d  [(size_t)C_*R_];
__device__ bf16  g_w1u  [(size_t)R_*HID_];
__device__ bf16  g_w2d  [(size_t)HID_*R_];
__device__ bf16  g_w2u  [(size_t)R_*C_];

// ---------------- device bodies shared by prologue ----------------
__device__ __forceinline__ void dwconv_body(int idx,
    const float* a, size_t strideA, const float* bsrc, size_t strideB,
    const float* w, const float* bias, float* outp)
{
    if (idx >= B_*SPLIT_*HW_) return;
    int p = idx % HW_;
    int c = (idx / HW_) % SPLIT_;
    int b = idx / (HW_*SPLIT_);
    int y = p / W56, xq = p % W56;
    const float* pa = a    + (size_t)b*strideA + (size_t)c*HW_;
    const float* pb = bsrc + (size_t)b*strideB + (size_t)c*HW_;
    const float* wc = w + c*9;
    float acc = bias[c];
    #pragma unroll
    for (int dy = -1; dy <= 1; dy++) {
        int yy = y + dy;
        if (yy < 0 || yy >= W56) continue;
        #pragma unroll
        for (int dx = -1; dx <= 1; dx++) {
            int xx = xq + dx;
            if (xx < 0 || xx >= W56) continue;
            float v = pa[yy*W56 + xx] + pb[yy*W56 + xx];
            acc = fmaf(v, wc[(dy+1)*3 + (dx+1)], acc);
        }
    }
    outp[idx] = acc;
}

__device__ __forceinline__ void cvt_body(int i,
    const float* s0, const float* s1p, const float* s2p, const float* s3,
    const float* s4, const float* s5,
    bf16* d0, bf16* d1, bf16* d2, bf16* d3, bf16* d4, bf16* d5)
{
    const int L0 = C_*3*C_, L1 = C_*C_, L2 = C_*R_, L3 = R_*HID_, L4 = HID_*R_, L5 = R_*C_;
    const float* s; bf16* d; int off = i;
    if (off < L0) { s = s0; d = d0; }
    else { off -= L0;
      if (off < L1) { s = s1p; d = d1; }
      else { off -= L1;
        if (off < L2) { s = s2p; d = d2; }
        else { off -= L2;
          if (off < L3) { s = s3; d = d3; }
          else { off -= L3;
            if (off < L4) { s = s4; d = d4; }
            else { off -= L4;
              if (off < L5) { s = s5; d = d5; }
              else return; } } } } }
    float4 v = *(const float4*)(s + off);
    bf162* o = (bf162*)(d + off);
    o[0] = __floats2bfloat162_rn(v.x, v.y);
    o[1] = __floats2bfloat162_rn(v.z, v.w);
}

// prologue: dwconv0 + weight cvt + zero(S,N), partitioned by blockIdx.
#define DW_BLOCKS  ((B_*SPLIT_*HW_ + 255)/256)
#define CVT_TOTAL  (C_*3*C_ + C_*C_ + C_*R_ + R_*HID_ + HID_*R_ + R_*C_)
#define CVT_BLOCKS ((CVT_TOTAL/4 + 255)/256)
#define ZR_TOTAL   (128*2304 + 128*96)
#define ZR_BLOCKS  ((ZR_TOTAL + 255)/256)

__global__ void __launch_bounds__(256) prologue_k(
    const float* __restrict__ x, const float* __restrict__ dw_w0,
    const float* __restrict__ dw_b0, float* __restrict__ s1out,
    const float* qkv_w, const float* proj_w, const float* m1dw,
    const float* m1uw, const float* m2dw, const float* m2uw,
    bf16* wqkv, bf16* wproj, bf16* w1d, bf16* w1u, bf16* w2d, bf16* w2u,
    float* gS, float* gN)
{
    int bid = blockIdx.x, tid = threadIdx.x;
    if (bid < DW_BLOCKS) {
        dwconv_body(bid*256 + tid,
                    x + (size_t)SPLIT_*HW_, (size_t)C_*HW_,
                    x, (size_t)C_*HW_, dw_w0, dw_b0, s1out);
    } else if (bid < DW_BLOCKS + CVT_BLOCKS) {
        int i = ((bid - DW_BLOCKS)*256 + tid)*4;
        cvt_body(i, qkv_w, proj_w, m1dw, m1uw, m2dw, m2uw,
                 wqkv, wproj, w1d, w1u, w2d, w2u);
    } else {
        int i = (bid - DW_BLOCKS - CVT_BLOCKS)*256 + tid;
        if (i < 128*2304) gS[i] = 0.f;
        else if (i < ZR_TOTAL) gN[i - 128*2304] = 0.f;
    }
}

// ---------------- depthwise conv (second stage) ----------------
__global__ void dwconv_k(const float* __restrict__ a, size_t strideA,
                         const float* __restrict__ bsrc, size_t strideB,
                         const float* __restrict__ w, const float* __restrict__ bias,
                         float* __restrict__ out)
{
    dwconv_body(blockIdx.x*blockDim.x + threadIdx.x, a, strideA, bsrc, strideB, w, bias, out);
}

// ------------- fused gather (concat NCHW -> token-major) + LayerNorm1 -------------
__global__ void __launch_bounds__(256) gatherln_k(const float* __restrict__ x,
                                                  const float* __restrict__ gam,
                                                  const float* __restrict__ bet,
                                                  float* __restrict__ xfl,
                                                  bf16* __restrict__ lnb)
{
    extern __shared__ float sm[];   // [32 tok][385]
    __shared__ float mean_s[32], rstd_s[32];
    int b = blockIdx.y, p0 = blockIdx.x * 32;
    int tid = threadIdx.x;

    #pragma unroll
    for (int it = 0; it < 48; it++) {
        int i = tid + 256*it;
        int c = i >> 5, tok = i & 31;
        float v;
        if (c < 128)      v = x   [((size_t)b*C_ + c)*HW_ + p0 + tok];
        else if (c < 256) v = g_s1[((size_t)b*SPLIT_ + (c-128))*HW_ + p0 + tok];
        else              v = g_s2[((size_t)b*SPLIT_ + (c-256))*HW_ + p0 + tok];
        sm[tok*385 + c] = v;
    }
    __syncthreads();

    int w = tid >> 5, lane = tid & 31;
    int sub = lane >> 3, li = lane & 7;
    int tok = w*4 + sub;
    const float* row = sm + tok*385;
    float s = 0.f;
    #pragma unroll
    for (int k = 0; k < 48; k++) s += row[li + 8*k];
    s += __shfl_xor_sync(0xffffffffu, s, 1);
    s += __shfl_xor_sync(0xffffffffu, s, 2);
    s += __shfl_xor_sync(0xffffffffu, s, 4);
    float mean = s * (1.f/384.f);
    float vs = 0.f;
    #pragma unroll
    for (int k = 0; k < 48; k++) { float d = row[li + 8*k] - mean; vs = fmaf(d, d, vs); }
    vs += __shfl_xor_sync(0xffffffffu, vs, 1);
    vs += __shfl_xor_sync(0xffffffffu, vs, 2);
    vs += __shfl_xor_sync(0xffffffffu, vs, 4);
    if (li == 0) {
        mean_s[tok] = mean;
        rstd_s[tok] = rsqrtf(vs * (1.f/384.f) + 1e-6f);
    }
    __syncthreads();

    #pragma unroll
    for (int it = 0; it < 24; it++) {
        int jp = tid + 256*it;
        int tk = jp / 192;
        int cp = (jp % 192) * 2;
        float v0 = sm[tk*385 + cp], v1 = sm[tk*385 + cp + 1];
        float m = mean_s[tk], r = rstd_s[tk];
        size_t base = ((size_t)b*HW_ + p0 + tk)*C_ + cp;
        *(float2*)(xfl + base) = make_float2(v0, v1);
        float o0 = (v0 - m)*r*gam[cp]   + bet[cp];
        float o1 = (v1 - m)*r*gam[cp+1] + bet[cp+1];
        *(bf162*)(lnb + base) = __floats2bfloat162_rn(o0, o1);
    }
}

// ---------------- LayerNorm (LN2) ----------------
__device__ __forceinline__ float warp_sum(float v)
{
    #pragma unroll
    for (int o = 16; o > 0; o >>= 1) v += __shfl_xor_sync(0xffffffffu, v, o);
    return v;
}

__global__ void __launch_bounds__(128) ln_k(const float* __restrict__ in,
                                            const float* __restrict__ gam,
                                            const float* __restrict__ bet,
                                            bf16* __restrict__ outp)
{
    int row = blockIdx.x;
    int tid = threadIdx.x;
    const float* r = in + (size_t)row*C_;
    float v0 = r[tid], v1 = r[tid+128], v2 = r[tid+256];
    __shared__ float red[4];
    int wid = tid >> 5, lane = tid & 31;
    float s = warp_sum(v0 + v1 + v2);
    if (lane == 0) red[wid] = s;
    __syncthreads();
    float mean = (red[0]+red[1]+red[2]+red[3]) * (1.f/384.f);
    float d0 = v0 - mean, d1 = v1 - mean, d2 = v2 - mean;
    float sq = warp_sum(d0*d0 + d1*d1 + d2*d2);
    __syncthreads();
    if (lane == 0) red[wid] = sq;
    __syncthreads();
    float var = (red[0]+red[1]+red[2]+red[3]) * (1.f/384.f);
    float rs = rsqrtf(var + 1e-6f);
    bf16* o = outp + (size_t)row*C_;
    o[tid]     = __float2bfloat16(d0*rs*gam[tid]     + bet[tid]);
    o[tid+128] = __float2bfloat16(d1*rs*gam[tid+128] + bet[tid+128]);
    o[tid+256] = __float2bfloat16(d2*rs*gam[tid+256] + bet[tid+256]);
}

// ================= shared MMA helpers =================
__device__ __forceinline__ uint32_t smem_u32(const void* p)
{
    return (uint32_t)__cvta_generic_to_shared(p);
}
__device__ __forceinline__ void cp16(uint32_t dst, const void* src)
{
    asm volatile("cp.async.cg.shared.global [%0], [%1], 16;" :: "r"(dst), "l"(src));
}
__device__ __forceinline__ void cpcommit()
{
    asm volatile("cp.async.commit_group;" ::: "memory");
}
__device__ __forceinline__ void cpwait0()
{
    asm volatile("cp.async.wait_group 0;" ::: "memory");
}
__device__ __forceinline__ void cpwait1()
{
    asm volatile("cp.async.wait_group 1;" ::: "memory");
}
__device__ __forceinline__ void ldsm4(uint32_t* r, uint32_t addr)
{
    asm volatile("ldmatrix.sync.aligned.m8n8.x4.shared.b16 {%0,%1,%2,%3}, [%4];"
        : "=r"(r[0]), "=r"(r[1]), "=r"(r[2]), "=r"(r[3]) : "r"(addr));
}
__device__ __forceinline__ void ldsm4t(uint32_t* r, uint32_t addr)
{
    asm volatile("ldmatrix.sync.aligned.m8n8.x4.trans.shared.b16 {%0,%1,%2,%3}, [%4];"
        : "=r"(r[0]), "=r"(r[1]), "=r"(r[2]), "=r"(r[3]) : "r"(addr));
}
__device__ __forceinline__ void mma_bf16(float* c, const uint32_t* a, const uint32_t* b)
{
    asm volatile(
        "mma.sync.aligned.m16n8k16.row.col.f32.bf16.bf16.f32 "
        "{%0,%1,%2,%3}, {%4,%5,%6,%7}, {%8,%9}, {%0,%1,%2,%3};"
        : "+f"(c[0]), "+f"(c[1]), "+f"(c[2]), "+f"(c[3])
        : "r"(a[0]), "r"(a[1]), "r"(a[2]), "r"(a[3]), "r"(b[0]), "r"(b[1]));
}

__device__ __forceinline__ void epi_store(float* cp, float r0, float r1, bool accum)
{
    float2* p2 = (float2*)cp;
    if (accum) {
        float2 o = *p2;
        r0 += o.x; r1 += o.y;
    }
    *p2 = make_float2(r0, r1);
}
__device__ __forceinline__ void epi_store(bf16* cp, float r0, float r1, bool accum)
{
    (void)accum;
    *(bf162*)cp = __floats2bfloat162_rn(r0, r1);
}

__device__ __forceinline__ void loadA_tile(bf16 (&As)[128][64], const bf16* Ap,
                                           int K, int k0, int tid)
{
    #pragma unroll
    for (int i = 0; i < 4; i++) {
        int q = tid + 256*i;
        int row = q >> 3, c = q & 7;
        int cs = c ^ (row & 7);
        cp16(smem_u32(&As[row][cs*8]), Ap + (size_t)row*K + k0 + c*8);
    }
}
__device__ __forceinline__ void loadB_tile(bf16 (&Bs)[64][64], const bf16* Bp,
                                           int Nn, int k0, int tid)
{
    #pragma unroll
    for (int i = 0; i < 2; i++) {
        int q = tid + 256*i;
        int row = q >> 3, c = q & 7;
        int cs = c ^ (row & 7);
        cp16(smem_u32(&Bs[row][cs*8]), Bp + (size_t)(k0 + row)*Nn + c*8);
    }
}
__device__ __forceinline__ void loadB_tile2(bf16 (&Bs)[64][128], const bf16* Bp,
                                            int Nn, int k0, int tid)
{
    #pragma unroll
    for (int i = 0; i < 4; i++) {
        int q = tid + 256*i;
        int row = q >> 4, c = q & 15;
        int cs = c ^ (row & 7);
        cp16(smem_u32(&Bs[row][cs*8]), Bp + (size_t)(k0 + row)*Nn + c*8);
    }
}

// =============== BN=64 GEMM (N=192 GEMMs): BM=128, BK=64, 3-stage ===============
template<typename TOUT, bool BIAS, bool ACCUM, bool GELU_ACT>
__global__ void __launch_bounds__(256) gemm_bf(const bf16* __restrict__ A,
                                               const bf16* __restrict__ Bw,
                                               const float* __restrict__ bias,
                                               TOUT* __restrict__ C,
                                               int M, int Nn, int K)
{
    extern __shared__ char smbf[];
    bf16 (*As)[128][64] = reinterpret_cast<bf16(*)[128][64]>(smbf);
    bf16 (*Bs)[64][64]  = reinterpret_cast<bf16(*)[64][64]>(smbf + 3*128*64*2);

    int tid = threadIdx.x;
    int w = tid >> 5, lane = tid & 31;
    int g = lane >> 2, t = lane & 3;
    int moff = (w & 3) * 32, noff = (w >> 2) * 32;
    int m0 = blockIdx.y * 128, n0 = blockIdx.x * 64;

    const bf16* Ap = A + (size_t)m0 * K;
    const bf16* Bp = Bw + n0;

    float acc[2][4][4];
    #pragma unroll
    for (int i = 0; i < 2; i++)
        #pragma unroll
        for (int j = 0; j < 4; j++)
            #pragma unroll
            for (int q = 0; q < 4; q++) acc[i][j][q] = 0.f;

    loadA_tile(As[0], Ap, K, 0, tid);
    loadB_tile(Bs[0], Bp, Nn, 0, tid);
    cpcommit();
    loadA_tile(As[1], Ap, K, 64, tid);
    loadB_tile(Bs[1], Bp, Nn, 64, tid);
    cpcommit();

    int nk = K >> 6;
    for (int it = 0; it < nk; it++) {
        int buf = it % 3;
        if (it + 1 < nk) cpwait1(); else cpwait0();
        __syncthreads();
        if (it + 2 < nk) {
            int k0 = (it + 2) << 6;
            int nb = (it + 2) % 3;
            loadA_tile(As[nb], Ap, K, k0, tid);
            loadB_tile(Bs[nb], Bp, Nn, k0, tid);
            cpcommit();
        }
        #pragma unroll
        for (int ks = 0; ks < 4; ks++) {
            uint32_t af[2][4], bfr[2][4];
            #pragma unroll
            for (int i = 0; i < 2; i++) {
                int mr = moff + i*16 + (lane & 15);
                int cc = (ks*2 + (lane >> 4)) ^ (mr & 7);
                ldsm4(af[i], smem_u32(&As[buf][mr][cc*8]));
            }
            #pragma unroll
            for (int jj = 0; jj < 2; jj++) {
                int kr = ks*16 + (lane & 15);
                int cc = (((noff + jj*16) >> 3) + (lane >> 4)) ^ (kr & 7);
                ldsm4t(bfr[jj], smem_u32(&Bs[buf][kr][cc*8]));
            }
            #pragma unroll
            for (int i = 0; i < 2; i++) {
                mma_bf16(acc[i][0], af[i], &bfr[0][0]);
                mma_bf16(acc[i][1], af[i], &bfr[0][2]);
                mma_bf16(acc[i][2], af[i], &bfr[1][0]);
                mma_bf16(acc[i][3], af[i], &bfr[1][2]);
            }
        }
    }

    __syncthreads();
    #pragma unroll
    for (int i = 0; i < 2; i++) {
        #pragma unroll
        for (int j = 0; j < 4; j++) {
            int col = n0 + noff + j*8 + t*2;
            float b0 = 0.f, b1 = 0.f;
            if (BIAS) { b0 = bias[col]; b1 = bias[col+1]; }
            #pragma unroll
            for (int hh = 0; hh < 2; hh++) {
                int row = m0 + moff + i*16 + g + hh*8;
                float r0 = acc[i][j][hh*2]   + b0;
                float r1 = acc[i][j][hh*2+1] + b1;
                if (GELU_ACT) {
                    r0 = 0.5f * r0 * (1.f + erff(r0 * 0.70710678118654752f));
                    r1 = 0.5f * r1 * (1.f + erff(r1 * 0.70710678118654752f));
                }
                epi_store(C + (size_t)row*Nn + col, r0, r1, ACCUM);
            }
        }
    }
}

// =============== BN=128 GEMM (big-N GEMMs): BM=128, BK=64, 3-stage ===============
template<typename TOUT, bool BIAS, bool ACCUM, bool GELU_ACT>
__global__ void __launch_bounds__(256) gemm2_k(const bf16* __restrict__ A,
                                               const bf16* __restrict__ Bw,
                                               const float* __restrict__ bias,
                                               TOUT* __restrict__ C,
                                               int M, int Nn, int K)
{
    extern __shared__ char sm2[];
    bf16 (*As)[128][64]  = reinterpret_cast<bf16(*)[128][64]>(sm2);
    bf16 (*Bs)[64][128]  = reinterpret_cast<bf16(*)[64][128]>(sm2 + 3*128*64*2);

    int tid = threadIdx.x;
    int w = tid >> 5, lane = tid & 31;
    int g = lane >> 2, t = lane & 3;
    int moff = (w & 1) * 64, noff = (w >> 1) * 32;
    int m0 = blockIdx.y * 128, n0 = blockIdx.x * 128;

    const bf16* Ap = A + (size_t)m0 * K;
    const bf16* Bp = Bw + n0;

    float acc[4][4][4];
    #pragma unroll
    for (int i = 0; i < 4; i++)
        #pragma unroll
        for (int j = 0; j < 4; j++)
            #pragma unroll
            for (int q = 0; q < 4; q++) acc[i][j][q] = 0.f;

    loadA_tile(As[0], Ap, K, 0, tid);
    loadB_tile2(Bs[0], Bp, Nn, 0, tid);
    cpcommit();
    loadA_tile(As[1], Ap, K, 64, tid);
    loadB_tile2(Bs[1], Bp, Nn, 64, tid);
    cpcommit();

    int nk = K >> 6;
    for (int it = 0; it < nk; it++) {
        int buf = it % 3;
        if (it + 1 < nk) cpwait1(); else cpwait0();
        __syncthreads();
        if (it + 2 < nk) {
            int k0 = (it + 2) << 6;
            int nb = (it + 2) % 3;
            loadA_tile(As[nb], Ap, K, k0, tid);
            loadB_tile2(Bs[nb], Bp, Nn, k0, tid);
            cpcommit();
        }
        #pragma unroll
        for (int ks = 0; ks < 4; ks++) {
            uint32_t af[4][4], bfr[2][4];
            #pragma unroll
            for (int i = 0; i < 4; i++) {
                int mr = moff + i*16 + (lane & 15);
                int cc = (ks*2 + (lane >> 4)) ^ (mr & 7);
                ldsm4(af[i], smem_u32(&As[buf][mr][cc*8]));
            }
            #pragma unroll
            for (int jj = 0; jj < 2; jj++) {
                int kr = ks*16 + (lane & 15);
                int jch = (noff >> 3) + jj*2 + (lane >> 4);
                int cc = jch ^ (kr & 7);
                ldsm4t(bfr[jj], smem_u32(&Bs[buf][kr][cc*8]));
            }
            #pragma unroll
            for (int i = 0; i < 4; i++) {
                mma_bf16(acc[i][0], af[i], &bfr[0][0]);
                mma_bf16(acc[i][1], af[i], &bfr[0][2]);
                mma_bf16(acc[i][2], af[i], &bfr[1][0]);
                mma_bf16(acc[i][3], af[i], &bfr[1][2]);
            }
        }
    }

    __syncthreads();
    #pragma unroll
    for (int i = 0; i < 4; i++) {
        #pragma unroll
        for (int j = 0; j < 4; j++) {
            int col = n0 + noff + j*8 + t*2;
            float b0 = 0.f, b1 = 0.f;
            if (BIAS) { b0 = bias[col]; b1 = bias[col+1]; }
            #pragma unroll
            for (int hh = 0; hh < 2; hh++) {
                int row = m0 + moff + i*16 + g + hh*8;
                float r0 = acc[i][j][hh*2]   + b0;
                float r1 = acc[i][j][hh*2+1] + b1;
                if (GELU_ACT) {
                    r0 = 0.5f * r0 * (1.f + erff(r0 * 0.70710678118654752f));
                    r1 = 0.5f * r1 * (1.f + erff(r1 * 0.70710678118654752f));
                }
                epi_store(C + (size_t)row*Nn + col, r0, r1, ACCUM);
            }
        }
    }
}

// ===== final GEMM: z = mid2 @ w2u + bias + residual(xfl), write NCHW out =====
__global__ void __launch_bounds__(256) gemm_out_k(const bf16* __restrict__ A,
                                                  const bf16* __restrict__ Bw,
                                                  const float* __restrict__ bias,
                                                  const float* __restrict__ resid,
                                                  float* __restrict__ outp)
{
    __shared__ char sbuf[49152];
    bf16 (&As)[2][128][64] = *reinterpret_cast<bf16(*)[2][128][64]>(sbuf);
    bf16 (&Bs)[2][64][64]  = *reinterpret_cast<bf16(*)[2][64][64]>(sbuf + 32768);

    const int K = 192, Nn = 384;
    int tid = threadIdx.x;
    int w = tid >> 5, lane = tid & 31;
    int g = lane >> 2, t = lane & 3;
    int moff = (w & 3) * 32, noff = (w >> 2) * 32;
    int m0 = blockIdx.y * 128, n0 = blockIdx.x * 64;

    const bf16* Ap = A + (size_t)m0 * K;
    const bf16* Bp = Bw + n0;

    float acc[2][4][4];
    #pragma unroll
    for (int i = 0; i < 2; i++)
        #pragma unroll
        for (int j = 0; j < 4; j++)
            #pragma unroll
            for (int q = 0; q < 4; q++) acc[i][j][q] = 0.f;

    loadA_tile(As[0], Ap, K, 0, tid);
    loadB_tile(Bs[0], Bp, Nn, 0, tid);
    cpcommit();

    int nk = K >> 6;   // 3
    for (int it = 0; it < nk; it++) {
        int buf = it & 1;
        if (it + 1 < nk) {
            int k0 = (it + 1) << 6;
            loadA_tile(As[buf ^ 1], Ap, K, k0, tid);
            loadB_tile(Bs[buf ^ 1], Bp, Nn, k0, tid);
            cpcommit();
            cpwait1();
        } else {
            cpwait0();
        }
        __syncthreads();
        #pragma unroll
        for (int ks = 0; ks < 4; ks++) {
            uint32_t af[2][4], bfr[2][4];
            #pragma unroll
            for (int i = 0; i < 2; i++) {
                int mr = moff + i*16 + (lane & 15);
                int cc = (ks*2 + (lane >> 4)) ^ (mr & 7);
                ldsm4(af[i], smem_u32(&As[buf][mr][cc*8]));
            }
            #pragma unroll
            for (int jj = 0; jj < 2; jj++) {
                int kr = ks*16 + (lane & 15);
                int cc = (((noff + jj*16) >> 3) + (lane >> 4)) ^ (kr & 7);
                ldsm4t(bfr[jj], smem_u32(&Bs[buf][kr][cc*8]));
            }
            #pragma unroll
            for (int i = 0; i < 2; i++) {
                mma_bf16(acc[i][0], af[i], &bfr[0][0]);
                mma_bf16(acc[i][1], af[i], &bfr[0][2]);
                mma_bf16(acc[i][2], af[i], &bfr[1][0]);
                mma_bf16(acc[i][3], af[i], &bfr[1][2]);
            }
        }
        __syncthreads();
    }

    float (&tr)[64][132] = *reinterpret_cast<float(*)[64][132]>(sbuf);
    #pragma unroll
    for (int i = 0; i < 2; i++) {
        #pragma unroll
        for (int j = 0; j < 4; j++) {
            int lc = noff + j*8 + t*2;
            float b0 = bias[n0 + lc], b1 = bias[n0 + lc + 1];
            #pragma unroll
            for (int hh = 0; hh < 2; hh++) {
                int lr = moff + i*16 + g + hh*8;
                float2 res = *(const float2*)(resid + (size_t)(m0 + lr)*Nn + n0 + lc);
                tr[lc][lr]     = acc[i][j][hh*2]   + b0 + res.x;
                tr[lc + 1][lr] = acc[i][j][hh*2+1] + b1 + res.y;
            }
        }
    }
    __syncthreads();

    {
        int cr = tid >> 2, ch = tid & 3;
        int tok0 = m0 + ch*32;
        int b = tok0 / HW_;
        int p = tok0 - b*HW_;
        float* op = outp + ((size_t)b*C_ + n0 + cr)*HW_ + p;
        #pragma unroll
        for (int z = 0; z < 32; z += 4) {
            float4 v = make_float4(tr[cr][ch*32 + z],     tr[cr][ch*32 + z + 1],
                                   tr[cr][ch*32 + z + 2], tr[cr][ch*32 + z + 3]);
            *(float4*)(op + z) = v;
        }
    }
}

// ================= XCA phase A: partial S = q @ k^T + norms (MMA) =================
__global__ void __launch_bounds__(256) xca_s_k(const bf16* __restrict__ qkv,
                                               float* __restrict__ gS,
                                               float* __restrict__ gN)
{
    extern __shared__ char smraw[];
    bf16*  q_s = (bf16*)smraw;                                // [48][456]
    bf16*  k_s = (bf16*)(smraw + 48*456*2);                   // [448][56]
    float* Ss  = (float*)(smraw + 48*456*2 + (size_t)XA_TOK*56*2); // [48][48]
    float* ns  = Ss + 48*48;                                  // [96]

    int bh = blockIdx.x, chunk = blockIdx.y;
    int b = bh >> 3, h = bh & 7;
    int tid = threadIdx.x;
    int w = tid >> 5, lane = tid & 31;
    int g = lane >> 2, t = lane & 3;
    const bf16* qb = qkv + ((size_t)b*HW_ + chunk*XA_TOK)*1152 + h*48;
    const bf16* kb = qb + 384;

    for (int i = tid; i < XA_TOK*6; i += 256) {
        int row = i/6, c = i%6;
        cp16(smem_u32(k_s + row*56 + c*8), kb + (size_t)row*1152 + c*8);
    }
    cpcommit();
    for (int i = tid; i < XA_TOK*24; i += 256) {
        int tok = i/24, dp = i%24;
        bf162 v = *(const bf162*)(qb + (size_t)tok*1152 + dp*2);
        q_s[(dp*2  )*456 + tok] = v.x;
        q_s[(dp*2+1)*456 + tok] = v.y;
    }
    for (int i = tid; i < 48*48; i += 256) Ss[i] = 0.f;
    if (tid < 96) ns[tid] = 0.f;
    cpwait0();
    __syncthreads();

    for (int u = tid; u < 384; u += 256) {
        int r = u >> 2, seg = u & 3;
        float acc = 0.f;
        if (r < 48) {
            const bf16* p = q_s + r*456 + seg*112;
            for (int x = 0; x < 112; x++) {
                float v = __bfloat162float(p[x]);
                acc = fmaf(v, v, acc);
            }
        } else {
            const bf16* p = k_s + (r - 48) + seg*112*56;
            for (int x = 0; x < 112; x++) {
                float v = __bfloat162float(p[x*56]);
                acc = fmaf(v, v, acc);
            }
        }
        atomicAdd(&ns[r], acc);
    }

    float acc[3][6][4];
    #pragma unroll
    for (int i = 0; i < 3; i++)
        #pragma unroll
        for (int j = 0; j < 6; j++)
            #pragma unroll
            for (int q = 0; q < 4; q++) acc[i][j][q] = 0.f;

    for (int s = w; s < 28; s += 8) {
        int k0 = s*16;
        uint32_t af[3][4], bfr[3][4];
        #pragma unroll
        for (int i = 0; i < 3; i++)
            ldsm4(af[i], smem_u32(q_s + (i*16 + (lane & 15))*456 + k0 + (lane >> 4)*8));
        #pragma unroll
        for (int jj = 0; jj < 3; jj++)
            ldsm4t(bfr[jj], smem_u32(k_s + (k0 + (lane & 15))*56 + jj*16 + (lane >> 4)*8));
        #pragma unroll
        for (int i = 0; i < 3; i++) {
            #pragma unroll
            for (int jj = 0; jj < 3; jj++) {
                mma_bf16(acc[i][jj*2  ], af[i], &bfr[jj][0]);
                mma_bf16(acc[i][jj*2+1], af[i], &bfr[jj][2]);
            }
        }
    }

    #pragma unroll
    for (int i = 0; i < 3; i++) {
        #pragma unroll
        for (int j = 0; j < 6; j++) {
            int r0 = i*16 + g, c0 = j*8 + t*2;
            atomicAdd(&Ss[r0*48 + c0    ], acc[i][j][0]);
            atomicAdd(&Ss[r0*48 + c0 + 1], acc[i][j][1]);
            atomicAdd(&Ss[(r0+8)*48 + c0    ], acc[i][j][2]);
            atomicAdd(&Ss[(r0+8)*48 + c0 + 1], acc[i][j][3]);
        }
    }
    __syncthreads();

    for (int i = tid; i < 48*48; i += 256)
        atomicAdd(&gS[(size_t)bh*2304 + i], Ss[i]);
    if (tid < 96)
        atomicAdd(&gN[bh*96 + tid], ns[tid]);
}

// ================= XCA softmax =================
__global__ void __launch_bounds__(96) xca_soft_k(const float* __restrict__ gS,
                                                 const float* __restrict__ gN,
                                                 bf16* __restrict__ gAT)
{
    __shared__ float iq[48], ik[48];
    int bh = blockIdx.x, tid = threadIdx.x;
    if (tid < 48)      iq[tid]    = 1.f / fmaxf(sqrtf(gN[bh*96 + tid]), 1e-12f);
    else               ik[tid-48] = 1.f / fmaxf(sqrtf(gN[bh*96 + tid]), 1e-12f);
    __syncthreads();
    if (tid < 48) {
        float row[48];
        const float* S = gS + (size_t)bh*2304 + tid*48;
        float mx = -1e30f;
        #pragma unroll 8
        for (int e = 0; e < 48; e++) {
            float l = S[e] * iq[tid] * ik[e];
            row[e] = l;
            mx = fmaxf(mx, l);
        }
        float sum = 0.f;
        #pragma unroll 8
        for (int e = 0; e < 48; e++) {
            float ex = expf(row[e] - mx);
            row[e] = ex;
            sum += ex;
        }
        float inv = 1.f / sum;
        #pragma unroll 8
        for (int e = 0; e < 48; e++)
            gAT[(size_t)bh*2304 + e*48 + tid] = __float2bfloat16(row[e] * inv);
    }
}

// ================= XCA phase C: y = v @ attn^T (MMA) =================
__global__ void __launch_bounds__(224) xca_av_k(const bf16* __restrict__ qkv,
                                                const bf16* __restrict__ gAT,
                                                bf16* __restrict__ outp)
{
    extern __shared__ char smraw[];
    bf16* v_s = (bf16*)smraw;                           // [448][56]
    bf16* aT  = (bf16*)(smraw + (size_t)XA_TOK*56*2);   // [48][56]

    int bh = blockIdx.x, chunk = blockIdx.y;
    int b = bh >> 3, h = bh & 7;
    int tid = threadIdx.x;
    int w = tid >> 5, lane = tid & 31;
    int g = lane >> 2, t = lane & 3;
    const bf16* vb = qkv + ((size_t)b*HW_ + chunk*XA_TOK)*1152 + h*48 + 768;

    for (int i = tid; i < XA_TOK*6; i += 224) {
        int row = i/6, c = i%6;
        cp16(smem_u32(v_s + row*56 + c*8), vb + (size_t)row*1152 + c*8);
    }
    for (int i = tid; i < 48*6; i += 224) {
        int e = i/6, c = i%6;
        cp16(smem_u32(aT + e*56 + c*8), gAT + (size_t)bh*2304 + e*48 + c*8);
    }
    cpcommit();
    cpwait0();
    __syncthreads();

    int tk0 = w*64;
    float acc[4][6][4];
    #pragma unroll
    for (int i = 0; i < 4; i++)
        #pragma unroll
        for (int j = 0; j < 6; j++)
            #pragma unroll
            for (int q = 0; q < 4; q++) acc[i][j][q] = 0.f;

    #pragma unroll
    for (int ks = 0; ks < 3; ks++) {
        int k0 = ks*16;
        uint32_t af[4][4], bfr[3][4];
        #pragma unroll
        for (int i = 0; i < 4; i++)
            ldsm4(af[i], smem_u32(v_s + (tk0 + i*16 + (lane & 15))*56 + k0 + (lane >> 4)*8));
        #pragma unroll
        for (int jj = 0; jj < 3; jj++)
            ldsm4t(bfr[jj], smem_u32(aT + (k0 + (lane & 15))*56 + jj*16 + (lane >> 4)*8));
        #pragma unroll
        for (int i = 0; i < 4; i++) {
            #pragma unroll
            for (int jj = 0; jj < 3; jj++) {
                mma_bf16(acc[i][jj*2  ], af[i], &bfr[jj][0]);
                mma_bf16(acc[i][jj*2+1], af[i], &bfr[jj][2]);
            }
        }
    }

    size_t tokbase = (size_t)b*HW_ + (size_t)chunk*XA_TOK + tk0;
    #pragma unroll
    for (int i = 0; i < 4; i++) {
        #pragma unroll
        for (int j = 0; j < 6; j++) {
            int r0 = i*16 + g, c0 = j*8 + t*2;
            *(bf162*)(outp + (tokbase + r0)*C_ + h*48 + c0) =
                __floats2bfloat162_rn(acc[i][j][0], acc[i][j][1]);
            *(bf162*)(outp + (tokbase + r0 + 8)*C_ + h*48 + c0) =
                __floats2bfloat162_rn(acc[i][j][2], acc[i][j][3]);
        }
    }
}

// ---------------- launch ----------------
extern "C" void kernel_launch(void* const* d_in, const int* in_sizes, int n_in,
                              void* d_out, int out_size)
{
    (void)in_sizes; (void)n_in; (void)out_size;
    const float* x      = (const float*)d_in[0];
    const float* dw_w0  = (const float*)d_in[1];
    const float* dw_b0  = (const float*)d_in[2];
    const float* dw_w1  = (const float*)d_in[3];
    const float* dw_b1  = (const float*)d_in[4];
    const float* ln1_g  = (const float*)d_in[5];
    const float* ln1_b  = (const float*)d_in[6];
    const float* qkv_w  = (const float*)d_in[7];
    const float* proj_w = (const float*)d_in[8];
    const float* proj_b = (const float*)d_in[9];
    const float* ln2_g  = (const float*)d_in[10];
    const float* ln2_b  = (const float*)d_in[11];
    const float* m1dw   = (const float*)d_in[12];
    const float* m1uw   = (const float*)d_in[13];
    const float* m1ub   = (const float*)d_in[14];
    const float* m2dw   = (const float*)d_in[15];
    const float* m2uw   = (const float*)d_in[16];
    const float* m2ub   = (const float*)d_in[17];
    float* out = (float*)d_out;

    void* p = 0;
    cudaGetSymbolAddress(&p, g_s1);
    float* s1 = (float*)p;
    cudaGetSymbolAddress(&p, g_s2);
    float* s2 = (float*)p;
    cudaGetSymbolAddress(&p, g_xfl);
    float* xfl = (float*)p;
    cudaGetSymbolAddress(&p, g_ln);
    bf16* lnb = (bf16*)p;
    cudaGetSymbolAddress(&p, g_qkv);
    bf16* qkvb = (bf16*)p;
    cudaGetSymbolAddress(&p, g_att);
    bf16* attb = (bf16*)p;
    cudaGetSymbolAddress(&p, g_mid1);
    bf16* mid1 = (bf16*)p;
    cudaGetSymbolAddress(&p, g_hid);
    bf16* hid = (bf16*)p;
    cudaGetSymbolAddress(&p, g_mid2);
    bf16* mid2 = (bf16*)p;
    cudaGetSymbolAddress(&p, g_S);
    float* gS = (float*)p;
    cudaGetSymbolAddress(&p, g_N);
    float* gN = (float*)p;
    cudaGetSymbolAddress(&p, g_aT);
    bf16* gAT = (bf16*)p;
    cudaGetSymbolAddress(&p, g_wqkv);
    bf16* wqkv = (bf16*)p;
    cudaGetSymbolAddress(&p, g_wproj);
    bf16* wproj = (bf16*)p;
    cudaGetSymbolAddress(&p, g_w1d);
    bf16* w1d = (bf16*)p;
    cudaGetSymbolAddress(&p, g_w1u);
    bf16* w1u = (bf16*)p;
    cudaGetSymbolAddress(&p, g_w2d);
    bf16* w2d = (bf16*)p;
    cudaGetSymbolAddress(&p, g_w2u);
    bf16* w2u = (bf16*)p;

    // dynamic smem opt-in
    const int XS_SMEM  = 48*456*2 + XA_TOK*56*2 + (48*48 + 96)*4;  // 103552
    const int AV_SMEM  = XA_TOK*56*2 + 48*56*2;                    // 55552
    const int GL_SMEM  = 32*385*4;                                 // 49280
    const int G2_SMEM  = 3*(128*64*2 + 64*128*2);                  // 98304
    const int GBF_SMEM = 3*(128*64*2 + 64*64*2);                   // 73728
    cudaFuncSetAttribute(xca_s_k,   cudaFuncAttributeMaxDynamicSharedMemorySize, XS_SMEM);
    cudaFuncSetAttribute(xca_av_k,  cudaFuncAttributeMaxDynamicSharedMemorySize, AV_SMEM);
    cudaFuncSetAttribute(gatherln_k, cudaFuncAttributeMaxDynamicSharedMemorySize, GL_SMEM);
    cudaFuncSetAttribute(gemm2_k<bf16, false, false, false>, cudaFuncAttributeMaxDynamicSharedMemorySize, G2_SMEM);
    cudaFuncSetAttribute(gemm2_k<float, true, true, false>,  cudaFuncAttributeMaxDynamicSharedMemorySize, G2_SMEM);
    cudaFuncSetAttribute(gemm2_k<bf16, true, false, true>,   cudaFuncAttributeMaxDynamicSharedMemorySize, G2_SMEM);
    cudaFuncSetAttribute(gemm_bf<bf16, false, false, false>, cudaFuncAttributeMaxDynamicSharedMemorySize, GBF_SMEM);

    // launch 0: prologue (dwconv0 + weight cvt + zero S/N)
    prologue_k<<<DW_BLOCKS + CVT_BLOCKS + ZR_BLOCKS, 256>>>(
        x, dw_w0, dw_b0, s1,
        qkv_w, proj_w, m1dw, m1uw, m2dw, m2uw,
        wqkv, wproj, w1d, w1u, w2d, w2u, gS, gN);

    // launch 1: dwconv stage 2
    dwconv_k<<<DW_BLOCKS, 256>>>(x + (size_t)2*SPLIT_*HW_, (size_t)C_*HW_,
                                 s1, (size_t)SPLIT_*HW_, dw_w1, dw_b1, s2);

    // launch 2: fused gather + LN1
    gatherln_k<<<dim3(HW_/32, B_), 256, GL_SMEM>>>(x, ln1_g, ln1_b, xfl, lnb);

    // launch 3: qkv GEMM (profiled slot)
    gemm2_k<bf16, false, false, false><<<dim3(1152/128, NTOK/128), 256, G2_SMEM>>>(lnb, wqkv, (const float*)0, qkvb, NTOK, 1152, 384);

    // XCA
    xca_s_k<<<dim3(128, XA_CH), 256, XS_SMEM>>>(qkvb, gS, gN);
    xca_soft_k<<<128, 96>>>(gS, gN, gAT);
    xca_av_k<<<dim3(128, XA_CH), 224, AV_SMEM>>>(qkvb, gAT, attb);

    // proj GEMM (+bias, += residual into xfl)
    gemm2_k<float, true, true, false><<<dim3(384/128, NTOK/128), 256, G2_SMEM>>>(attb, wproj, proj_b, xfl, NTOK, 384, 384);

    // MLP
    ln_k<<<NTOK, 128>>>(xfl, ln2_g, ln2_b, lnb);
    gemm_bf<bf16, false, false, false><<<dim3(192/64, NTOK/128), 256, GBF_SMEM>>>(lnb, w1d, (const float*)0, mid1, NTOK, 192, 384);
    gemm2_k<bf16, true, false, true><<<dim3(1536/128, NTOK/128), 256, G2_SMEM>>>(mid1, w1u, m1ub, hid, NTOK, 1536, 192);
    gemm_bf<bf16, false, false, false><<<dim3(192/64, NTOK/128), 256, GBF_SMEM>>>(hid, w2d, (const float*)0, mid2, NTOK, 192, 1536);

    // final GEMM fused with residual + NCHW scatter
    gemm_out_k<<<dim3(384/64, NTOK/128), 256>>>(mid2, w2u, m2ub, xfl, out);
}